// round 12
// baseline (speedup 1.0000x reference)
#include <cuda_runtime.h>
#include <stddef.h>
#include <stdint.h>

#define N_NODES 100000
#define N_EDGES 300000
#define NGRAPHS 3000
#define D 256
#define MSG_EPS 1e-7f
#define LN_EPS  1e-5f
#define SCAN_B 1024
#define NBLK ((N_NODES + SCAN_B - 1) / SCAN_B)   // 98

// ---------------- scratch (static device allocations; no cudaMalloc) ----------------
__device__ __align__(16) float g_h  [(size_t)N_NODES * D];
__device__ __align__(16) float g_hb [(size_t)N_NODES * D];   // second h buffer (ping-pong)
__device__ __align__(16) float g_h2 [(size_t)N_NODES * D];
__device__ __align__(16) float g_hv [(size_t)N_NODES * D];   // hv = h2 + vn[batch]
__device__ __align__(16) float g_vn [(size_t)NGRAPHS * D];
__device__ __align__(16) float g_combo[512 * D];
__device__ int g_off[NGRAPHS + 1];
__device__ int g_deg[N_NODES];
__device__ int g_noff[N_NODES + 1];
__device__ int g_cursor[N_NODES];
__device__ int g_elist[N_EDGES];
__device__ int g_bsum[NBLK];

__device__ __forceinline__ void cp_async16(uint32_t smem_dst, const void* gsrc) {
    asm volatile("cp.async.cg.shared.global [%0], [%1], 16;\n"
                 :: "r"(smem_dst), "l"(gsrc));
}
__device__ __forceinline__ void cp_commit() {
    asm volatile("cp.async.commit_group;\n" ::);
}
__device__ __forceinline__ void cp_wait0() {
    asm volatile("cp.async.wait_group 0;\n" ::: "memory");
}

// ================= CSR build =================
__global__ void zero_deg_kernel() {
    int i = blockIdx.x * blockDim.x + threadIdx.x;
    if (i < N_NODES) g_deg[i] = 0;
}
__global__ void hist_kernel(const int* __restrict__ ei) {
    int e = blockIdx.x * blockDim.x + threadIdx.x;
    if (e < N_EDGES) atomicAdd(&g_deg[ei[N_EDGES + e]], 1);
}
__global__ void scan_block_kernel() {
    __shared__ int s[SCAN_B];
    int tid = threadIdx.x;
    int i = blockIdx.x * SCAN_B + tid;
    int v = (i < N_NODES) ? g_deg[i] : 0;
    s[tid] = v;
    __syncthreads();
#pragma unroll
    for (int d = 1; d < SCAN_B; d <<= 1) {
        int t = (tid >= d) ? s[tid - d] : 0;
        __syncthreads();
        s[tid] += t;
        __syncthreads();
    }
    if (i < N_NODES) g_noff[i + 1] = s[tid];
    if (tid == SCAN_B - 1) g_bsum[blockIdx.x] = s[tid];
}
__global__ void scan_sums_kernel() {
    __shared__ int s[128];
    int tid = threadIdx.x;
    int v = (tid < NBLK) ? g_bsum[tid] : 0;
    s[tid] = v;
    __syncthreads();
#pragma unroll
    for (int d = 1; d < 128; d <<= 1) {
        int t = (tid >= d) ? s[tid - d] : 0;
        __syncthreads();
        s[tid] += t;
        __syncthreads();
    }
    if (tid < NBLK) g_bsum[tid] = s[tid] - v;
    if (tid == 0) g_noff[0] = 0;
}
__global__ void add_off_kernel() {       // also seeds cursor
    int i = blockIdx.x * blockDim.x + threadIdx.x;
    if (i < N_NODES) {
        int v = g_noff[i + 1] + g_bsum[i / SCAN_B];
        g_noff[i + 1] = v;
        if (i + 1 < N_NODES) g_cursor[i + 1] = v;
        if (i == 0) g_cursor[0] = 0;
    }
}
__global__ void fill_kernel(const int* __restrict__ ei, const int* __restrict__ ea) {
    int e = blockIdx.x * blockDim.x + threadIdx.x;
    if (e >= N_EDGES) return;
    int src = ei[e];
    int dst = ei[N_EDGES + e];
    int combo = ea[3 * e + 0] | (ea[3 * e + 1] << 3) | (ea[3 * e + 2] << 6);
    int pos = atomicAdd(&g_cursor[dst], 1);
    g_elist[pos] = src | (combo << 17);
}
__global__ void combo_kernel(const float* __restrict__ bond) {
    int c = blockIdx.x;
    int d = threadIdx.x;
    int a0 = c & 7, a1 = (c >> 3) & 7, a2 = (c >> 6) & 7;
    g_combo[c * D + d] = bond[(size_t)(0 * 8 + a0) * D + d]
                       + bond[(size_t)(1 * 8 + a1) * D + d]
                       + bond[(size_t)(2 * 8 + a2) * D + d];
}

// ---------------- node init (4 nodes/block, float4) ----------------
__global__ void node_init_kernel(const int* __restrict__ x,
                                 const float4* __restrict__ atom_emb,
                                 const float4* __restrict__ vn_emb,
                                 float4* __restrict__ h,
                                 float4* __restrict__ vn,
                                 float4* __restrict__ out_hinit)
{
    int n = blockIdx.x * 4 + (threadIdx.x >> 6);
    if (n >= N_NODES) return;
    int q = threadIdx.x & 63;
    float4 s = make_float4(0.f, 0.f, 0.f, 0.f);
#pragma unroll
    for (int f = 0; f < 9; f++) {
        int xi = __ldg(&x[n * 9 + f]);
        float4 v = atom_emb[((size_t)f * 64 + xi) * 64 + q];
        s.x += v.x; s.y += v.y; s.z += v.z; s.w += v.w;
    }
    size_t idx = (size_t)n * 64 + q;
    out_hinit[idx] = s;
    float4 vv = vn_emb[q];
    h[idx] = make_float4(s.x + vv.x, s.y + vv.y, s.z + vv.z, s.w + vv.w);
    if (n < NGRAPHS) vn[(size_t)n * 64 + q] = vv;
}

// ---------------- graph segment offsets ----------------
__global__ void offsets_kernel(const int* __restrict__ batch, int* __restrict__ off)
{
    int g = blockIdx.x * blockDim.x + threadIdx.x;
    if (g > NGRAPHS) return;
    int lo = 0, hi = N_NODES;
    while (lo < hi) {
        int mid = (lo + hi) >> 1;
        if (batch[mid] < g) lo = mid + 1; else hi = mid;
    }
    off[g] = lo;
}

// ---------------- tf32 helpers ----------------
__device__ __forceinline__ float tf32r(float x) {
    uint32_t u;
    asm("cvt.rna.tf32.f32 %0, %1;" : "=r"(u) : "f"(x));
    return __uint_as_float(u);
}
__device__ __forceinline__ uint32_t tf32u(float x) {
    uint32_t u;
    asm("cvt.rna.tf32.f32 %0, %1;" : "=r"(u) : "f"(x));
    return u;
}
__device__ __forceinline__ void mma_tf32(float* c, const uint32_t* a, const uint32_t* b) {
    asm volatile("mma.sync.aligned.m16n8k8.row.col.f32.tf32.tf32.f32 "
                 "{%0,%1,%2,%3}, {%4,%5,%6,%7}, {%8,%9}, {%0,%1,%2,%3};\n"
                 : "+f"(c[0]), "+f"(c[1]), "+f"(c[2]), "+f"(c[3])
                 : "r"(a[0]), "r"(a[1]), "r"(a[2]), "r"(a[3]),
                   "r"(b[0]), "r"(b[1]));
}

// ============ fused gather-aggregate + GCN GEMM + residual + LN/ReLU [+ FFN] ============
// Prologue: each block gathers agg rows m0..m0+63 (CSR) straight into smem HT (tf32).
// Mainloop: A-fragments read directly from HT (no staging); B double-buffered cp.async.
// Dynamic smem (112640 B):
//   [0, 66560)        HT float[64][260]   (A-tile; later h-tile for FFN phase)
//   [66560, 100352)   Bs[2][16][264]
//   [100352, 109568)  Wf[2][16][72]
//   [109568, 112640)  ssA[64][5], ssB[64][5], smu[64], srs[64]
#define HT_STRIDE 260
#define SM_BS    66560
#define SM_WF    100352
#define SM_SSA   109568
#define SM_SSB   110848
#define SM_MU    112128
#define SM_RS    112384
#define SM_TOTAL 112640

__global__ __launch_bounds__(256)
void gemm_fused(const float4* __restrict__ gsrc,      // gather source (h or hv), [N,64] float4
                const float* __restrict__ W, const float* __restrict__ bias,
                const float* __restrict__ res,
                const float* __restrict__ gam, const float* __restrict__ bet,
                const float* __restrict__ ffnW, const float* __restrict__ ffnB,
                float* __restrict__ outh, float* __restrict__ outh2,
                float* __restrict__ outf, int M)
{
    constexpr int BM = 64, BN = 256, BK = 16, K = D;
    constexpr int NITER = K / BK;
    constexpr int MT = 2, NT = 8;
    extern __shared__ char smraw[];
    float* HT = reinterpret_cast<float*>(smraw);           // [64][HT_STRIDE]
    float* Bs = reinterpret_cast<float*>(smraw + SM_BS);   // [buf*16+k][264]
    float* Wf = reinterpret_cast<float*>(smraw + SM_WF);   // [buf*16+k][72]
    float* ssA = reinterpret_cast<float*>(smraw + SM_SSA);
    float* ssB = reinterpret_cast<float*>(smraw + SM_SSB);
    float* smu = reinterpret_cast<float*>(smraw + SM_MU);
    float* srs = reinterpret_cast<float*>(smraw + SM_RS);
    const uint32_t smbase = (uint32_t)__cvta_generic_to_shared(smraw);

    const int tid  = threadIdx.x;
    const int lane = tid & 31;
    const int wid  = tid >> 5;
    const int wr   = wid >> 2;
    const int wc   = wid & 3;
    const int gid  = lane >> 2;
    const int tig  = lane & 3;
    const int m0   = blockIdx.x * BM;

    const int bk  = tid >> 4;
    const int bnc = (tid & 15) << 4;
    const float* bptr = W + (size_t)bk * BN + bnc;

    // ---- B stage 0 prefetch (overlaps the gather phase) ----
    {
        uint32_t dst = smbase + SM_BS + (uint32_t)((bk * 264 + bnc) * 4);
#pragma unroll
        for (int j = 0; j < 4; j++)
            cp_async16(dst + j * 16, bptr + j * 4);
        cp_commit();
    }

    // ---- gather-aggregate phase: 64 rows into HT (tf32) ----
    {
        const int grp = tid >> 6;       // 0..3
        const int q   = tid & 63;
        const float4* combo4 = reinterpret_cast<const float4*>(g_combo);
#pragma unroll 4
        for (int it = 0; it < 16; it++) {
            int lr = it * 4 + grp;
            int n = m0 + lr;
            if (n < M) {
                int i0 = g_noff[n], i1 = g_noff[n + 1];
                float4 self = gsrc[(size_t)n * 64 + q];
                float ax = self.x, ay = self.y, az = self.z, aw = self.w;
                int i = i0;
                for (; i + 1 < i1; i += 2) {
                    int ed0 = __ldg(&g_elist[i]);
                    int ed1 = __ldg(&g_elist[i + 1]);
                    int s0 = ed0 & 0x1FFFF, c0 = ed0 >> 17;
                    int s1 = ed1 & 0x1FFFF, c1 = ed1 >> 17;
                    float4 v0 = gsrc[(size_t)s0 * 64 + q];
                    float4 v1 = gsrc[(size_t)s1 * 64 + q];
                    float4 b0 = combo4[(size_t)c0 * 64 + q];
                    float4 b1 = combo4[(size_t)c1 * 64 + q];
                    ax += fmaxf(v0.x + b0.x, 0.f) + MSG_EPS + fmaxf(v1.x + b1.x, 0.f) + MSG_EPS;
                    ay += fmaxf(v0.y + b0.y, 0.f) + MSG_EPS + fmaxf(v1.y + b1.y, 0.f) + MSG_EPS;
                    az += fmaxf(v0.z + b0.z, 0.f) + MSG_EPS + fmaxf(v1.z + b1.z, 0.f) + MSG_EPS;
                    aw += fmaxf(v0.w + b0.w, 0.f) + MSG_EPS + fmaxf(v1.w + b1.w, 0.f) + MSG_EPS;
                }
                if (i < i1) {
                    int ed = __ldg(&g_elist[i]);
                    int s0 = ed & 0x1FFFF, c0 = ed >> 17;
                    float4 v = gsrc[(size_t)s0 * 64 + q];
                    float4 b = combo4[(size_t)c0 * 64 + q];
                    ax += fmaxf(v.x + b.x, 0.f) + MSG_EPS;
                    ay += fmaxf(v.y + b.y, 0.f) + MSG_EPS;
                    az += fmaxf(v.z + b.z, 0.f) + MSG_EPS;
                    aw += fmaxf(v.w + b.w, 0.f) + MSG_EPS;
                }
                *reinterpret_cast<float4*>(&HT[lr * HT_STRIDE + q * 4]) =
                    make_float4(tf32r(ax), tf32r(ay), tf32r(az), tf32r(aw));
            }
        }
    }
    cp_wait0();
    __syncthreads();

    float acc[MT][NT][4];
#pragma unroll
    for (int i = 0; i < MT; i++)
#pragma unroll
        for (int j = 0; j < NT; j++)
#pragma unroll
            for (int q = 0; q < 4; q++) acc[i][j][q] = 0.f;

    for (int k0 = 0; k0 < NITER; k0++) {
        const int cur = k0 & 1;
        if (k0 + 1 < NITER) {
            const int nxt = cur ^ 1;
            uint32_t dst = smbase + SM_BS + (uint32_t)(((nxt * 16 + bk) * 264 + bnc) * 4);
            const float* bp = bptr + (size_t)(k0 + 1) * BK * BN;
#pragma unroll
            for (int j = 0; j < 4; j++)
                cp_async16(dst + j * 16, bp + j * 4);
            cp_commit();
        }
#pragma unroll
        for (int ks = 0; ks < 2; ks++) {
            const int kb = k0 * BK + ks * 8;
            uint32_t af[MT][4];
            uint32_t bf[NT][2];
#pragma unroll
            for (int mt = 0; mt < MT; mt++) {
                int r = wr * 32 + mt * 16 + gid;
                af[mt][0] = __float_as_uint(HT[r * HT_STRIDE + kb + tig]);
                af[mt][1] = __float_as_uint(HT[(r + 8) * HT_STRIDE + kb + tig]);
                af[mt][2] = __float_as_uint(HT[r * HT_STRIDE + kb + tig + 4]);
                af[mt][3] = __float_as_uint(HT[(r + 8) * HT_STRIDE + kb + tig + 4]);
            }
#pragma unroll
            for (int nt = 0; nt < NT; nt++) {
                int c = wc * 64 + nt * 8 + gid;
                bf[nt][0] = tf32u(Bs[(cur * 16 + ks * 8 + tig) * 264 + c]);
                bf[nt][1] = tf32u(Bs[(cur * 16 + ks * 8 + tig + 4) * 264 + c]);
            }
#pragma unroll
            for (int mt = 0; mt < MT; mt++)
#pragma unroll
                for (int nt = 0; nt < NT; nt++)
                    mma_tf32(acc[mt][nt], af[mt], bf[nt]);
        }
        if (k0 + 1 < NITER) {
            cp_wait0();
            __syncthreads();
        }
    }

    if (ffnW) {   // prefetch FFN W chunk 0
        int kr = tid >> 4;
        int wcol = (tid & 15) << 2;
        uint32_t dst = smbase + SM_WF + (uint32_t)((kr * 72 + wcol) * 4);
        cp_async16(dst, ffnW + (size_t)kr * 64 + wcol);
        cp_commit();
    }

    // ---- epilogue: v = acc + bias (+res); write h ----
#pragma unroll
    for (int mt = 0; mt < MT; mt++) {
        int r  = m0 + wr * 32 + mt * 16 + gid;
        int r2 = r + 8;
#pragma unroll
        for (int nt = 0; nt < NT; nt++) {
            int c = wc * 64 + nt * 8 + 2 * tig;
            float2 bi = *reinterpret_cast<const float2*>(&bias[c]);
            float v0 = acc[mt][nt][0] + bi.x;
            float v1 = acc[mt][nt][1] + bi.y;
            float v2 = acc[mt][nt][2] + bi.x;
            float v3 = acc[mt][nt][3] + bi.y;
            if (res) {
                if (r < M) {
                    float2 rr = *reinterpret_cast<const float2*>(&res[(size_t)r * D + c]);
                    v0 += rr.x; v1 += rr.y;
                }
                if (r2 < M) {
                    float2 rr = *reinterpret_cast<const float2*>(&res[(size_t)r2 * D + c]);
                    v2 += rr.x; v3 += rr.y;
                }
            }
            acc[mt][nt][0] = v0; acc[mt][nt][1] = v1;
            acc[mt][nt][2] = v2; acc[mt][nt][3] = v3;
            if (r < M)
                *reinterpret_cast<float2*>(&outh[(size_t)r * D + c]) = make_float2(v0, v1);
            if (r2 < M)
                *reinterpret_cast<float2*>(&outh[(size_t)r2 * D + c]) = make_float2(v2, v3);
        }
    }

    if (ffnW) {   // A-tile no longer needed -> overwrite HT with h (tf32)
        __syncthreads();
#pragma unroll
        for (int mt = 0; mt < MT; mt++) {
            int lr  = wr * 32 + mt * 16 + gid;
            int lr2 = lr + 8;
#pragma unroll
            for (int nt = 0; nt < NT; nt++) {
                int c = wc * 64 + nt * 8 + 2 * tig;
                HT[lr  * HT_STRIDE + c    ] = tf32r(acc[mt][nt][0]);
                HT[lr  * HT_STRIDE + c + 1] = tf32r(acc[mt][nt][1]);
                HT[lr2 * HT_STRIDE + c    ] = tf32r(acc[mt][nt][2]);
                HT[lr2 * HT_STRIDE + c + 1] = tf32r(acc[mt][nt][3]);
            }
        }
    }

    // ---- LayerNorm + ReLU -> outh2 ----
    if (gam) {
#pragma unroll
        for (int mt = 0; mt < MT; mt++) {
#pragma unroll
            for (int hh = 0; hh < 2; hh++) {
                float s = 0.f, q = 0.f;
#pragma unroll
                for (int nt = 0; nt < NT; nt++) {
                    float u0 = acc[mt][nt][2 * hh];
                    float u1 = acc[mt][nt][2 * hh + 1];
                    s += u0 + u1;
                    q += u0 * u0 + u1 * u1;
                }
                s += __shfl_xor_sync(0xffffffffu, s, 1);
                q += __shfl_xor_sync(0xffffffffu, q, 1);
                s += __shfl_xor_sync(0xffffffffu, s, 2);
                q += __shfl_xor_sync(0xffffffffu, q, 2);
                if (tig == 0) {
                    int lr = wr * 32 + mt * 16 + hh * 8 + gid;
                    ssA[lr * 5 + wc] = s;
                    ssB[lr * 5 + wc] = q;
                }
            }
        }
        __syncthreads();
        if (tid < BM) {
            float s = ssA[tid * 5 + 0] + ssA[tid * 5 + 1] + ssA[tid * 5 + 2] + ssA[tid * 5 + 3];
            float q = ssB[tid * 5 + 0] + ssB[tid * 5 + 1] + ssB[tid * 5 + 2] + ssB[tid * 5 + 3];
            float mu  = s * (1.f / D);
            float var = q * (1.f / D) - mu * mu;
            smu[tid] = mu;
            srs[tid] = rsqrtf(var + LN_EPS);
        }
        __syncthreads();
#pragma unroll
        for (int mt = 0; mt < MT; mt++) {
            int lr  = wr * 32 + mt * 16 + gid;
            int lr2 = lr + 8;
            int r   = m0 + lr;
            int r2  = m0 + lr2;
            float mu0 = smu[lr],  rs0 = srs[lr];
            float mu1 = smu[lr2], rs1 = srs[lr2];
#pragma unroll
            for (int nt = 0; nt < NT; nt++) {
                int c = wc * 64 + nt * 8 + 2 * tig;
                float2 gg = *reinterpret_cast<const float2*>(&gam[c]);
                float2 bb = *reinterpret_cast<const float2*>(&bet[c]);
                if (r < M) {
                    float y0 = (acc[mt][nt][0] - mu0) * rs0 * gg.x + bb.x;
                    float y1 = (acc[mt][nt][1] - mu0) * rs0 * gg.y + bb.y;
                    *reinterpret_cast<float2*>(&outh2[(size_t)r * D + c]) =
                        make_float2(fmaxf(y0, 0.f), fmaxf(y1, 0.f));
                }
                if (r2 < M) {
                    float y2 = (acc[mt][nt][2] - mu1) * rs1 * gg.x + bb.x;
                    float y3 = (acc[mt][nt][3] - mu1) * rs1 * gg.y + bb.y;
                    *reinterpret_cast<float2*>(&outh2[(size_t)r2 * D + c]) =
                        make_float2(fmaxf(y2, 0.f), fmaxf(y3, 0.f));
                }
            }
        }
    }

    if (!ffnW) return;

    // ---- FFN phase: outf = h_tile @ ffnW + ffnB, 64x64x256 ----
    const int wrf = wid >> 1;
    const int wcf = wid & 1;
    const int fkr = tid >> 4;
    const int fwc = (tid & 15) << 2;
    cp_wait0();
    __syncthreads();

    float fac[4][4];
#pragma unroll
    for (int i = 0; i < 4; i++)
#pragma unroll
        for (int j = 0; j < 4; j++) fac[i][j] = 0.f;

    constexpr int FCH = 16;
    for (int ch = 0; ch < FCH; ch++) {
        const int cur = ch & 1;
        if (ch + 1 < FCH) {
            const int nxt = cur ^ 1;
            uint32_t dst = smbase + SM_WF + (uint32_t)(((nxt * 16 + fkr) * 72 + fwc) * 4);
            cp_async16(dst, ffnW + (size_t)((ch + 1) * 16 + fkr) * 64 + fwc);
            cp_commit();
        }
#pragma unroll
        for (int ks = 0; ks < 2; ks++) {
            int kb = ch * 16 + ks * 8;
            uint32_t af[4];
            {
                int r = wrf * 16 + gid;
                af[0] = __float_as_uint(HT[r * HT_STRIDE + kb + tig]);
                af[1] = __float_as_uint(HT[(r + 8) * HT_STRIDE + kb + tig]);
                af[2] = __float_as_uint(HT[r * HT_STRIDE + kb + tig + 4]);
                af[3] = __float_as_uint(HT[(r + 8) * HT_STRIDE + kb + tig + 4]);
            }
#pragma unroll
            for (int nt = 0; nt < 4; nt++) {
                int c = wcf * 32 + nt * 8 + gid;
                uint32_t bf[2];
                bf[0] = tf32u(Wf[(cur * 16 + ks * 8 + tig) * 72 + c]);
                bf[1] = tf32u(Wf[(cur * 16 + ks * 8 + tig + 4) * 72 + c]);
                mma_tf32(fac[nt], af, bf);
            }
        }
        if (ch + 1 < FCH) {
            cp_wait0();
            __syncthreads();
        }
    }

    {
        int r  = m0 + wrf * 16 + gid;
        int r2 = r + 8;
#pragma unroll
        for (int nt = 0; nt < 4; nt++) {
            int c = wcf * 32 + nt * 8 + 2 * tig;
            float2 bi = *reinterpret_cast<const float2*>(&ffnB[c]);
            if (r < M)
                *reinterpret_cast<float2*>(&outf[(size_t)r * 256 + c]) =
                    make_float2(fac[nt][0] + bi.x, fac[nt][1] + bi.y);
            if (r2 < M)
                *reinterpret_cast<float2*>(&outf[(size_t)r2 * 256 + c]) =
                    make_float2(fac[nt][2] + bi.x, fac[nt][3] + bi.y);
        }
    }
}

// ---------------- standalone tf32 FFN GEMM (runs on side stream) ----------------
template<int BN, int WR, int WC>
__global__ __launch_bounds__(256)
void gemm_tf32(const float* __restrict__ A,
               const float* __restrict__ W, const float* __restrict__ bias,
               float* __restrict__ out,
               int M, int ldout, int ldw)
{
    constexpr int BM = 128, BK = 16, K = D;
    constexpr int NITER = K / BK;
    constexpr int TM = BM / WR;
    constexpr int TN = BN / WC;
    constexpr int MT = TM / 16;
    constexpr int NT = TN / 8;
    constexpr int PAD = 8;
    __shared__ float As[2][BK][BM + PAD];
    __shared__ float Bs[2][BK][BN + PAD];

    const int tid  = threadIdx.x;
    const int lane = tid & 31;
    const int wid  = tid >> 5;
    const int wr   = wid / WC;
    const int wc   = wid % WC;
    const int gid  = lane >> 2;
    const int tig  = lane & 3;
    const int m0   = blockIdx.x * BM;

    const int arow = tid & 127;
    const int akc  = (tid >> 7) << 3;
    const bool avalid = (m0 + arow) < M;
    const float* aptr = A + (size_t)(m0 + arow) * K + akc;

    constexpr int BVEC = (BN == 128) ? 2 : 1;
    const int bk  = tid >> 4;
    const int bnc = (tid & 15) * (BVEC * 4);
    const float* bptr = W + (size_t)bk * ldw + bnc;

    float4 a_st[2];
    float4 b_st[BVEC];

    a_st[0] = make_float4(0.f, 0.f, 0.f, 0.f);
    a_st[1] = a_st[0];
    if (avalid) {
        a_st[0] = *reinterpret_cast<const float4*>(aptr);
        a_st[1] = *reinterpret_cast<const float4*>(aptr + 4);
    }
#pragma unroll
    for (int i = 0; i < BVEC; i++)
        b_st[i] = *reinterpret_cast<const float4*>(bptr + i * 4);

    {
        const float* av = reinterpret_cast<const float*>(a_st);
#pragma unroll
        for (int j = 0; j < 8; j++) As[0][akc + j][arow] = tf32r(av[j]);
        const float* bv = reinterpret_cast<const float*>(b_st);
#pragma unroll
        for (int j = 0; j < BVEC * 4; j++) Bs[0][bk][bnc + j] = tf32r(bv[j]);
    }
    __syncthreads();

    float acc[MT][NT][4];
#pragma unroll
    for (int i = 0; i < MT; i++)
#pragma unroll
        for (int j = 0; j < NT; j++)
#pragma unroll
            for (int q = 0; q < 4; q++) acc[i][j][q] = 0.f;

    for (int k0 = 0; k0 < NITER; k0++) {
        const int cur = k0 & 1;
        if (k0 + 1 < NITER) {
            a_st[0] = make_float4(0.f, 0.f, 0.f, 0.f);
            a_st[1] = a_st[0];
            if (avalid) {
                a_st[0] = *reinterpret_cast<const float4*>(aptr + (k0 + 1) * BK);
                a_st[1] = *reinterpret_cast<const float4*>(aptr + (k0 + 1) * BK + 4);
            }
#pragma unroll
            for (int i = 0; i < BVEC; i++)
                b_st[i] = *reinterpret_cast<const float4*>(bptr + (size_t)(k0 + 1) * BK * ldw + i * 4);
        }
#pragma unroll
        for (int ks = 0; ks < 2; ks++) {
            uint32_t af[MT][4];
            uint32_t bf[NT][2];
#pragma unroll
            for (int mt = 0; mt < MT; mt++) {
                int r = wr * TM + mt * 16 + gid;
                af[mt][0] = __float_as_uint(As[cur][ks * 8 + tig    ][r]);
                af[mt][1] = __float_as_uint(As[cur][ks * 8 + tig    ][r + 8]);
                af[mt][2] = __float_as_uint(As[cur][ks * 8 + tig + 4][r]);
                af[mt][3] = __float_as_uint(As[cur][ks * 8 + tig + 4][r + 8]);
            }
#pragma unroll
            for (int nt = 0; nt < NT; nt++) {
                int c = wc * TN + nt * 8 + gid;
                bf[nt][0] = __float_as_uint(Bs[cur][ks * 8 + tig    ][c]);
                bf[nt][1] = __float_as_uint(Bs[cur][ks * 8 + tig + 4][c]);
            }
#pragma unroll
            for (int mt = 0; mt < MT; mt++)
#pragma unroll
                for (int nt = 0; nt < NT; nt++)
                    mma_tf32(acc[mt][nt], af[mt], bf[nt]);
        }
        if (k0 + 1 < NITER) {
            const int nxt = cur ^ 1;
            const float* av = reinterpret_cast<const float*>(a_st);
#pragma unroll
            for (int j = 0; j < 8; j++) As[nxt][akc + j][arow] = tf32r(av[j]);
            const float* bv = reinterpret_cast<const float*>(b_st);
#pragma unroll
            for (int j = 0; j < BVEC * 4; j++) Bs[nxt][bk][bnc + j] = tf32r(bv[j]);
            __syncthreads();
        }
    }

#pragma unroll
    for (int mt = 0; mt < MT; mt++) {
#pragma unroll
        for (int nt = 0; nt < NT; nt++) {
            int r = m0 + wr * TM + mt * 16 + gid;
            int c = wc * TN + nt * 8 + 2 * tig;
            float2 bi = *reinterpret_cast<const float2*>(&bias[c]);
            if (r < M)
                *reinterpret_cast<float2*>(&out[(size_t)r * ldout + c]) =
                    make_float2(acc[mt][nt][0] + bi.x, acc[mt][nt][1] + bi.y);
            int r2 = r + 8;
            if (r2 < M)
                *reinterpret_cast<float2*>(&out[(size_t)r2 * ldout + c]) =
                    make_float2(acc[mt][nt][2] + bi.x, acc[mt][nt][3] + bi.y);
        }
    }
}

// ---------------- virtual-node path (+ hv = h2 + vn[batch] write-out) ----------------
__device__ __forceinline__ void ln_rows8(float (*t)[D], float (*s)[D],
                                         const float* __restrict__ gam,
                                         const float* __restrict__ bet,
                                         float* smu, float* srs)
{
    int lane = threadIdx.x & 31, w = threadIdx.x >> 5;
    float a = 0.f, b = 0.f;
#pragma unroll
    for (int i = 0; i < 8; i++) {
        float v = t[w][lane + 32 * i];
        a += v; b += v * v;
    }
#pragma unroll
    for (int o = 16; o; o >>= 1) {
        a += __shfl_down_sync(0xffffffffu, a, o);
        b += __shfl_down_sync(0xffffffffu, b, o);
    }
    if (lane == 0) {
        float mu = a * (1.f / D);
        float var = b * (1.f / D) - mu * mu;
        smu[w] = mu;
        srs[w] = rsqrtf(var + LN_EPS);
    }
    __syncthreads();
    int d = threadIdx.x;
    float gd = gam[d], bd = bet[d];
#pragma unroll
    for (int gg = 0; gg < 8; gg++) {
        float v = (t[gg][d] - smu[gg]) * srs[gg] * gd + bd;
        s[gg][d] = fmaxf(v, 0.f);
    }
}

__global__ void vn_mlp_kernel(const float* __restrict__ h2, const int* __restrict__ off,
                              const float* __restrict__ W1, const float* __restrict__ b1,
                              const float* __restrict__ g1, const float* __restrict__ be1,
                              const float* __restrict__ W2, const float* __restrict__ b2,
                              const float* __restrict__ g2, const float* __restrict__ be2,
                              float* __restrict__ vn, float* __restrict__ hv)
{
    __shared__ float s[8][D];
    __shared__ float t[8][D];
    __shared__ float smu[8], srs[8];
    int d = threadIdx.x;
    int g0 = blockIdx.x * 8;

#pragma unroll
    for (int gg = 0; gg < 8; gg++) {
        int g = g0 + gg;
        float acc = vn[(size_t)g * D + d];
        int n1 = off[g + 1];
        for (int n = off[g]; n < n1; n++)
            acc += h2[(size_t)n * D + d];
        s[gg][d] = acc;
    }
    __syncthreads();

    float y[8];
#pragma unroll
    for (int gg = 0; gg < 8; gg++) y[gg] = b1[d];
    for (int k = 0; k < D; k++) {
        float w = W1[(size_t)k * D + d];
#pragma unroll
        for (int gg = 0; gg < 8; gg++) y[gg] = fmaf(s[gg][k], w, y[gg]);
    }
    __syncthreads();
#pragma unroll
    for (int gg = 0; gg < 8; gg++) t[gg][d] = y[gg];
    __syncthreads();
    ln_rows8(t, s, g1, be1, smu, srs);
    __syncthreads();

#pragma unroll
    for (int gg = 0; gg < 8; gg++) y[gg] = b2[d];
    for (int k = 0; k < D; k++) {
        float w = W2[(size_t)k * D + d];
#pragma unroll
        for (int gg = 0; gg < 8; gg++) y[gg] = fmaf(s[gg][k], w, y[gg]);
    }
    __syncthreads();
#pragma unroll
    for (int gg = 0; gg < 8; gg++) t[gg][d] = y[gg];
    __syncthreads();
    ln_rows8(t, s, g2, be2, smu, srs);
    __syncthreads();

    // write vn + materialize hv = h2 + vn[batch] for this block's node ranges
#pragma unroll
    for (int gg = 0; gg < 8; gg++) {
        int g = g0 + gg;
        float v = s[gg][d];
        vn[(size_t)g * D + d] = v;
        int n1 = off[g + 1];
        for (int n = off[g]; n < n1; n++)
            hv[(size_t)n * D + d] = h2[(size_t)n * D + d] + v;
    }
}

// ---------------- launcher ----------------
extern "C" void kernel_launch(void* const* d_in, const int* in_sizes, int n_in,
                              void* d_out, int out_size)
{
    const int*   x          = (const int*)  d_in[0];
    const int*   edge_attr  = (const int*)  d_in[1];
    const int*   edge_index = (const int*)  d_in[2];
    const int*   batch      = (const int*)  d_in[3];
    const float* atom_emb   = (const float*)d_in[4];
    const float* bond_emb   = (const float*)d_in[5];
    const float* vn_emb     = (const float*)d_in[6];
    const float* gcn_w      = (const float*)d_in[7];
    const float* gcn_b      = (const float*)d_in[8];
    const float* norm_g     = (const float*)d_in[9];
    const float* norm_b     = (const float*)d_in[10];
    const float* ffn_w      = (const float*)d_in[11];
    const float* ffn_b      = (const float*)d_in[12];
    const float* vn_w1      = (const float*)d_in[13];
    const float* vn_b1      = (const float*)d_in[14];
    const float* vn_g1      = (const float*)d_in[15];
    const float* vn_be1     = (const float*)d_in[16];
    const float* vn_w2      = (const float*)d_in[17];
    const float* vn_b2      = (const float*)d_in[18];
    const float* vn_g2      = (const float*)d_in[19];
    const float* vn_be2     = (const float*)d_in[20];

    float* out       = (float*)d_out;                       // h_graph [N,256]
    float* out_hinit = out + (size_t)N_NODES * D;           // h_init  [N,256]

    float *hb0, *hb1, *ph2, *phv, *pvn; int* poff;
    cudaGetSymbolAddress((void**)&hb0,  g_h);
    cudaGetSymbolAddress((void**)&hb1,  g_hb);
    cudaGetSymbolAddress((void**)&ph2,  g_h2);
    cudaGetSymbolAddress((void**)&phv,  g_hv);
    cudaGetSymbolAddress((void**)&pvn,  g_vn);
    cudaGetSymbolAddress((void**)&poff, g_off);

    static cudaStream_t s1 = nullptr;
    static cudaEvent_t evFork, evSide, evH[3], evF[3];
    if (!s1) {
        cudaStreamCreateWithFlags(&s1, cudaStreamNonBlocking);
        cudaEventCreateWithFlags(&evFork, cudaEventDisableTiming);
        cudaEventCreateWithFlags(&evSide, cudaEventDisableTiming);
        for (int i = 0; i < 3; i++) {
            cudaEventCreateWithFlags(&evH[i], cudaEventDisableTiming);
            cudaEventCreateWithFlags(&evF[i], cudaEventDisableTiming);
        }
        cudaFuncSetAttribute(gemm_fused, cudaFuncAttributeMaxDynamicSharedMemorySize, SM_TOTAL);
    }

    const int FUSED_GRID = (N_NODES + 63) / 64;    // 1563
    const int FFN_GRID   = (N_NODES + 127) / 128;  // 782
    const int VN_GRID    = NGRAPHS / 8;

    // h write targets must differ from gather sources within one gemm_fused launch.
    float* hwr[4]  = {hb1, hb0, hb1, hb0};
    float* hres[4] = {nullptr, hb1, hb0, hb1};

    // ---- fork: prologue on two streams ----
    cudaEventRecord(evFork, 0);
    cudaStreamWaitEvent(s1, evFork, 0);

    // stream 0: CSR build chain
    zero_deg_kernel<<<(N_NODES + 255) / 256, 256>>>();
    hist_kernel<<<(N_EDGES + 255) / 256, 256>>>(edge_index);
    scan_block_kernel<<<NBLK, SCAN_B>>>();
    scan_sums_kernel<<<1, 128>>>();
    add_off_kernel<<<(N_NODES + 255) / 256, 256>>>();
    fill_kernel<<<(N_EDGES + 255) / 256, 256>>>(edge_index, edge_attr);

    // stream 1: node init, combo table, graph offsets
    node_init_kernel<<<N_NODES / 4, 256, 0, s1>>>(x, (const float4*)atom_emb,
                                                  (const float4*)vn_emb,
                                                  (float4*)hb0, (float4*)pvn,
                                                  (float4*)out_hinit);
    combo_kernel<<<512, 256, 0, s1>>>(bond_emb);
    offsets_kernel<<<(NGRAPHS + 1 + 255) / 256, 256, 0, s1>>>(batch, poff);
    cudaEventRecord(evSide, s1);
    cudaStreamWaitEvent(0, evSide, 0);

    // ----- layer 0: gather from hb0, write h -> hb1 -----
    gemm_fused<<<FUSED_GRID, 256, SM_TOTAL>>>((const float4*)hb0, gcn_w, gcn_b, nullptr,
                                              norm_g, norm_b, nullptr, nullptr,
                                              hwr[0], ph2, nullptr, N_NODES);
    cudaEventRecord(evH[0], 0);
    cudaStreamWaitEvent(s1, evH[0], 0);
    gemm_tf32<64, 4, 2><<<FFN_GRID, 256, 0, s1>>>(hwr[0], ffn_w, ffn_b, out, N_NODES, D, 64);
    cudaEventRecord(evF[0], s1);

    // ----- layers 1..2 (FFN on side stream) -----
    for (int l = 1; l < 3; l++) {
        int j = l - 1;
        vn_mlp_kernel<<<VN_GRID, 256>>>(ph2, poff,
                                        vn_w1 + (size_t)j * D * D, vn_b1 + (size_t)j * D,
                                        vn_g1 + (size_t)j * D,     vn_be1 + (size_t)j * D,
                                        vn_w2 + (size_t)j * D * D, vn_b2 + (size_t)j * D,
                                        vn_g2 + (size_t)j * D,     vn_be2 + (size_t)j * D,
                                        pvn, phv);
        if (l == 2) cudaStreamWaitEvent(0, evF[0], 0);    // about to rewrite hb1
        gemm_fused<<<FUSED_GRID, 256, SM_TOTAL>>>((const float4*)phv,
                                                  gcn_w + (size_t)l * D * D,
                                                  gcn_b + (size_t)l * D, hres[l],
                                                  norm_g + (size_t)l * D, norm_b + (size_t)l * D,
                                                  nullptr, nullptr,
                                                  hwr[l], ph2, nullptr, N_NODES);
        cudaEventRecord(evH[l], 0);
        cudaStreamWaitEvent(s1, evH[l], 0);
        gemm_tf32<64, 4, 2><<<FFN_GRID, 256, 0, s1>>>(hwr[l], ffn_w + (size_t)l * D * 64,
                                                      ffn_b + (size_t)l * 64,
                                                      out + (size_t)l * 64, N_NODES, D, 64);
        cudaEventRecord(evF[l], s1);
    }

    // ----- layer 3 (FFN fused; nothing left to overlap) -----
    {
        int l = 3, j = 2;
        vn_mlp_kernel<<<VN_GRID, 256>>>(ph2, poff,
                                        vn_w1 + (size_t)j * D * D, vn_b1 + (size_t)j * D,
                                        vn_g1 + (size_t)j * D,     vn_be1 + (size_t)j * D,
                                        vn_w2 + (size_t)j * D * D, vn_b2 + (size_t)j * D,
                                        vn_g2 + (size_t)j * D,     vn_be2 + (size_t)j * D,
                                        pvn, phv);
        cudaStreamWaitEvent(0, evF[1], 0);                // about to rewrite hb0
        gemm_fused<<<FUSED_GRID, 256, SM_TOTAL>>>((const float4*)phv,
                                                  gcn_w + (size_t)l * D * D,
                                                  gcn_b + (size_t)l * D, hres[l],
                                                  nullptr, nullptr,
                                                  ffn_w + (size_t)l * D * 64,
                                                  ffn_b + (size_t)l * 64,
                                                  hwr[l], ph2, out + (size_t)l * 64, N_NODES);
    }

    // ---- join side stream before returning ----
    cudaStreamWaitEvent(0, evF[2], 0);
}

// round 13
// speedup vs baseline: 1.1249x; 1.1249x over previous
#include <cuda_runtime.h>
#include <stddef.h>
#include <stdint.h>

#define N_NODES 100000
#define N_EDGES 300000
#define NGRAPHS 3000
#define D 256
#define MSG_EPS 1e-7f
#define LN_EPS  1e-5f
#define SCAN_B 1024
#define NBLK ((N_NODES + SCAN_B - 1) / SCAN_B)   // 98

// ---------------- scratch (static device allocations; no cudaMalloc) ----------------
__device__ __align__(16) float g_h  [(size_t)N_NODES * D];
__device__ __align__(16) float g_hb [(size_t)N_NODES * D];   // second h buffer (ping-pong)
__device__ __align__(16) float g_h2 [(size_t)N_NODES * D];
__device__ __align__(16) float g_hv [(size_t)N_NODES * D];   // hv = h2 + vn[batch]
__device__ __align__(16) float g_agg[(size_t)N_NODES * D];
__device__ __align__(16) float g_vn [(size_t)NGRAPHS * D];
__device__ __align__(16) float g_combo[512 * D];
__device__ int g_off[NGRAPHS + 1];
__device__ int g_deg[N_NODES];
__device__ int g_noff[N_NODES + 1];
__device__ int g_cursor[N_NODES];
__device__ int g_elist[N_EDGES];
__device__ int g_bsum[NBLK];

__device__ __forceinline__ void cp_async16(uint32_t smem_dst, const void* gsrc) {
    asm volatile("cp.async.cg.shared.global [%0], [%1], 16;\n"
                 :: "r"(smem_dst), "l"(gsrc));
}
__device__ __forceinline__ void cp_commit() {
    asm volatile("cp.async.commit_group;\n" ::);
}
__device__ __forceinline__ void cp_wait0() {
    asm volatile("cp.async.wait_group 0;\n" ::: "memory");
}

// ================= CSR build =================
__global__ void zero_deg_kernel() {
    int i = blockIdx.x * blockDim.x + threadIdx.x;
    if (i < N_NODES) g_deg[i] = 0;
}
__global__ void hist_kernel(const int* __restrict__ ei) {
    int e = blockIdx.x * blockDim.x + threadIdx.x;
    if (e < N_EDGES) atomicAdd(&g_deg[ei[N_EDGES + e]], 1);
}
__global__ void scan_block_kernel() {
    __shared__ int s[SCAN_B];
    int tid = threadIdx.x;
    int i = blockIdx.x * SCAN_B + tid;
    int v = (i < N_NODES) ? g_deg[i] : 0;
    s[tid] = v;
    __syncthreads();
#pragma unroll
    for (int d = 1; d < SCAN_B; d <<= 1) {
        int t = (tid >= d) ? s[tid - d] : 0;
        __syncthreads();
        s[tid] += t;
        __syncthreads();
    }
    if (i < N_NODES) g_noff[i + 1] = s[tid];
    if (tid == SCAN_B - 1) g_bsum[blockIdx.x] = s[tid];
}
__global__ void scan_sums_kernel() {
    __shared__ int s[128];
    int tid = threadIdx.x;
    int v = (tid < NBLK) ? g_bsum[tid] : 0;
    s[tid] = v;
    __syncthreads();
#pragma unroll
    for (int d = 1; d < 128; d <<= 1) {
        int t = (tid >= d) ? s[tid - d] : 0;
        __syncthreads();
        s[tid] += t;
        __syncthreads();
    }
    if (tid < NBLK) g_bsum[tid] = s[tid] - v;
    if (tid == 0) g_noff[0] = 0;
}
__global__ void add_off_kernel() {       // also seeds cursor
    int i = blockIdx.x * blockDim.x + threadIdx.x;
    if (i < N_NODES) {
        int v = g_noff[i + 1] + g_bsum[i / SCAN_B];
        g_noff[i + 1] = v;
        if (i + 1 < N_NODES) g_cursor[i + 1] = v;
        if (i == 0) g_cursor[0] = 0;
    }
}
__global__ void fill_kernel(const int* __restrict__ ei, const int* __restrict__ ea) {
    int e = blockIdx.x * blockDim.x + threadIdx.x;
    if (e >= N_EDGES) return;
    int src = ei[e];
    int dst = ei[N_EDGES + e];
    int combo = ea[3 * e + 0] | (ea[3 * e + 1] << 3) | (ea[3 * e + 2] << 6);
    int pos = atomicAdd(&g_cursor[dst], 1);
    g_elist[pos] = src | (combo << 17);
}
__global__ void combo_kernel(const float* __restrict__ bond) {
    int c = blockIdx.x;
    int d = threadIdx.x;
    int a0 = c & 7, a1 = (c >> 3) & 7, a2 = (c >> 6) & 7;
    g_combo[c * D + d] = bond[(size_t)(0 * 8 + a0) * D + d]
                       + bond[(size_t)(1 * 8 + a1) * D + d]
                       + bond[(size_t)(2 * 8 + a2) * D + d];
}

// ---------------- node init (4 nodes/block, float4) ----------------
__global__ void node_init_kernel(const int* __restrict__ x,
                                 const float4* __restrict__ atom_emb,
                                 const float4* __restrict__ vn_emb,
                                 float4* __restrict__ h,
                                 float4* __restrict__ vn,
                                 float4* __restrict__ out_hinit)
{
    int n = blockIdx.x * 4 + (threadIdx.x >> 6);
    if (n >= N_NODES) return;
    int q = threadIdx.x & 63;
    float4 s = make_float4(0.f, 0.f, 0.f, 0.f);
#pragma unroll
    for (int f = 0; f < 9; f++) {
        int xi = __ldg(&x[n * 9 + f]);
        float4 v = atom_emb[((size_t)f * 64 + xi) * 64 + q];
        s.x += v.x; s.y += v.y; s.z += v.z; s.w += v.w;
    }
    size_t idx = (size_t)n * 64 + q;
    out_hinit[idx] = s;
    float4 vv = vn_emb[q];
    h[idx] = make_float4(s.x + vv.x, s.y + vv.y, s.z + vv.z, s.w + vv.w);
    if (n < NGRAPHS) vn[(size_t)n * 64 + q] = vv;
}

// ---------------- graph segment offsets ----------------
__global__ void offsets_kernel(const int* __restrict__ batch, int* __restrict__ off)
{
    int g = blockIdx.x * blockDim.x + threadIdx.x;
    if (g > NGRAPHS) return;
    int lo = 0, hi = N_NODES;
    while (lo < hi) {
        int mid = (lo + hi) >> 1;
        if (batch[mid] < g) lo = mid + 1; else hi = mid;
    }
    off[g] = lo;
}

// ---------------- hv = h2 + vn[batch]  (node-parallel, coalesced) ----------------
__global__ void add_hv_kernel(const float4* __restrict__ h2,
                              const float4* __restrict__ vn,
                              const int* __restrict__ batch,
                              float4* __restrict__ hv)
{
    int n = blockIdx.x * 4 + (threadIdx.x >> 6);
    if (n >= N_NODES) return;
    int q = threadIdx.x & 63;
    int bg = __ldg(&batch[n]);
    float4 a = h2[(size_t)n * 64 + q];
    float4 b = vn[(size_t)bg * 64 + q];
    hv[(size_t)n * 64 + q] = make_float4(a.x + b.x, a.y + b.y, a.z + b.z, a.w + b.w);
}

// ---------------- CSR gather aggregation (no vn: source already has it) ----------------
__global__ void aggregate_kernel(const float4* __restrict__ hin,
                                 float4* __restrict__ agg)
{
    int n = blockIdx.x * 4 + (threadIdx.x >> 6);
    if (n >= N_NODES) return;
    int q = threadIdx.x & 63;
    const float4* combo4 = reinterpret_cast<const float4*>(g_combo);
    int i0 = g_noff[n], i1 = g_noff[n + 1];
    float4 self = hin[(size_t)n * 64 + q];
    float ax = self.x, ay = self.y, az = self.z, aw = self.w;
    int i = i0;
    for (; i + 1 < i1; i += 2) {
        int ed0 = __ldg(&g_elist[i]);
        int ed1 = __ldg(&g_elist[i + 1]);
        int s0 = ed0 & 0x1FFFF, c0 = ed0 >> 17;
        int s1 = ed1 & 0x1FFFF, c1 = ed1 >> 17;
        float4 v0 = hin[(size_t)s0 * 64 + q];
        float4 v1 = hin[(size_t)s1 * 64 + q];
        float4 b0 = combo4[(size_t)c0 * 64 + q];
        float4 b1 = combo4[(size_t)c1 * 64 + q];
        ax += fmaxf(v0.x + b0.x, 0.f) + MSG_EPS + fmaxf(v1.x + b1.x, 0.f) + MSG_EPS;
        ay += fmaxf(v0.y + b0.y, 0.f) + MSG_EPS + fmaxf(v1.y + b1.y, 0.f) + MSG_EPS;
        az += fmaxf(v0.z + b0.z, 0.f) + MSG_EPS + fmaxf(v1.z + b1.z, 0.f) + MSG_EPS;
        aw += fmaxf(v0.w + b0.w, 0.f) + MSG_EPS + fmaxf(v1.w + b1.w, 0.f) + MSG_EPS;
    }
    if (i < i1) {
        int ed = __ldg(&g_elist[i]);
        int s0 = ed & 0x1FFFF, c0 = ed >> 17;
        float4 v = hin[(size_t)s0 * 64 + q];
        float4 b = combo4[(size_t)c0 * 64 + q];
        ax += fmaxf(v.x + b.x, 0.f) + MSG_EPS;
        ay += fmaxf(v.y + b.y, 0.f) + MSG_EPS;
        az += fmaxf(v.z + b.z, 0.f) + MSG_EPS;
        aw += fmaxf(v.w + b.w, 0.f) + MSG_EPS;
    }
    agg[(size_t)n * 64 + q] = make_float4(ax, ay, az, aw);
}

// ---------------- tf32 helpers ----------------
__device__ __forceinline__ float tf32r(float x) {
    uint32_t u;
    asm("cvt.rna.tf32.f32 %0, %1;" : "=r"(u) : "f"(x));
    return __uint_as_float(u);
}
__device__ __forceinline__ uint32_t tf32u(float x) {
    uint32_t u;
    asm("cvt.rna.tf32.f32 %0, %1;" : "=r"(u) : "f"(x));
    return u;
}
__device__ __forceinline__ void mma_tf32(float* c, const uint32_t* a, const uint32_t* b) {
    asm volatile("mma.sync.aligned.m16n8k8.row.col.f32.tf32.tf32.f32 "
                 "{%0,%1,%2,%3}, {%4,%5,%6,%7}, {%8,%9}, {%0,%1,%2,%3};\n"
                 : "+f"(c[0]), "+f"(c[1]), "+f"(c[2]), "+f"(c[3])
                 : "r"(a[0]), "r"(a[1]), "r"(a[2]), "r"(a[3]),
                   "r"(b[0]), "r"(b[1]));
}

// ==================== fused GCN GEMM + residual + LN/ReLU [+ FFN] ====================
// BM=64, BN=256; FFN phase only when ffnW != nullptr (layer 3).
#define HT_STRIDE 260
#define SM_AS   0
#define SM_BS   9216
#define SM_WF   66560
#define SM_SSA  75776
#define SM_SSB  77056
#define SM_MU   78336
#define SM_RS   78592
#define SM_TOTAL 78848

__global__ __launch_bounds__(256)
void gemm_fused(const float* __restrict__ A,
                const float* __restrict__ W, const float* __restrict__ bias,
                const float* __restrict__ res,
                const float* __restrict__ gam, const float* __restrict__ bet,
                const float* __restrict__ ffnW, const float* __restrict__ ffnB,
                float* __restrict__ outh, float* __restrict__ outh2,
                float* __restrict__ outf, int M)
{
    constexpr int BM = 64, BN = 256, BK = 16, K = D;
    constexpr int NITER = K / BK;
    constexpr int MT = 2, NT = 8;
    extern __shared__ char smraw[];
    float* As = reinterpret_cast<float*>(smraw + SM_AS);   // [buf*16+k][72]
    float* Bs = reinterpret_cast<float*>(smraw + SM_BS);   // [buf*16+k][264]
    float* HT = reinterpret_cast<float*>(smraw);           // [64][HT_STRIDE]
    float* Wf = reinterpret_cast<float*>(smraw + SM_WF);   // [buf*16+k][72]
    float* ssA = reinterpret_cast<float*>(smraw + SM_SSA);
    float* ssB = reinterpret_cast<float*>(smraw + SM_SSB);
    float* smu = reinterpret_cast<float*>(smraw + SM_MU);
    float* srs = reinterpret_cast<float*>(smraw + SM_RS);
    const uint32_t smbase = (uint32_t)__cvta_generic_to_shared(smraw);

    const int tid  = threadIdx.x;
    const int lane = tid & 31;
    const int wid  = tid >> 5;
    const int wr   = wid >> 2;
    const int wc   = wid & 3;
    const int gid  = lane >> 2;
    const int tig  = lane & 3;
    const int m0   = blockIdx.x * BM;

    const int arow = tid & 63;
    const int akc  = (tid >> 6) << 2;
    const bool avalid = (m0 + arow) < M;
    const float* aptr = A + (size_t)(m0 + arow) * K + akc;

    const int bk  = tid >> 4;
    const int bnc = (tid & 15) << 4;
    const float* bptr = W + (size_t)bk * BN + bnc;

    // ---- prologue ----
    {
        uint32_t dst = smbase + SM_BS + (uint32_t)((bk * 264 + bnc) * 4);
#pragma unroll
        for (int j = 0; j < 4; j++)
            cp_async16(dst + j * 16, bptr + j * 4);
        cp_commit();
    }
    float4 a0 = make_float4(0.f, 0.f, 0.f, 0.f);
    if (avalid) a0 = *reinterpret_cast<const float4*>(aptr);
    As[(akc + 0) * 72 + arow] = tf32r(a0.x);
    As[(akc + 1) * 72 + arow] = tf32r(a0.y);
    As[(akc + 2) * 72 + arow] = tf32r(a0.z);
    As[(akc + 3) * 72 + arow] = tf32r(a0.w);
    cp_wait0();
    __syncthreads();

    float acc[MT][NT][4];
#pragma unroll
    for (int i = 0; i < MT; i++)
#pragma unroll
        for (int j = 0; j < NT; j++)
#pragma unroll
            for (int q = 0; q < 4; q++) acc[i][j][q] = 0.f;

    for (int k0 = 0; k0 < NITER; k0++) {
        const int cur = k0 & 1;
        float4 an = make_float4(0.f, 0.f, 0.f, 0.f);
        if (k0 + 1 < NITER) {
            const int nxt = cur ^ 1;
            uint32_t dst = smbase + SM_BS + (uint32_t)(((nxt * 16 + bk) * 264 + bnc) * 4);
            const float* bp = bptr + (size_t)(k0 + 1) * BK * BN;
#pragma unroll
            for (int j = 0; j < 4; j++)
                cp_async16(dst + j * 16, bp + j * 4);
            cp_commit();
            if (avalid) an = *reinterpret_cast<const float4*>(aptr + (k0 + 1) * BK);
        }
#pragma unroll
        for (int ks = 0; ks < 2; ks++) {
            uint32_t af[MT][4];
            uint32_t bf[NT][2];
#pragma unroll
            for (int mt = 0; mt < MT; mt++) {
                int r = wr * 32 + mt * 16 + gid;
                af[mt][0] = __float_as_uint(As[(cur * 16 + ks * 8 + tig) * 72 + r]);
                af[mt][1] = __float_as_uint(As[(cur * 16 + ks * 8 + tig) * 72 + r + 8]);
                af[mt][2] = __float_as_uint(As[(cur * 16 + ks * 8 + tig + 4) * 72 + r]);
                af[mt][3] = __float_as_uint(As[(cur * 16 + ks * 8 + tig + 4) * 72 + r + 8]);
            }
#pragma unroll
            for (int nt = 0; nt < NT; nt++) {
                int c = wc * 64 + nt * 8 + gid;
                bf[nt][0] = tf32u(Bs[(cur * 16 + ks * 8 + tig) * 264 + c]);
                bf[nt][1] = tf32u(Bs[(cur * 16 + ks * 8 + tig + 4) * 264 + c]);
            }
#pragma unroll
            for (int mt = 0; mt < MT; mt++)
#pragma unroll
                for (int nt = 0; nt < NT; nt++)
                    mma_tf32(acc[mt][nt], af[mt], bf[nt]);
        }
        if (k0 + 1 < NITER) {
            const int nxt = cur ^ 1;
            As[(nxt * 16 + akc + 0) * 72 + arow] = tf32r(an.x);
            As[(nxt * 16 + akc + 1) * 72 + arow] = tf32r(an.y);
            As[(nxt * 16 + akc + 2) * 72 + arow] = tf32r(an.z);
            As[(nxt * 16 + akc + 3) * 72 + arow] = tf32r(an.w);
            cp_wait0();
            __syncthreads();
        }
    }

    if (ffnW) {   // prefetch FFN W chunk 0
        int kr = tid >> 4;
        int wcol = (tid & 15) << 2;
        uint32_t dst = smbase + SM_WF + (uint32_t)((kr * 72 + wcol) * 4);
        cp_async16(dst, ffnW + (size_t)kr * 64 + wcol);
        cp_commit();
    }

    // ---- epilogue: v = acc + bias (+res); write h ----
#pragma unroll
    for (int mt = 0; mt < MT; mt++) {
        int r  = m0 + wr * 32 + mt * 16 + gid;
        int r2 = r + 8;
#pragma unroll
        for (int nt = 0; nt < NT; nt++) {
            int c = wc * 64 + nt * 8 + 2 * tig;
            float2 bi = *reinterpret_cast<const float2*>(&bias[c]);
            float v0 = acc[mt][nt][0] + bi.x;
            float v1 = acc[mt][nt][1] + bi.y;
            float v2 = acc[mt][nt][2] + bi.x;
            float v3 = acc[mt][nt][3] + bi.y;
            if (res) {
                if (r < M) {
                    float2 rr = *reinterpret_cast<const float2*>(&res[(size_t)r * D + c]);
                    v0 += rr.x; v1 += rr.y;
                }
                if (r2 < M) {
                    float2 rr = *reinterpret_cast<const float2*>(&res[(size_t)r2 * D + c]);
                    v2 += rr.x; v3 += rr.y;
                }
            }
            acc[mt][nt][0] = v0; acc[mt][nt][1] = v1;
            acc[mt][nt][2] = v2; acc[mt][nt][3] = v3;
            if (r < M)
                *reinterpret_cast<float2*>(&outh[(size_t)r * D + c]) = make_float2(v0, v1);
            if (r2 < M)
                *reinterpret_cast<float2*>(&outh[(size_t)r2 * D + c]) = make_float2(v2, v3);
        }
    }

    if (ffnW) {   // mainloop smem reads done -> h_tile
        __syncthreads();
#pragma unroll
        for (int mt = 0; mt < MT; mt++) {
            int lr  = wr * 32 + mt * 16 + gid;
            int lr2 = lr + 8;
#pragma unroll
            for (int nt = 0; nt < NT; nt++) {
                int c = wc * 64 + nt * 8 + 2 * tig;
                HT[lr  * HT_STRIDE + c    ] = tf32r(acc[mt][nt][0]);
                HT[lr  * HT_STRIDE + c + 1] = tf32r(acc[mt][nt][1]);
                HT[lr2 * HT_STRIDE + c    ] = tf32r(acc[mt][nt][2]);
                HT[lr2 * HT_STRIDE + c + 1] = tf32r(acc[mt][nt][3]);
            }
        }
    }

    // ---- LayerNorm + ReLU -> outh2 ----
    if (gam) {
#pragma unroll
        for (int mt = 0; mt < MT; mt++) {
#pragma unroll
            for (int hh = 0; hh < 2; hh++) {
                float s = 0.f, q = 0.f;
#pragma unroll
                for (int nt = 0; nt < NT; nt++) {
                    float u0 = acc[mt][nt][2 * hh];
                    float u1 = acc[mt][nt][2 * hh + 1];
                    s += u0 + u1;
                    q += u0 * u0 + u1 * u1;
                }
                s += __shfl_xor_sync(0xffffffffu, s, 1);
                q += __shfl_xor_sync(0xffffffffu, q, 1);
                s += __shfl_xor_sync(0xffffffffu, s, 2);
                q += __shfl_xor_sync(0xffffffffu, q, 2);
                if (tig == 0) {
                    int lr = wr * 32 + mt * 16 + hh * 8 + gid;
                    ssA[lr * 5 + wc] = s;
                    ssB[lr * 5 + wc] = q;
                }
            }
        }
        __syncthreads();
        if (tid < BM) {
            float s = ssA[tid * 5 + 0] + ssA[tid * 5 + 1] + ssA[tid * 5 + 2] + ssA[tid * 5 + 3];
            float q = ssB[tid * 5 + 0] + ssB[tid * 5 + 1] + ssB[tid * 5 + 2] + ssB[tid * 5 + 3];
            float mu  = s * (1.f / D);
            float var = q * (1.f / D) - mu * mu;
            smu[tid] = mu;
            srs[tid] = rsqrtf(var + LN_EPS);
        }
        __syncthreads();
#pragma unroll
        for (int mt = 0; mt < MT; mt++) {
            int lr  = wr * 32 + mt * 16 + gid;
            int lr2 = lr + 8;
            int r   = m0 + lr;
            int r2  = m0 + lr2;
            float mu0 = smu[lr],  rs0 = srs[lr];
            float mu1 = smu[lr2], rs1 = srs[lr2];
#pragma unroll
            for (int nt = 0; nt < NT; nt++) {
                int c = wc * 64 + nt * 8 + 2 * tig;
                float2 gg = *reinterpret_cast<const float2*>(&gam[c]);
                float2 bb = *reinterpret_cast<const float2*>(&bet[c]);
                if (r < M) {
                    float y0 = (acc[mt][nt][0] - mu0) * rs0 * gg.x + bb.x;
                    float y1 = (acc[mt][nt][1] - mu0) * rs0 * gg.y + bb.y;
                    *reinterpret_cast<float2*>(&outh2[(size_t)r * D + c]) =
                        make_float2(fmaxf(y0, 0.f), fmaxf(y1, 0.f));
                }
                if (r2 < M) {
                    float y2 = (acc[mt][nt][2] - mu1) * rs1 * gg.x + bb.x;
                    float y3 = (acc[mt][nt][3] - mu1) * rs1 * gg.y + bb.y;
                    *reinterpret_cast<float2*>(&outh2[(size_t)r2 * D + c]) =
                        make_float2(fmaxf(y2, 0.f), fmaxf(y3, 0.f));
                }
            }
        }
    }

    if (!ffnW) return;

    // ---- FFN phase: outf = h_tile @ ffnW + ffnB, 64x64x256 ----
    const int wrf = wid >> 1;
    const int wcf = wid & 1;
    const int fkr = tid >> 4;
    const int fwc = (tid & 15) << 2;
    cp_wait0();
    __syncthreads();

    float fac[4][4];
#pragma unroll
    for (int i = 0; i < 4; i++)
#pragma unroll
        for (int j = 0; j < 4; j++) fac[i][j] = 0.f;

    constexpr int FCH = 16;
    for (int ch = 0; ch < FCH; ch++) {
        const int cur = ch & 1;
        if (ch + 1 < FCH) {
            const int nxt = cur ^ 1;
            uint32_t dst = smbase + SM_WF + (uint32_t)(((nxt * 16 + fkr) * 72 + fwc) * 4);
            cp_async16(dst, ffnW + (size_t)((ch + 1) * 16 + fkr) * 64 + fwc);
            cp_commit();
        }
#pragma unroll
        for (int ks = 0; ks < 2; ks++) {
            int kb = ch * 16 + ks * 8;
            uint32_t af[4];
            {
                int r = wrf * 16 + gid;
                af[0] = __float_as_uint(HT[r * HT_STRIDE + kb + tig]);
                af[1] = __float_as_uint(HT[(r + 8) * HT_STRIDE + kb + tig]);
                af[2] = __float_as_uint(HT[r * HT_STRIDE + kb + tig + 4]);
                af[3] = __float_as_uint(HT[(r + 8) * HT_STRIDE + kb + tig + 4]);
            }
#pragma unroll
            for (int nt = 0; nt < 4; nt++) {
                int c = wcf * 32 + nt * 8 + gid;
                uint32_t bf[2];
                bf[0] = tf32u(Wf[(cur * 16 + ks * 8 + tig) * 72 + c]);
                bf[1] = tf32u(Wf[(cur * 16 + ks * 8 + tig + 4) * 72 + c]);
                mma_tf32(fac[nt], af, bf);
            }
        }
        if (ch + 1 < FCH) {
            cp_wait0();
            __syncthreads();
        }
    }

    {
        int r  = m0 + wrf * 16 + gid;
        int r2 = r + 8;
#pragma unroll
        for (int nt = 0; nt < 4; nt++) {
            int c = wcf * 32 + nt * 8 + 2 * tig;
            float2 bi = *reinterpret_cast<const float2*>(&ffnB[c]);
            if (r < M)
                *reinterpret_cast<float2*>(&outf[(size_t)r * 256 + c]) =
                    make_float2(fac[nt][0] + bi.x, fac[nt][1] + bi.y);
            if (r2 < M)
                *reinterpret_cast<float2*>(&outf[(size_t)r2 * 256 + c]) =
                    make_float2(fac[nt][2] + bi.x, fac[nt][3] + bi.y);
        }
    }
}

// ---------------- standalone tf32 FFN GEMM (runs on side stream) ----------------
template<int BN, int WR, int WC>
__global__ __launch_bounds__(256)
void gemm_tf32(const float* __restrict__ A,
               const float* __restrict__ W, const float* __restrict__ bias,
               float* __restrict__ out,
               int M, int ldout, int ldw)
{
    constexpr int BM = 128, BK = 16, K = D;
    constexpr int NITER = K / BK;
    constexpr int TM = BM / WR;
    constexpr int TN = BN / WC;
    constexpr int MT = TM / 16;
    constexpr int NT = TN / 8;
    constexpr int PAD = 8;
    __shared__ float As[2][BK][BM + PAD];
    __shared__ float Bs[2][BK][BN + PAD];

    const int tid  = threadIdx.x;
    const int lane = tid & 31;
    const int wid  = tid >> 5;
    const int wr   = wid / WC;
    const int wc   = wid % WC;
    const int gid  = lane >> 2;
    const int tig  = lane & 3;
    const int m0   = blockIdx.x * BM;

    const int arow = tid & 127;
    const int akc  = (tid >> 7) << 3;
    const bool avalid = (m0 + arow) < M;
    const float* aptr = A + (size_t)(m0 + arow) * K + akc;

    constexpr int BVEC = (BN == 128) ? 2 : 1;
    const int bk  = tid >> 4;
    const int bnc = (tid & 15) * (BVEC * 4);
    const float* bptr = W + (size_t)bk * ldw + bnc;

    float4 a_st[2];
    float4 b_st[BVEC];

    a_st[0] = make_float4(0.f, 0.f, 0.f, 0.f);
    a_st[1] = a_st[0];
    if (avalid) {
        a_st[0] = *reinterpret_cast<const float4*>(aptr);
        a_st[1] = *reinterpret_cast<const float4*>(aptr + 4);
    }
#pragma unroll
    for (int i = 0; i < BVEC; i++)
        b_st[i] = *reinterpret_cast<const float4*>(bptr + i * 4);

    {
        const float* av = reinterpret_cast<const float*>(a_st);
#pragma unroll
        for (int j = 0; j < 8; j++) As[0][akc + j][arow] = tf32r(av[j]);
        const float* bv = reinterpret_cast<const float*>(b_st);
#pragma unroll
        for (int j = 0; j < BVEC * 4; j++) Bs[0][bk][bnc + j] = tf32r(bv[j]);
    }
    __syncthreads();

    float acc[MT][NT][4];
#pragma unroll
    for (int i = 0; i < MT; i++)
#pragma unroll
        for (int j = 0; j < NT; j++)
#pragma unroll
            for (int q = 0; q < 4; q++) acc[i][j][q] = 0.f;

    for (int k0 = 0; k0 < NITER; k0++) {
        const int cur = k0 & 1;
        if (k0 + 1 < NITER) {
            a_st[0] = make_float4(0.f, 0.f, 0.f, 0.f);
            a_st[1] = a_st[0];
            if (avalid) {
                a_st[0] = *reinterpret_cast<const float4*>(aptr + (k0 + 1) * BK);
                a_st[1] = *reinterpret_cast<const float4*>(aptr + (k0 + 1) * BK + 4);
            }
#pragma unroll
            for (int i = 0; i < BVEC; i++)
                b_st[i] = *reinterpret_cast<const float4*>(bptr + (size_t)(k0 + 1) * BK * ldw + i * 4);
        }
#pragma unroll
        for (int ks = 0; ks < 2; ks++) {
            uint32_t af[MT][4];
            uint32_t bf[NT][2];
#pragma unroll
            for (int mt = 0; mt < MT; mt++) {
                int r = wr * TM + mt * 16 + gid;
                af[mt][0] = __float_as_uint(As[cur][ks * 8 + tig    ][r]);
                af[mt][1] = __float_as_uint(As[cur][ks * 8 + tig    ][r + 8]);
                af[mt][2] = __float_as_uint(As[cur][ks * 8 + tig + 4][r]);
                af[mt][3] = __float_as_uint(As[cur][ks * 8 + tig + 4][r + 8]);
            }
#pragma unroll
            for (int nt = 0; nt < NT; nt++) {
                int c = wc * TN + nt * 8 + gid;
                bf[nt][0] = __float_as_uint(Bs[cur][ks * 8 + tig    ][c]);
                bf[nt][1] = __float_as_uint(Bs[cur][ks * 8 + tig + 4][c]);
            }
#pragma unroll
            for (int mt = 0; mt < MT; mt++)
#pragma unroll
                for (int nt = 0; nt < NT; nt++)
                    mma_tf32(acc[mt][nt], af[mt], bf[nt]);
        }
        if (k0 + 1 < NITER) {
            const int nxt = cur ^ 1;
            const float* av = reinterpret_cast<const float*>(a_st);
#pragma unroll
            for (int j = 0; j < 8; j++) As[nxt][akc + j][arow] = tf32r(av[j]);
            const float* bv = reinterpret_cast<const float*>(b_st);
#pragma unroll
            for (int j = 0; j < BVEC * 4; j++) Bs[nxt][bk][bnc + j] = tf32r(bv[j]);
            __syncthreads();
        }
    }

#pragma unroll
    for (int mt = 0; mt < MT; mt++) {
#pragma unroll
        for (int nt = 0; nt < NT; nt++) {
            int r = m0 + wr * TM + mt * 16 + gid;
            int c = wc * TN + nt * 8 + 2 * tig;
            float2 bi = *reinterpret_cast<const float2*>(&bias[c]);
            if (r < M)
                *reinterpret_cast<float2*>(&out[(size_t)r * ldout + c]) =
                    make_float2(acc[mt][nt][0] + bi.x, acc[mt][nt][1] + bi.y);
            int r2 = r + 8;
            if (r2 < M)
                *reinterpret_cast<float2*>(&out[(size_t)r2 * ldout + c]) =
                    make_float2(acc[mt][nt][2] + bi.x, acc[mt][nt][3] + bi.y);
        }
    }
}

// ---------------- virtual-node path ----------------
__device__ __forceinline__ void ln_rows8(float (*t)[D], float (*s)[D],
                                         const float* __restrict__ gam,
                                         const float* __restrict__ bet,
                                         float* smu, float* srs)
{
    int lane = threadIdx.x & 31, w = threadIdx.x >> 5;
    float a = 0.f, b = 0.f;
#pragma unroll
    for (int i = 0; i < 8; i++) {
        float v = t[w][lane + 32 * i];
        a += v; b += v * v;
    }
#pragma unroll
    for (int o = 16; o; o >>= 1) {
        a += __shfl_down_sync(0xffffffffu, a, o);
        b += __shfl_down_sync(0xffffffffu, b, o);
    }
    if (lane == 0) {
        float mu = a * (1.f / D);
        float var = b * (1.f / D) - mu * mu;
        smu[w] = mu;
        srs[w] = rsqrtf(var + LN_EPS);
    }
    __syncthreads();
    int d = threadIdx.x;
    float gd = gam[d], bd = bet[d];
#pragma unroll
    for (int gg = 0; gg < 8; gg++) {
        float v = (t[gg][d] - smu[gg]) * srs[gg] * gd + bd;
        s[gg][d] = fmaxf(v, 0.f);
    }
}

__global__ void vn_mlp_kernel(const float* __restrict__ h2, const int* __restrict__ off,
                              const float* __restrict__ W1, const float* __restrict__ b1,
                              const float* __restrict__ g1, const float* __restrict__ be1,
                              const float* __restrict__ W2, const float* __restrict__ b2,
                              const float* __restrict__ g2, const float* __restrict__ be2,
                              float* __restrict__ vn)
{
    __shared__ float s[8][D];
    __shared__ float t[8][D];
    __shared__ float smu[8], srs[8];
    int d = threadIdx.x;
    int g0 = blockIdx.x * 8;

#pragma unroll
    for (int gg = 0; gg < 8; gg++) {
        int g = g0 + gg;
        float acc = vn[(size_t)g * D + d];
        int n1 = off[g + 1];
        for (int n = off[g]; n < n1; n++)
            acc += h2[(size_t)n * D + d];
        s[gg][d] = acc;
    }
    __syncthreads();

    float y[8];
#pragma unroll
    for (int gg = 0; gg < 8; gg++) y[gg] = b1[d];
    for (int k = 0; k < D; k++) {
        float w = W1[(size_t)k * D + d];
#pragma unroll
        for (int gg = 0; gg < 8; gg++) y[gg] = fmaf(s[gg][k], w, y[gg]);
    }
    __syncthreads();
#pragma unroll
    for (int gg = 0; gg < 8; gg++) t[gg][d] = y[gg];
    __syncthreads();
    ln_rows8(t, s, g1, be1, smu, srs);
    __syncthreads();

#pragma unroll
    for (int gg = 0; gg < 8; gg++) y[gg] = b2[d];
    for (int k = 0; k < D; k++) {
        float w = W2[(size_t)k * D + d];
#pragma unroll
        for (int gg = 0; gg < 8; gg++) y[gg] = fmaf(s[gg][k], w, y[gg]);
    }
    __syncthreads();
#pragma unroll
    for (int gg = 0; gg < 8; gg++) t[gg][d] = y[gg];
    __syncthreads();
    ln_rows8(t, s, g2, be2, smu, srs);
    __syncthreads();
#pragma unroll
    for (int gg = 0; gg < 8; gg++)
        vn[(size_t)(g0 + gg) * D + d] = s[gg][d];
}

// ---------------- launcher ----------------
extern "C" void kernel_launch(void* const* d_in, const int* in_sizes, int n_in,
                              void* d_out, int out_size)
{
    const int*   x          = (const int*)  d_in[0];
    const int*   edge_attr  = (const int*)  d_in[1];
    const int*   edge_index = (const int*)  d_in[2];
    const int*   batch      = (const int*)  d_in[3];
    const float* atom_emb   = (const float*)d_in[4];
    const float* bond_emb   = (const float*)d_in[5];
    const float* vn_emb     = (const float*)d_in[6];
    const float* gcn_w      = (const float*)d_in[7];
    const float* gcn_b      = (const float*)d_in[8];
    const float* norm_g     = (const float*)d_in[9];
    const float* norm_b     = (const float*)d_in[10];
    const float* ffn_w      = (const float*)d_in[11];
    const float* ffn_b      = (const float*)d_in[12];
    const float* vn_w1      = (const float*)d_in[13];
    const float* vn_b1      = (const float*)d_in[14];
    const float* vn_g1      = (const float*)d_in[15];
    const float* vn_be1     = (const float*)d_in[16];
    const float* vn_w2      = (const float*)d_in[17];
    const float* vn_b2      = (const float*)d_in[18];
    const float* vn_g2      = (const float*)d_in[19];
    const float* vn_be2     = (const float*)d_in[20];

    float* out       = (float*)d_out;                       // h_graph [N,256]
    float* out_hinit = out + (size_t)N_NODES * D;           // h_init  [N,256]

    float *hb0, *hb1, *ph2, *phv, *pagg, *pvn; int* poff;
    cudaGetSymbolAddress((void**)&hb0,  g_h);
    cudaGetSymbolAddress((void**)&hb1,  g_hb);
    cudaGetSymbolAddress((void**)&ph2,  g_h2);
    cudaGetSymbolAddress((void**)&phv,  g_hv);
    cudaGetSymbolAddress((void**)&pagg, g_agg);
    cudaGetSymbolAddress((void**)&pvn,  g_vn);
    cudaGetSymbolAddress((void**)&poff, g_off);

    static cudaStream_t s1 = nullptr;
    static cudaEvent_t evFork, evSide, evH[3], evF[3];
    if (!s1) {
        cudaStreamCreateWithFlags(&s1, cudaStreamNonBlocking);
        cudaEventCreateWithFlags(&evFork, cudaEventDisableTiming);
        cudaEventCreateWithFlags(&evSide, cudaEventDisableTiming);
        for (int i = 0; i < 3; i++) {
            cudaEventCreateWithFlags(&evH[i], cudaEventDisableTiming);
            cudaEventCreateWithFlags(&evF[i], cudaEventDisableTiming);
        }
        cudaFuncSetAttribute(gemm_fused, cudaFuncAttributeMaxDynamicSharedMemorySize, SM_TOTAL);
    }

    const int FUSED_GRID = (N_NODES + 63) / 64;    // 1563
    const int FFN_GRID   = (N_NODES + 127) / 128;  // 782
    const int NODE_GRID  = (N_NODES + 3) / 4;      // 25000

    float* hwr[4]  = {hb0, hb1, hb0, hb1};
    float* hres[4] = {nullptr, hb0, hb1, hb0};

    // ---- fork: prologue on two streams ----
    cudaEventRecord(evFork, 0);
    cudaStreamWaitEvent(s1, evFork, 0);

    // stream 0: CSR build chain
    zero_deg_kernel<<<(N_NODES + 255) / 256, 256>>>();
    hist_kernel<<<(N_EDGES + 255) / 256, 256>>>(edge_index);
    scan_block_kernel<<<NBLK, SCAN_B>>>();
    scan_sums_kernel<<<1, 128>>>();
    add_off_kernel<<<(N_NODES + 255) / 256, 256>>>();
    fill_kernel<<<(N_EDGES + 255) / 256, 256>>>(edge_index, edge_attr);

    // stream 1: node init, combo table, graph offsets
    node_init_kernel<<<N_NODES / 4, 256, 0, s1>>>(x, (const float4*)atom_emb,
                                                  (const float4*)vn_emb,
                                                  (float4*)hb0, (float4*)pvn,
                                                  (float4*)out_hinit);
    combo_kernel<<<512, 256, 0, s1>>>(bond_emb);
    offsets_kernel<<<(NGRAPHS + 1 + 255) / 256, 256, 0, s1>>>(batch, poff);
    cudaEventRecord(evSide, s1);
    cudaStreamWaitEvent(0, evSide, 0);

    // ----- layer 0 -----
    aggregate_kernel<<<NODE_GRID, 256>>>((const float4*)hb0, (float4*)pagg);
    gemm_fused<<<FUSED_GRID, 256, SM_TOTAL>>>(pagg, gcn_w, gcn_b, nullptr,
                                              norm_g, norm_b, nullptr, nullptr,
                                              hwr[0], ph2, nullptr, N_NODES);
    cudaEventRecord(evH[0], 0);
    cudaStreamWaitEvent(s1, evH[0], 0);
    gemm_tf32<64, 4, 2><<<FFN_GRID, 256, 0, s1>>>(hwr[0], ffn_w, ffn_b, out, N_NODES, D, 64);
    cudaEventRecord(evF[0], s1);

    // ----- layers 1..2 (FFN on side stream) -----
    for (int l = 1; l < 3; l++) {
        int j = l - 1;
        vn_mlp_kernel<<<NGRAPHS / 8, 256>>>(ph2, poff,
                                            vn_w1 + (size_t)j * D * D, vn_b1 + (size_t)j * D,
                                            vn_g1 + (size_t)j * D,     vn_be1 + (size_t)j * D,
                                            vn_w2 + (size_t)j * D * D, vn_b2 + (size_t)j * D,
                                            vn_g2 + (size_t)j * D,     vn_be2 + (size_t)j * D,
                                            pvn);
        add_hv_kernel<<<NODE_GRID, 256>>>((const float4*)ph2, (const float4*)pvn,
                                          batch, (float4*)phv);
        aggregate_kernel<<<NODE_GRID, 256>>>((const float4*)phv, (float4*)pagg);
        if (l == 2) cudaStreamWaitEvent(0, evF[0], 0);    // about to rewrite hb0
        gemm_fused<<<FUSED_GRID, 256, SM_TOTAL>>>(pagg, gcn_w + (size_t)l * D * D,
                                                  gcn_b + (size_t)l * D, hres[l],
                                                  norm_g + (size_t)l * D, norm_b + (size_t)l * D,
                                                  nullptr, nullptr,
                                                  hwr[l], ph2, nullptr, N_NODES);
        cudaEventRecord(evH[l], 0);
        cudaStreamWaitEvent(s1, evH[l], 0);
        gemm_tf32<64, 4, 2><<<FFN_GRID, 256, 0, s1>>>(hwr[l], ffn_w + (size_t)l * D * 64,
                                                      ffn_b + (size_t)l * 64,
                                                      out + (size_t)l * 64, N_NODES, D, 64);
        cudaEventRecord(evF[l], s1);
    }

    // ----- layer 3 (FFN fused; nothing left to overlap) -----
    {
        int l = 3, j = 2;
        vn_mlp_kernel<<<NGRAPHS / 8, 256>>>(ph2, poff,
                                            vn_w1 + (size_t)j * D * D, vn_b1 + (size_t)j * D,
                                            vn_g1 + (size_t)j * D,     vn_be1 + (size_t)j * D,
                                            vn_w2 + (size_t)j * D * D, vn_b2 + (size_t)j * D,
                                            vn_g2 + (size_t)j * D,     vn_be2 + (size_t)j * D,
                                            pvn);
        add_hv_kernel<<<NODE_GRID, 256>>>((const float4*)ph2, (const float4*)pvn,
                                          batch, (float4*)phv);
        aggregate_kernel<<<NODE_GRID, 256>>>((const float4*)phv, (float4*)pagg);
        cudaStreamWaitEvent(0, evF[1], 0);                // about to rewrite hb1
        gemm_fused<<<FUSED_GRID, 256, SM_TOTAL>>>(pagg, gcn_w + (size_t)l * D * D,
                                                  gcn_b + (size_t)l * D, hres[l],
                                                  nullptr, nullptr,
                                                  ffn_w + (size_t)l * D * 64,
                                                  ffn_b + (size_t)l * 64,
                                                  hwr[l], ph2, out + (size_t)l * 64, N_NODES);
    }

    // ---- join side stream before returning ----
    cudaStreamWaitEvent(0, evF[2], 0);
}

// round 14
// speedup vs baseline: 1.1674x; 1.0378x over previous
#include <cuda_runtime.h>
#include <stddef.h>
#include <stdint.h>

#define N_NODES 100000
#define N_EDGES 300000
#define NGRAPHS 3000
#define D 256
#define MSG_EPS 1e-7f
#define LN_EPS  1e-5f
#define SCAN_B 1024
#define NBLK ((N_NODES + SCAN_B - 1) / SCAN_B)   // 98

// ---------------- scratch (static device allocations; no cudaMalloc) ----------------
__device__ __align__(16) float g_h  [(size_t)N_NODES * D];
__device__ __align__(16) float g_hb [(size_t)N_NODES * D];   // second h buffer (ping-pong)
__device__ __align__(16) float g_h2 [(size_t)N_NODES * D];
__device__ __align__(16) float g_agg[(size_t)N_NODES * D];
__device__ __align__(16) float g_vn [(size_t)NGRAPHS * D];
__device__ __align__(16) float g_combo[512 * D];
__device__ int g_off[NGRAPHS + 1];
__device__ int g_deg[N_NODES];
__device__ int g_noff[N_NODES + 1];
__device__ int g_cursor[N_NODES];
__device__ int g_elist[N_EDGES];
__device__ int g_bsum[NBLK];

__device__ __forceinline__ void cp_async16(uint32_t smem_dst, const void* gsrc) {
    asm volatile("cp.async.cg.shared.global [%0], [%1], 16;\n"
                 :: "r"(smem_dst), "l"(gsrc));
}
__device__ __forceinline__ void cp_commit() {
    asm volatile("cp.async.commit_group;\n" ::);
}
__device__ __forceinline__ void cp_wait0() {
    asm volatile("cp.async.wait_group 0;\n" ::: "memory");
}
__device__ __forceinline__ void cp_wait1() {
    asm volatile("cp.async.wait_group 1;\n" ::: "memory");
}

// ================= CSR build =================
__global__ void zero_deg_kernel() {
    int i = blockIdx.x * blockDim.x + threadIdx.x;
    if (i < N_NODES) g_deg[i] = 0;
}
__global__ void hist_kernel(const int* __restrict__ ei) {
    int e = blockIdx.x * blockDim.x + threadIdx.x;
    if (e < N_EDGES) atomicAdd(&g_deg[ei[N_EDGES + e]], 1);
}
__global__ void scan_block_kernel() {
    __shared__ int s[SCAN_B];
    int tid = threadIdx.x;
    int i = blockIdx.x * SCAN_B + tid;
    int v = (i < N_NODES) ? g_deg[i] : 0;
    s[tid] = v;
    __syncthreads();
#pragma unroll
    for (int d = 1; d < SCAN_B; d <<= 1) {
        int t = (tid >= d) ? s[tid - d] : 0;
        __syncthreads();
        s[tid] += t;
        __syncthreads();
    }
    if (i < N_NODES) g_noff[i + 1] = s[tid];
    if (tid == SCAN_B - 1) g_bsum[blockIdx.x] = s[tid];
}
__global__ void scan_sums_kernel() {
    __shared__ int s[128];
    int tid = threadIdx.x;
    int v = (tid < NBLK) ? g_bsum[tid] : 0;
    s[tid] = v;
    __syncthreads();
#pragma unroll
    for (int d = 1; d < 128; d <<= 1) {
        int t = (tid >= d) ? s[tid - d] : 0;
        __syncthreads();
        s[tid] += t;
        __syncthreads();
    }
    if (tid < NBLK) g_bsum[tid] = s[tid] - v;
    if (tid == 0) g_noff[0] = 0;
}
__global__ void add_off_kernel() {       // also seeds cursor
    int i = blockIdx.x * blockDim.x + threadIdx.x;
    if (i < N_NODES) {
        int v = g_noff[i + 1] + g_bsum[i / SCAN_B];
        g_noff[i + 1] = v;
        if (i + 1 < N_NODES) g_cursor[i + 1] = v;
        if (i == 0) g_cursor[0] = 0;
    }
}
__global__ void fill_kernel(const int* __restrict__ ei, const int* __restrict__ ea) {
    int e = blockIdx.x * blockDim.x + threadIdx.x;
    if (e >= N_EDGES) return;
    int src = ei[e];
    int dst = ei[N_EDGES + e];
    int combo = ea[3 * e + 0] | (ea[3 * e + 1] << 3) | (ea[3 * e + 2] << 6);
    int pos = atomicAdd(&g_cursor[dst], 1);
    g_elist[pos] = src | (combo << 17);
}
__global__ void combo_kernel(const float* __restrict__ bond) {
    int c = blockIdx.x;
    int d = threadIdx.x;
    int a0 = c & 7, a1 = (c >> 3) & 7, a2 = (c >> 6) & 7;
    g_combo[c * D + d] = bond[(size_t)(0 * 8 + a0) * D + d]
                       + bond[(size_t)(1 * 8 + a1) * D + d]
                       + bond[(size_t)(2 * 8 + a2) * D + d];
}

// ---------------- node init (4 nodes/block, float4) ----------------
__global__ void node_init_kernel(const int* __restrict__ x,
                                 const float4* __restrict__ atom_emb,
                                 const float4* __restrict__ vn_emb,
                                 float4* __restrict__ h,
                                 float4* __restrict__ vn,
                                 float4* __restrict__ out_hinit)
{
    int n = blockIdx.x * 4 + (threadIdx.x >> 6);
    if (n >= N_NODES) return;
    int q = threadIdx.x & 63;
    float4 s = make_float4(0.f, 0.f, 0.f, 0.f);
#pragma unroll
    for (int f = 0; f < 9; f++) {
        int xi = __ldg(&x[n * 9 + f]);
        float4 v = atom_emb[((size_t)f * 64 + xi) * 64 + q];
        s.x += v.x; s.y += v.y; s.z += v.z; s.w += v.w;
    }
    size_t idx = (size_t)n * 64 + q;
    out_hinit[idx] = s;
    float4 vv = vn_emb[q];
    h[idx] = make_float4(s.x + vv.x, s.y + vv.y, s.z + vv.z, s.w + vv.w);
    if (n < NGRAPHS) vn[(size_t)n * 64 + q] = vv;
}

// ---------------- graph segment offsets ----------------
__global__ void offsets_kernel(const int* __restrict__ batch, int* __restrict__ off)
{
    int g = blockIdx.x * blockDim.x + threadIdx.x;
    if (g > NGRAPHS) return;
    int lo = 0, hi = N_NODES;
    while (lo < hi) {
        int mid = (lo + hi) >> 1;
        if (batch[mid] < g) lo = mid + 1; else hi = mid;
    }
    off[g] = lo;
}

// ---------------- CSR gather aggregation ----------------
template<bool WITHVN>
__global__ void aggregate_kernel(const float4* __restrict__ hin,
                                 const float4* __restrict__ vn,
                                 const int* __restrict__ batch,
                                 float4* __restrict__ agg)
{
    int n = blockIdx.x * 4 + (threadIdx.x >> 6);
    if (n >= N_NODES) return;
    int q = threadIdx.x & 63;
    const float4* combo4 = reinterpret_cast<const float4*>(g_combo);
    int i0 = g_noff[n], i1 = g_noff[n + 1];
    float4 self = hin[(size_t)n * 64 + q];
    float ax = self.x, ay = self.y, az = self.z, aw = self.w;
    if (WITHVN) {
        int bg = __ldg(&batch[n]);
        float4 vv = vn[(size_t)bg * 64 + q];
        ax += vv.x; ay += vv.y; az += vv.z; aw += vv.w;
    }
    int i = i0;
    for (; i + 1 < i1; i += 2) {
        int ed0 = __ldg(&g_elist[i]);
        int ed1 = __ldg(&g_elist[i + 1]);
        int s0 = ed0 & 0x1FFFF, c0 = ed0 >> 17;
        int s1 = ed1 & 0x1FFFF, c1 = ed1 >> 17;
        float4 v0 = hin[(size_t)s0 * 64 + q];
        float4 v1 = hin[(size_t)s1 * 64 + q];
        float4 b0 = combo4[(size_t)c0 * 64 + q];
        float4 b1 = combo4[(size_t)c1 * 64 + q];
        if (WITHVN) {
            int bg0 = __ldg(&batch[s0]);
            int bg1 = __ldg(&batch[s1]);
            float4 w0 = vn[(size_t)bg0 * 64 + q];
            float4 w1 = vn[(size_t)bg1 * 64 + q];
            v0.x += w0.x; v0.y += w0.y; v0.z += w0.z; v0.w += w0.w;
            v1.x += w1.x; v1.y += w1.y; v1.z += w1.z; v1.w += w1.w;
        }
        ax += fmaxf(v0.x + b0.x, 0.f) + MSG_EPS + fmaxf(v1.x + b1.x, 0.f) + MSG_EPS;
        ay += fmaxf(v0.y + b0.y, 0.f) + MSG_EPS + fmaxf(v1.y + b1.y, 0.f) + MSG_EPS;
        az += fmaxf(v0.z + b0.z, 0.f) + MSG_EPS + fmaxf(v1.z + b1.z, 0.f) + MSG_EPS;
        aw += fmaxf(v0.w + b0.w, 0.f) + MSG_EPS + fmaxf(v1.w + b1.w, 0.f) + MSG_EPS;
    }
    if (i < i1) {
        int ed = __ldg(&g_elist[i]);
        int s0 = ed & 0x1FFFF, c0 = ed >> 17;
        float4 v = hin[(size_t)s0 * 64 + q];
        float4 b = combo4[(size_t)c0 * 64 + q];
        if (WITHVN) {
            int bg0 = __ldg(&batch[s0]);
            float4 w = vn[(size_t)bg0 * 64 + q];
            v.x += w.x; v.y += w.y; v.z += w.z; v.w += w.w;
        }
        ax += fmaxf(v.x + b.x, 0.f) + MSG_EPS;
        ay += fmaxf(v.y + b.y, 0.f) + MSG_EPS;
        az += fmaxf(v.z + b.z, 0.f) + MSG_EPS;
        aw += fmaxf(v.w + b.w, 0.f) + MSG_EPS;
    }
    agg[(size_t)n * 64 + q] = make_float4(ax, ay, az, aw);
}

// ---------------- tf32 helpers ----------------
__device__ __forceinline__ float tf32r(float x) {
    uint32_t u;
    asm("cvt.rna.tf32.f32 %0, %1;" : "=r"(u) : "f"(x));
    return __uint_as_float(u);
}
__device__ __forceinline__ uint32_t tf32u(float x) {
    uint32_t u;
    asm("cvt.rna.tf32.f32 %0, %1;" : "=r"(u) : "f"(x));
    return u;
}
__device__ __forceinline__ void mma_tf32(float* c, const uint32_t* a, const uint32_t* b) {
    asm volatile("mma.sync.aligned.m16n8k8.row.col.f32.tf32.tf32.f32 "
                 "{%0,%1,%2,%3}, {%4,%5,%6,%7}, {%8,%9}, {%0,%1,%2,%3};\n"
                 : "+f"(c[0]), "+f"(c[1]), "+f"(c[2]), "+f"(c[3])
                 : "r"(a[0]), "r"(a[1]), "r"(a[2]), "r"(a[3]),
                   "r"(b[0]), "r"(b[1]));
}

// ==================== fused GCN GEMM + residual + LN/ReLU [+ FFN] ====================
// BM=64, BN=256; 3-stage cp.async B pipeline (wait_group 1); FFN phase only for layer 3.
// Dynamic smem (83456 B):
//   [0, 66560)       HT float[64][260]   (FFN phase; aliases As/Bs of mainloop)
//     [0, 9216)      As[2][16][72]
//     [9216, 59904)  Bs[3][16][264]
//   [66560, 80384)   Wf[3][16][72]
//   [80384, 83456)   ssA[64][5], ssB[64][5], smu[64], srs[64]
#define HT_STRIDE 260
#define SM_AS   0
#define SM_BS   9216
#define SM_WF   66560
#define SM_SSA  80384
#define SM_SSB  81664
#define SM_MU   82944
#define SM_RS   83200
#define SM_TOTAL 83456

__global__ __launch_bounds__(256)
void gemm_fused(const float* __restrict__ A,
                const float* __restrict__ W, const float* __restrict__ bias,
                const float* __restrict__ res,
                const float* __restrict__ gam, const float* __restrict__ bet,
                const float* __restrict__ ffnW, const float* __restrict__ ffnB,
                float* __restrict__ outh, float* __restrict__ outh2,
                float* __restrict__ outf, int M)
{
    constexpr int BM = 64, BN = 256, BK = 16, K = D;
    constexpr int NITER = K / BK;
    constexpr int MT = 2, NT = 8;
    extern __shared__ char smraw[];
    float* As = reinterpret_cast<float*>(smraw + SM_AS);   // [buf*16+k][72]
    float* Bs = reinterpret_cast<float*>(smraw + SM_BS);   // [buf*16+k][264], 3 bufs
    float* HT = reinterpret_cast<float*>(smraw);           // [64][HT_STRIDE]
    float* Wf = reinterpret_cast<float*>(smraw + SM_WF);   // [buf*16+k][72], 3 bufs
    float* ssA = reinterpret_cast<float*>(smraw + SM_SSA);
    float* ssB = reinterpret_cast<float*>(smraw + SM_SSB);
    float* smu = reinterpret_cast<float*>(smraw + SM_MU);
    float* srs = reinterpret_cast<float*>(smraw + SM_RS);
    const uint32_t smbase = (uint32_t)__cvta_generic_to_shared(smraw);

    const int tid  = threadIdx.x;
    const int lane = tid & 31;
    const int wid  = tid >> 5;
    const int wr   = wid >> 2;
    const int wc   = wid & 3;
    const int gid  = lane >> 2;
    const int tig  = lane & 3;
    const int m0   = blockIdx.x * BM;

    const int arow = tid & 63;
    const int akc  = (tid >> 6) << 2;
    const bool avalid = (m0 + arow) < M;
    const float* aptr = A + (size_t)(m0 + arow) * K + akc;

    const int bk  = tid >> 4;
    const int bnc = (tid & 15) << 4;
    const float* bptr = W + (size_t)bk * BN + bnc;

    // ---- prologue: B stages 0 and 1 in flight ----
    {
        uint32_t dst0 = smbase + SM_BS + (uint32_t)((bk * 264 + bnc) * 4);
#pragma unroll
        for (int j = 0; j < 4; j++)
            cp_async16(dst0 + j * 16, bptr + j * 4);
        cp_commit();
        uint32_t dst1 = smbase + SM_BS + (uint32_t)(((16 + bk) * 264 + bnc) * 4);
        const float* bp1 = bptr + (size_t)BK * BN;
#pragma unroll
        for (int j = 0; j < 4; j++)
            cp_async16(dst1 + j * 16, bp1 + j * 4);
        cp_commit();
    }
    float4 a0 = make_float4(0.f, 0.f, 0.f, 0.f);
    if (avalid) a0 = *reinterpret_cast<const float4*>(aptr);
    As[(akc + 0) * 72 + arow] = tf32r(a0.x);
    As[(akc + 1) * 72 + arow] = tf32r(a0.y);
    As[(akc + 2) * 72 + arow] = tf32r(a0.z);
    As[(akc + 3) * 72 + arow] = tf32r(a0.w);
    cp_wait1();                 // stage 0 ready, stage 1 still in flight
    __syncthreads();

    float acc[MT][NT][4];
#pragma unroll
    for (int i = 0; i < MT; i++)
#pragma unroll
        for (int j = 0; j < NT; j++)
#pragma unroll
            for (int q = 0; q < 4; q++) acc[i][j][q] = 0.f;

    for (int k0 = 0; k0 < NITER; k0++) {
        const int acur = k0 & 1;
        const int bcur = k0 % 3;
        float4 an = make_float4(0.f, 0.f, 0.f, 0.f);
        if (k0 + 2 < NITER) {
            const int bnx = (k0 + 2) % 3;
            uint32_t dst = smbase + SM_BS + (uint32_t)(((bnx * 16 + bk) * 264 + bnc) * 4);
            const float* bp = bptr + (size_t)(k0 + 2) * BK * BN;
#pragma unroll
            for (int j = 0; j < 4; j++)
                cp_async16(dst + j * 16, bp + j * 4);
            cp_commit();
        }
        if (k0 + 1 < NITER) {
            if (avalid) an = *reinterpret_cast<const float4*>(aptr + (k0 + 1) * BK);
        }
#pragma unroll
        for (int ks = 0; ks < 2; ks++) {
            uint32_t af[MT][4];
            uint32_t bf[NT][2];
#pragma unroll
            for (int mt = 0; mt < MT; mt++) {
                int r = wr * 32 + mt * 16 + gid;
                af[mt][0] = __float_as_uint(As[(acur * 16 + ks * 8 + tig) * 72 + r]);
                af[mt][1] = __float_as_uint(As[(acur * 16 + ks * 8 + tig) * 72 + r + 8]);
                af[mt][2] = __float_as_uint(As[(acur * 16 + ks * 8 + tig + 4) * 72 + r]);
                af[mt][3] = __float_as_uint(As[(acur * 16 + ks * 8 + tig + 4) * 72 + r + 8]);
            }
#pragma unroll
            for (int nt = 0; nt < NT; nt++) {
                int c = wc * 64 + nt * 8 + gid;
                bf[nt][0] = tf32u(Bs[(bcur * 16 + ks * 8 + tig) * 264 + c]);
                bf[nt][1] = tf32u(Bs[(bcur * 16 + ks * 8 + tig + 4) * 264 + c]);
            }
#pragma unroll
            for (int mt = 0; mt < MT; mt++)
#pragma unroll
                for (int nt = 0; nt < NT; nt++)
                    mma_tf32(acc[mt][nt], af[mt], bf[nt]);
        }
        if (k0 + 1 < NITER) {
            const int anx = acur ^ 1;
            As[(anx * 16 + akc + 0) * 72 + arow] = tf32r(an.x);
            As[(anx * 16 + akc + 1) * 72 + arow] = tf32r(an.y);
            As[(anx * 16 + akc + 2) * 72 + arow] = tf32r(an.z);
            As[(anx * 16 + akc + 3) * 72 + arow] = tf32r(an.w);
            if (k0 + 2 < NITER) cp_wait1(); else cp_wait0();
            __syncthreads();
        }
    }

    if (ffnW) {   // prefetch FFN W chunks 0 and 1 (disjoint Wf region)
        int kr = tid >> 4;
        int wcol = (tid & 15) << 2;
        uint32_t dst0 = smbase + SM_WF + (uint32_t)((kr * 72 + wcol) * 4);
        cp_async16(dst0, ffnW + (size_t)kr * 64 + wcol);
        cp_commit();
        uint32_t dst1 = smbase + SM_WF + (uint32_t)(((16 + kr) * 72 + wcol) * 4);
        cp_async16(dst1, ffnW + (size_t)(16 + kr) * 64 + wcol);
        cp_commit();
    }

    // ---- epilogue: v = acc + bias (+res); write h ----
#pragma unroll
    for (int mt = 0; mt < MT; mt++) {
        int r  = m0 + wr * 32 + mt * 16 + gid;
        int r2 = r + 8;
#pragma unroll
        for (int nt = 0; nt < NT; nt++) {
            int c = wc * 64 + nt * 8 + 2 * tig;
            float2 bi = *reinterpret_cast<const float2*>(&bias[c]);
            float v0 = acc[mt][nt][0] + bi.x;
            float v1 = acc[mt][nt][1] + bi.y;
            float v2 = acc[mt][nt][2] + bi.x;
            float v3 = acc[mt][nt][3] + bi.y;
            if (res) {
                if (r < M) {
                    float2 rr = *reinterpret_cast<const float2*>(&res[(size_t)r * D + c]);
                    v0 += rr.x; v1 += rr.y;
                }
                if (r2 < M) {
                    float2 rr = *reinterpret_cast<const float2*>(&res[(size_t)r2 * D + c]);
                    v2 += rr.x; v3 += rr.y;
                }
            }
            acc[mt][nt][0] = v0; acc[mt][nt][1] = v1;
            acc[mt][nt][2] = v2; acc[mt][nt][3] = v3;
            if (r < M)
                *reinterpret_cast<float2*>(&outh[(size_t)r * D + c]) = make_float2(v0, v1);
            if (r2 < M)
                *reinterpret_cast<float2*>(&outh[(size_t)r2 * D + c]) = make_float2(v2, v3);
        }
    }

    if (ffnW) {   // mainloop smem reads done -> h_tile
        __syncthreads();
#pragma unroll
        for (int mt = 0; mt < MT; mt++) {
            int lr  = wr * 32 + mt * 16 + gid;
            int lr2 = lr + 8;
#pragma unroll
            for (int nt = 0; nt < NT; nt++) {
                int c = wc * 64 + nt * 8 + 2 * tig;
                HT[lr  * HT_STRIDE + c    ] = tf32r(acc[mt][nt][0]);
                HT[lr  * HT_STRIDE + c + 1] = tf32r(acc[mt][nt][1]);
                HT[lr2 * HT_STRIDE + c    ] = tf32r(acc[mt][nt][2]);
                HT[lr2 * HT_STRIDE + c + 1] = tf32r(acc[mt][nt][3]);
            }
        }
    }

    // ---- LayerNorm + ReLU -> outh2 ----
    if (gam) {
#pragma unroll
        for (int mt = 0; mt < MT; mt++) {
#pragma unroll
            for (int hh = 0; hh < 2; hh++) {
                float s = 0.f, q = 0.f;
#pragma unroll
                for (int nt = 0; nt < NT; nt++) {
                    float u0 = acc[mt][nt][2 * hh];
                    float u1 = acc[mt][nt][2 * hh + 1];
                    s += u0 + u1;
                    q += u0 * u0 + u1 * u1;
                }
                s += __shfl_xor_sync(0xffffffffu, s, 1);
                q += __shfl_xor_sync(0xffffffffu, q, 1);
                s += __shfl_xor_sync(0xffffffffu, s, 2);
                q += __shfl_xor_sync(0xffffffffu, q, 2);
                if (tig == 0) {
                    int lr = wr * 32 + mt * 16 + hh * 8 + gid;
                    ssA[lr * 5 + wc] = s;
                    ssB[lr * 5 + wc] = q;
                }
            }
        }
        __syncthreads();
        if (tid < BM) {
            float s = ssA[tid * 5 + 0] + ssA[tid * 5 + 1] + ssA[tid * 5 + 2] + ssA[tid * 5 + 3];
            float q = ssB[tid * 5 + 0] + ssB[tid * 5 + 1] + ssB[tid * 5 + 2] + ssB[tid * 5 + 3];
            float mu  = s * (1.f / D);
            float var = q * (1.f / D) - mu * mu;
            smu[tid] = mu;
            srs[tid] = rsqrtf(var + LN_EPS);
        }
        __syncthreads();
#pragma unroll
        for (int mt = 0; mt < MT; mt++) {
            int lr  = wr * 32 + mt * 16 + gid;
            int lr2 = lr + 8;
            int r   = m0 + lr;
            int r2  = m0 + lr2;
            float mu0 = smu[lr],  rs0 = srs[lr];
            float mu1 = smu[lr2], rs1 = srs[lr2];
#pragma unroll
            for (int nt = 0; nt < NT; nt++) {
                int c = wc * 64 + nt * 8 + 2 * tig;
                float2 gg = *reinterpret_cast<const float2*>(&gam[c]);
                float2 bb = *reinterpret_cast<const float2*>(&bet[c]);
                if (r < M) {
                    float y0 = (acc[mt][nt][0] - mu0) * rs0 * gg.x + bb.x;
                    float y1 = (acc[mt][nt][1] - mu0) * rs0 * gg.y + bb.y;
                    *reinterpret_cast<float2*>(&outh2[(size_t)r * D + c]) =
                        make_float2(fmaxf(y0, 0.f), fmaxf(y1, 0.f));
                }
                if (r2 < M) {
                    float y2 = (acc[mt][nt][2] - mu1) * rs1 * gg.x + bb.x;
                    float y3 = (acc[mt][nt][3] - mu1) * rs1 * gg.y + bb.y;
                    *reinterpret_cast<float2*>(&outh2[(size_t)r2 * D + c]) =
                        make_float2(fmaxf(y2, 0.f), fmaxf(y3, 0.f));
                }
            }
        }
    }

    if (!ffnW) return;

    // ---- FFN phase: outf = h_tile @ ffnW + ffnB, 64x64x256, 3-stage Wf ----
    const int wrf = wid >> 1;
    const int wcf = wid & 1;
    const int fkr = tid >> 4;
    const int fwc = (tid & 15) << 2;
    cp_wait1();                 // chunk 0 ready, chunk 1 in flight
    __syncthreads();            // h_tile fully written

    float fac[4][4];
#pragma unroll
    for (int i = 0; i < 4; i++)
#pragma unroll
        for (int j = 0; j < 4; j++) fac[i][j] = 0.f;

    constexpr int FCH = 16;
    for (int ch = 0; ch < FCH; ch++) {
        const int cur = ch % 3;
        if (ch + 2 < FCH) {
            const int nx = (ch + 2) % 3;
            uint32_t dst = smbase + SM_WF + (uint32_t)(((nx * 16 + fkr) * 72 + fwc) * 4);
            cp_async16(dst, ffnW + (size_t)((ch + 2) * 16 + fkr) * 64 + fwc);
            cp_commit();
        }
#pragma unroll
        for (int ks = 0; ks < 2; ks++) {
            int kb = ch * 16 + ks * 8;
            uint32_t af[4];
            {
                int r = wrf * 16 + gid;
                af[0] = __float_as_uint(HT[r * HT_STRIDE + kb + tig]);
                af[1] = __float_as_uint(HT[(r + 8) * HT_STRIDE + kb + tig]);
                af[2] = __float_as_uint(HT[r * HT_STRIDE + kb + tig + 4]);
                af[3] = __float_as_uint(HT[(r + 8) * HT_STRIDE + kb + tig + 4]);
            }
#pragma unroll
            for (int nt = 0; nt < 4; nt++) {
                int c = wcf * 32 + nt * 8 + gid;
                uint32_t bf[2];
                bf[0] = tf32u(Wf[(cur * 16 + ks * 8 + tig) * 72 + c]);
                bf[1] = tf32u(Wf[(cur * 16 + ks * 8 + tig + 4) * 72 + c]);
                mma_tf32(fac[nt], af, bf);
            }
        }
        if (ch + 1 < FCH) {
            if (ch + 2 < FCH) cp_wait1(); else cp_wait0();
            __syncthreads();
        }
    }

    {
        int r  = m0 + wrf * 16 + gid;
        int r2 = r + 8;
#pragma unroll
        for (int nt = 0; nt < 4; nt++) {
            int c = wcf * 32 + nt * 8 + 2 * tig;
            float2 bi = *reinterpret_cast<const float2*>(&ffnB[c]);
            if (r < M)
                *reinterpret_cast<float2*>(&outf[(size_t)r * 256 + c]) =
                    make_float2(fac[nt][0] + bi.x, fac[nt][1] + bi.y);
            if (r2 < M)
                *reinterpret_cast<float2*>(&outf[(size_t)r2 * 256 + c]) =
                    make_float2(fac[nt][2] + bi.x, fac[nt][3] + bi.y);
        }
    }
}

// ---------------- standalone tf32 FFN GEMM (runs on side stream) ----------------
template<int BN, int WR, int WC>
__global__ __launch_bounds__(256)
void gemm_tf32(const float* __restrict__ A,
               const float* __restrict__ W, const float* __restrict__ bias,
               float* __restrict__ out,
               int M, int ldout, int ldw)
{
    constexpr int BM = 128, BK = 16, K = D;
    constexpr int NITER = K / BK;
    constexpr int TM = BM / WR;
    constexpr int TN = BN / WC;
    constexpr int MT = TM / 16;
    constexpr int NT = TN / 8;
    constexpr int PAD = 8;
    __shared__ float As[2][BK][BM + PAD];
    __shared__ float Bs[2][BK][BN + PAD];

    const int tid  = threadIdx.x;
    const int lane = tid & 31;
    const int wid  = tid >> 5;
    const int wr   = wid / WC;
    const int wc   = wid % WC;
    const int gid  = lane >> 2;
    const int tig  = lane & 3;
    const int m0   = blockIdx.x * BM;

    const int arow = tid & 127;
    const int akc  = (tid >> 7) << 3;
    const bool avalid = (m0 + arow) < M;
    const float* aptr = A + (size_t)(m0 + arow) * K + akc;

    constexpr int BVEC = (BN == 128) ? 2 : 1;
    const int bk  = tid >> 4;
    const int bnc = (tid & 15) * (BVEC * 4);
    const float* bptr = W + (size_t)bk * ldw + bnc;

    float4 a_st[2];
    float4 b_st[BVEC];

    a_st[0] = make_float4(0.f, 0.f, 0.f, 0.f);
    a_st[1] = a_st[0];
    if (avalid) {
        a_st[0] = *reinterpret_cast<const float4*>(aptr);
        a_st[1] = *reinterpret_cast<const float4*>(aptr + 4);
    }
#pragma unroll
    for (int i = 0; i < BVEC; i++)
        b_st[i] = *reinterpret_cast<const float4*>(bptr + i * 4);

    {
        const float* av = reinterpret_cast<const float*>(a_st);
#pragma unroll
        for (int j = 0; j < 8; j++) As[0][akc + j][arow] = tf32r(av[j]);
        const float* bv = reinterpret_cast<const float*>(b_st);
#pragma unroll
        for (int j = 0; j < BVEC * 4; j++) Bs[0][bk][bnc + j] = tf32r(bv[j]);
    }
    __syncthreads();

    float acc[MT][NT][4];
#pragma unroll
    for (int i = 0; i < MT; i++)
#pragma unroll
        for (int j = 0; j < NT; j++)
#pragma unroll
            for (int q = 0; q < 4; q++) acc[i][j][q] = 0.f;

    for (int k0 = 0; k0 < NITER; k0++) {
        const int cur = k0 & 1;
        if (k0 + 1 < NITER) {
            a_st[0] = make_float4(0.f, 0.f, 0.f, 0.f);
            a_st[1] = a_st[0];
            if (avalid) {
                a_st[0] = *reinterpret_cast<const float4*>(aptr + (k0 + 1) * BK);
                a_st[1] = *reinterpret_cast<const float4*>(aptr + (k0 + 1) * BK + 4);
            }
#pragma unroll
            for (int i = 0; i < BVEC; i++)
                b_st[i] = *reinterpret_cast<const float4*>(bptr + (size_t)(k0 + 1) * BK * ldw + i * 4);
        }
#pragma unroll
        for (int ks = 0; ks < 2; ks++) {
            uint32_t af[MT][4];
            uint32_t bf[NT][2];
#pragma unroll
            for (int mt = 0; mt < MT; mt++) {
                int r = wr * TM + mt * 16 + gid;
                af[mt][0] = __float_as_uint(As[cur][ks * 8 + tig    ][r]);
                af[mt][1] = __float_as_uint(As[cur][ks * 8 + tig    ][r + 8]);
                af[mt][2] = __float_as_uint(As[cur][ks * 8 + tig + 4][r]);
                af[mt][3] = __float_as_uint(As[cur][ks * 8 + tig + 4][r + 8]);
            }
#pragma unroll
            for (int nt = 0; nt < NT; nt++) {
                int c = wc * TN + nt * 8 + gid;
                bf[nt][0] = __float_as_uint(Bs[cur][ks * 8 + tig    ][c]);
                bf[nt][1] = __float_as_uint(Bs[cur][ks * 8 + tig + 4][c]);
            }
#pragma unroll
            for (int mt = 0; mt < MT; mt++)
#pragma unroll
                for (int nt = 0; nt < NT; nt++)
                    mma_tf32(acc[mt][nt], af[mt], bf[nt]);
        }
        if (k0 + 1 < NITER) {
            const int nxt = cur ^ 1;
            const float* av = reinterpret_cast<const float*>(a_st);
#pragma unroll
            for (int j = 0; j < 8; j++) As[nxt][akc + j][arow] = tf32r(av[j]);
            const float* bv = reinterpret_cast<const float*>(b_st);
#pragma unroll
            for (int j = 0; j < BVEC * 4; j++) Bs[nxt][bk][bnc + j] = tf32r(bv[j]);
            __syncthreads();
        }
    }

#pragma unroll
    for (int mt = 0; mt < MT; mt++) {
#pragma unroll
        for (int nt = 0; nt < NT; nt++) {
            int r = m0 + wr * TM + mt * 16 + gid;
            int c = wc * TN + nt * 8 + 2 * tig;
            float2 bi = *reinterpret_cast<const float2*>(&bias[c]);
            if (r < M)
                *reinterpret_cast<float2*>(&out[(size_t)r * ldout + c]) =
                    make_float2(acc[mt][nt][0] + bi.x, acc[mt][nt][1] + bi.y);
            int r2 = r + 8;
            if (r2 < M)
                *reinterpret_cast<float2*>(&out[(size_t)r2 * ldout + c]) =
                    make_float2(acc[mt][nt][2] + bi.x, acc[mt][nt][3] + bi.y);
        }
    }
}

// ---------------- virtual-node path ----------------
__device__ __forceinline__ void ln_rows8(float (*t)[D], float (*s)[D],
                                         const float* __restrict__ gam,
                                         const float* __restrict__ bet,
                                         float* smu, float* srs)
{
    int lane = threadIdx.x & 31, w = threadIdx.x >> 5;
    float a = 0.f, b = 0.f;
#pragma unroll
    for (int i = 0; i < 8; i++) {
        float v = t[w][lane + 32 * i];
        a += v; b += v * v;
    }
#pragma unroll
    for (int o = 16; o; o >>= 1) {
        a += __shfl_down_sync(0xffffffffu, a, o);
        b += __shfl_down_sync(0xffffffffu, b, o);
    }
    if (lane == 0) {
        float mu = a * (1.f / D);
        float var = b * (1.f / D) - mu * mu;
        smu[w] = mu;
        srs[w] = rsqrtf(var + LN_EPS);
    }
    __syncthreads();
    int d = threadIdx.x;
    float gd = gam[d], bd = bet[d];
#pragma unroll
    for (int gg = 0; gg < 8; gg++) {
        float v = (t[gg][d] - smu[gg]) * srs[gg] * gd + bd;
        s[gg][d] = fmaxf(v, 0.f);
    }
}

__global__ void vn_mlp_kernel(const float* __restrict__ h2, const int* __restrict__ off,
                              const float* __restrict__ W1, const float* __restrict__ b1,
                              const float* __restrict__ g1, const float* __restrict__ be1,
                              const float* __restrict__ W2, const float* __restrict__ b2,
                              const float* __restrict__ g2, const float* __restrict__ be2,
                              float* __restrict__ vn)
{
    __shared__ float s[8][D];
    __shared__ float t[8][D];
    __shared__ float smu[8], srs[8];
    int d = threadIdx.x;
    int g0 = blockIdx.x * 8;

#pragma unroll
    for (int gg = 0; gg < 8; gg++) {
        int g = g0 + gg;
        float acc = vn[(size_t)g * D + d];
        int n1 = off[g + 1];
        for (int n = off[g]; n < n1; n++)
            acc += h2[(size_t)n * D + d];
        s[gg][d] = acc;
    }
    __syncthreads();

    float y[8];
#pragma unroll
    for (int gg = 0; gg < 8; gg++) y[gg] = b1[d];
    for (int k = 0; k < D; k++) {
        float w = W1[(size_t)k * D + d];
#pragma unroll
        for (int gg = 0; gg < 8; gg++) y[gg] = fmaf(s[gg][k], w, y[gg]);
    }
    __syncthreads();
#pragma unroll
    for (int gg = 0; gg < 8; gg++) t[gg][d] = y[gg];
    __syncthreads();
    ln_rows8(t, s, g1, be1, smu, srs);
    __syncthreads();

#pragma unroll
    for (int gg = 0; gg < 8; gg++) y[gg] = b2[d];
    for (int k = 0; k < D; k++) {
        float w = W2[(size_t)k * D + d];
#pragma unroll
        for (int gg = 0; gg < 8; gg++) y[gg] = fmaf(s[gg][k], w, y[gg]);
    }
    __syncthreads();
#pragma unroll
    for (int gg = 0; gg < 8; gg++) t[gg][d] = y[gg];
    __syncthreads();
    ln_rows8(t, s, g2, be2, smu, srs);
    __syncthreads();
#pragma unroll
    for (int gg = 0; gg < 8; gg++)
        vn[(size_t)(g0 + gg) * D + d] = s[gg][d];
}

// ---------------- launcher ----------------
extern "C" void kernel_launch(void* const* d_in, const int* in_sizes, int n_in,
                              void* d_out, int out_size)
{
    const int*   x          = (const int*)  d_in[0];
    const int*   edge_attr  = (const int*)  d_in[1];
    const int*   edge_index = (const int*)  d_in[2];
    const int*   batch      = (const int*)  d_in[3];
    const float* atom_emb   = (const float*)d_in[4];
    const float* bond_emb   = (const float*)d_in[5];
    const float* vn_emb     = (const float*)d_in[6];
    const float* gcn_w      = (const float*)d_in[7];
    const float* gcn_b      = (const float*)d_in[8];
    const float* norm_g     = (const float*)d_in[9];
    const float* norm_b     = (const float*)d_in[10];
    const float* ffn_w      = (const float*)d_in[11];
    const float* ffn_b      = (const float*)d_in[12];
    const float* vn_w1      = (const float*)d_in[13];
    const float* vn_b1      = (const float*)d_in[14];
    const float* vn_g1      = (const float*)d_in[15];
    const float* vn_be1     = (const float*)d_in[16];
    const float* vn_w2      = (const float*)d_in[17];
    const float* vn_b2      = (const float*)d_in[18];
    const float* vn_g2      = (const float*)d_in[19];
    const float* vn_be2     = (const float*)d_in[20];

    float* out       = (float*)d_out;                       // h_graph [N,256]
    float* out_hinit = out + (size_t)N_NODES * D;           // h_init  [N,256]

    float *hb0, *hb1, *ph2, *pagg, *pvn; int* poff;
    cudaGetSymbolAddress((void**)&hb0,  g_h);
    cudaGetSymbolAddress((void**)&hb1,  g_hb);
    cudaGetSymbolAddress((void**)&ph2,  g_h2);
    cudaGetSymbolAddress((void**)&pagg, g_agg);
    cudaGetSymbolAddress((void**)&pvn,  g_vn);
    cudaGetSymbolAddress((void**)&poff, g_off);

    static cudaStream_t s1 = nullptr;
    static cudaEvent_t evFork, evSide, evH[3], evF[3];
    if (!s1) {
        cudaStreamCreateWithFlags(&s1, cudaStreamNonBlocking);
        cudaEventCreateWithFlags(&evFork, cudaEventDisableTiming);
        cudaEventCreateWithFlags(&evSide, cudaEventDisableTiming);
        for (int i = 0; i < 3; i++) {
            cudaEventCreateWithFlags(&evH[i], cudaEventDisableTiming);
            cudaEventCreateWithFlags(&evF[i], cudaEventDisableTiming);
        }
        cudaFuncSetAttribute(gemm_fused, cudaFuncAttributeMaxDynamicSharedMemorySize, SM_TOTAL);
    }

    const int FUSED_GRID = (N_NODES + 63) / 64;    // 1563
    const int FFN_GRID   = (N_NODES + 127) / 128;  // 782
    const int AGG_GRID   = (N_NODES + 3) / 4;

    float* hwr[4]  = {hb0, hb1, hb0, hb1};
    float* hres[4] = {nullptr, hb0, hb1, hb0};

    // ---- fork: prologue on two streams ----
    cudaEventRecord(evFork, 0);
    cudaStreamWaitEvent(s1, evFork, 0);

    // stream 0: CSR build chain
    zero_deg_kernel<<<(N_NODES + 255) / 256, 256>>>();
    hist_kernel<<<(N_EDGES + 255) / 256, 256>>>(edge_index);
    scan_block_kernel<<<NBLK, SCAN_B>>>();
    scan_sums_kernel<<<1, 128>>>();
    add_off_kernel<<<(N_NODES + 255) / 256, 256>>>();
    fill_kernel<<<(N_EDGES + 255) / 256, 256>>>(edge_index, edge_attr);

    // stream 1: node init, combo table, graph offsets
    node_init_kernel<<<N_NODES / 4, 256, 0, s1>>>(x, (const float4*)atom_emb,
                                                  (const float4*)vn_emb,
                                                  (float4*)hb0, (float4*)pvn,
                                                  (float4*)out_hinit);
    combo_kernel<<<512, 256, 0, s1>>>(bond_emb);
    offsets_kernel<<<(NGRAPHS + 1 + 255) / 256, 256, 0, s1>>>(batch, poff);
    cudaEventRecord(evSide, s1);
    cudaStreamWaitEvent(0, evSide, 0);

    // ----- layer 0 -----
    aggregate_kernel<false><<<AGG_GRID, 256>>>((const float4*)hb0, nullptr, nullptr, (float4*)pagg);
    gemm_fused<<<FUSED_GRID, 256, SM_TOTAL>>>(pagg, gcn_w, gcn_b, nullptr,
                                              norm_g, norm_b, nullptr, nullptr,
                                              hwr[0], ph2, nullptr, N_NODES);
    cudaEventRecord(evH[0], 0);
    cudaStreamWaitEvent(s1, evH[0], 0);
    gemm_tf32<64, 4, 2><<<FFN_GRID, 256, 0, s1>>>(hwr[0], ffn_w, ffn_b, out, N_NODES, D, 64);
    cudaEventRecord(evF[0], s1);

    // ----- layers 1..2 (FFN on side stream) -----
    for (int l = 1; l < 3; l++) {
        int j = l - 1;
        vn_mlp_kernel<<<NGRAPHS / 8, 256>>>(ph2, poff,
                                            vn_w1 + (size_t)j * D * D, vn_b1 + (size_t)j * D,
                                            vn_g1 + (size_t)j * D,     vn_be1 + (size_t)j * D,
                                            vn_w2 + (size_t)j * D * D, vn_b2 + (size_t)j * D,
                                            vn_g2 + (size_t)j * D,     vn_be2 + (size_t)j * D,
                                            pvn);
        aggregate_kernel<true><<<AGG_GRID, 256>>>((const float4*)ph2, (const float4*)pvn,
                                                  batch, (float4*)pagg);
        if (l == 2) cudaStreamWaitEvent(0, evF[0], 0);    // about to rewrite hb0
        gemm_fused<<<FUSED_GRID, 256, SM_TOTAL>>>(pagg, gcn_w + (size_t)l * D * D,
                                                  gcn_b + (size_t)l * D, hres[l],
                                                  norm_g + (size_t)l * D, norm_b + (size_t)l * D,
                                                  nullptr, nullptr,
                                                  hwr[l], ph2, nullptr, N_NODES);
        cudaEventRecord(evH[l], 0);
        cudaStreamWaitEvent(s1, evH[l], 0);
        gemm_tf32<64, 4, 2><<<FFN_GRID, 256, 0, s1>>>(hwr[l], ffn_w + (size_t)l * D * 64,
                                                      ffn_b + (size_t)l * 64,
                                                      out + (size_t)l * 64, N_NODES, D, 64);
        cudaEventRecord(evF[l], s1);
    }

    // ----- layer 3 (FFN fused; nothing left to overlap) -----
    {
        int l = 3, j = 2;
        vn_mlp_kernel<<<NGRAPHS / 8, 256>>>(ph2, poff,
                                            vn_w1 + (size_t)j * D * D, vn_b1 + (size_t)j * D,
                                            vn_g1 + (size_t)j * D,     vn_be1 + (size_t)j * D,
                                            vn_w2 + (size_t)j * D * D, vn_b2 + (size_t)j * D,
                                            vn_g2 + (size_t)j * D,     vn_be2 + (size_t)j * D,
                                            pvn);
        aggregate_kernel<true><<<AGG_GRID, 256>>>((const float4*)ph2, (const float4*)pvn,
                                                  batch, (float4*)pagg);
        cudaStreamWaitEvent(0, evF[1], 0);                // about to rewrite hb1
        gemm_fused<<<FUSED_GRID, 256, SM_TOTAL>>>(pagg, gcn_w + (size_t)l * D * D,
                                                  gcn_b + (size_t)l * D, hres[l],
                                                  nullptr, nullptr,
                                                  ffn_w + (size_t)l * D * 64,
                                                  ffn_b + (size_t)l * 64,
                                                  hwr[l], ph2, out + (size_t)l * 64, N_NODES);
    }

    // ---- join side stream before returning ----
    cudaStreamWaitEvent(0, evF[2], 0);
}

// round 15
// speedup vs baseline: 1.2062x; 1.0333x over previous
#include <cuda_runtime.h>
#include <cuda_fp16.h>
#include <stddef.h>
#include <stdint.h>

#define N_NODES 100000
#define N_EDGES 300000
#define NGRAPHS 3000
#define D 256
#define MSG_EPS 1e-7f
#define LN_EPS  1e-5f
#define SCAN_B 1024
#define NBLK ((N_NODES + SCAN_B - 1) / SCAN_B)   // 98

// ---------------- scratch (static device allocations; no cudaMalloc) ----------------
__device__ __align__(16) float g_h  [(size_t)N_NODES * D];
__device__ __align__(16) float g_hb [(size_t)N_NODES * D];   // second h buffer (ping-pong)
__device__ __align__(16) float g_h2 [(size_t)N_NODES * D];
__device__ __align__(16) __half g_hh  [(size_t)N_NODES * D]; // fp16 copy of h (layer-0 gather src)
__device__ __align__(16) __half g_h2h [(size_t)N_NODES * D]; // fp16 copy of h2 (gather src)
__device__ __align__(16) __half g_aggh[(size_t)N_NODES * D]; // fp16 agg (GEMM A operand)
__device__ __align__(16) float g_vn [(size_t)NGRAPHS * D];
__device__ __align__(16) float g_combo[512 * D];
__device__ int g_off[NGRAPHS + 1];
__device__ int g_deg[N_NODES];
__device__ int g_noff[N_NODES + 1];
__device__ int g_cursor[N_NODES];
__device__ int g_elist[N_EDGES];
__device__ int g_bsum[NBLK];

__device__ __forceinline__ void cp_async16(uint32_t smem_dst, const void* gsrc) {
    asm volatile("cp.async.cg.shared.global [%0], [%1], 16;\n"
                 :: "r"(smem_dst), "l"(gsrc));
}
__device__ __forceinline__ void cp_commit() {
    asm volatile("cp.async.commit_group;\n" ::);
}
__device__ __forceinline__ void cp_wait0() {
    asm volatile("cp.async.wait_group 0;\n" ::: "memory");
}
__device__ __forceinline__ void cp_wait1() {
    asm volatile("cp.async.wait_group 1;\n" ::: "memory");
}
__device__ __forceinline__ float2 h2f2(unsigned u) {
    __half2 h = *reinterpret_cast<__half2*>(&u);
    return __half22float2(h);
}
__device__ __forceinline__ unsigned f22h2(float a, float b) {
    __half2 h = __floats2half2_rn(a, b);
    return *reinterpret_cast<unsigned*>(&h);
}

// ================= CSR build =================
__global__ void zero_deg_kernel() {
    int i = blockIdx.x * blockDim.x + threadIdx.x;
    if (i < N_NODES) g_deg[i] = 0;
}
__global__ void hist_kernel(const int* __restrict__ ei) {
    int e = blockIdx.x * blockDim.x + threadIdx.x;
    if (e < N_EDGES) atomicAdd(&g_deg[ei[N_EDGES + e]], 1);
}
__global__ void scan_block_kernel() {
    __shared__ int s[SCAN_B];
    int tid = threadIdx.x;
    int i = blockIdx.x * SCAN_B + tid;
    int v = (i < N_NODES) ? g_deg[i] : 0;
    s[tid] = v;
    __syncthreads();
#pragma unroll
    for (int d = 1; d < SCAN_B; d <<= 1) {
        int t = (tid >= d) ? s[tid - d] : 0;
        __syncthreads();
        s[tid] += t;
        __syncthreads();
    }
    if (i < N_NODES) g_noff[i + 1] = s[tid];
    if (tid == SCAN_B - 1) g_bsum[blockIdx.x] = s[tid];
}
__global__ void scan_sums_kernel() {
    __shared__ int s[128];
    int tid = threadIdx.x;
    int v = (tid < NBLK) ? g_bsum[tid] : 0;
    s[tid] = v;
    __syncthreads();
#pragma unroll
    for (int d = 1; d < 128; d <<= 1) {
        int t = (tid >= d) ? s[tid - d] : 0;
        __syncthreads();
        s[tid] += t;
        __syncthreads();
    }
    if (tid < NBLK) g_bsum[tid] = s[tid] - v;
    if (tid == 0) g_noff[0] = 0;
}
__global__ void add_off_kernel() {       // also seeds cursor
    int i = blockIdx.x * blockDim.x + threadIdx.x;
    if (i < N_NODES) {
        int v = g_noff[i + 1] + g_bsum[i / SCAN_B];
        g_noff[i + 1] = v;
        if (i + 1 < N_NODES) g_cursor[i + 1] = v;
        if (i == 0) g_cursor[0] = 0;
    }
}
__global__ void fill_kernel(const int* __restrict__ ei, const int* __restrict__ ea) {
    int e = blockIdx.x * blockDim.x + threadIdx.x;
    if (e >= N_EDGES) return;
    int src = ei[e];
    int dst = ei[N_EDGES + e];
    int combo = ea[3 * e + 0] | (ea[3 * e + 1] << 3) | (ea[3 * e + 2] << 6);
    int pos = atomicAdd(&g_cursor[dst], 1);
    g_elist[pos] = src | (combo << 17);
}
__global__ void combo_kernel(const float* __restrict__ bond) {
    int c = blockIdx.x;
    int d = threadIdx.x;
    int a0 = c & 7, a1 = (c >> 3) & 7, a2 = (c >> 6) & 7;
    g_combo[c * D + d] = bond[(size_t)(0 * 8 + a0) * D + d]
                       + bond[(size_t)(1 * 8 + a1) * D + d]
                       + bond[(size_t)(2 * 8 + a2) * D + d];
}

// ---------------- node init (4 nodes/block, float4) ----------------
__global__ void node_init_kernel(const int* __restrict__ x,
                                 const float4* __restrict__ atom_emb,
                                 const float4* __restrict__ vn_emb,
                                 float4* __restrict__ h,
                                 uint2* __restrict__ hh,
                                 float4* __restrict__ vn,
                                 float4* __restrict__ out_hinit)
{
    int n = blockIdx.x * 4 + (threadIdx.x >> 6);
    if (n >= N_NODES) return;
    int q = threadIdx.x & 63;
    float4 s = make_float4(0.f, 0.f, 0.f, 0.f);
#pragma unroll
    for (int f = 0; f < 9; f++) {
        int xi = __ldg(&x[n * 9 + f]);
        float4 v = atom_emb[((size_t)f * 64 + xi) * 64 + q];
        s.x += v.x; s.y += v.y; s.z += v.z; s.w += v.w;
    }
    size_t idx = (size_t)n * 64 + q;
    out_hinit[idx] = s;
    float4 vv = vn_emb[q];
    float4 hv = make_float4(s.x + vv.x, s.y + vv.y, s.z + vv.z, s.w + vv.w);
    h[idx] = hv;
    uint2 hu;
    hu.x = f22h2(hv.x, hv.y);
    hu.y = f22h2(hv.z, hv.w);
    hh[idx] = hu;
    if (n < NGRAPHS) vn[(size_t)n * 64 + q] = vv;
}

// ---------------- graph segment offsets ----------------
__global__ void offsets_kernel(const int* __restrict__ batch, int* __restrict__ off)
{
    int g = blockIdx.x * blockDim.x + threadIdx.x;
    if (g > NGRAPHS) return;
    int lo = 0, hi = N_NODES;
    while (lo < hi) {
        int mid = (lo + hi) >> 1;
        if (batch[mid] < g) lo = mid + 1; else hi = mid;
    }
    off[g] = lo;
}

// ---------------- CSR gather aggregation (fp16 in, fp16 out, fp32 math) ----------------
template<bool WITHVN>
__global__ void aggregate_kernel(const uint2* __restrict__ hin,    // fp16, 4 halves/uint2
                                 const float4* __restrict__ vn,
                                 const int* __restrict__ batch,
                                 uint2* __restrict__ agg)          // fp16 out
{
    int n = blockIdx.x * 4 + (threadIdx.x >> 6);
    if (n >= N_NODES) return;
    int q = threadIdx.x & 63;
    const float4* combo4 = reinterpret_cast<const float4*>(g_combo);
    int i0 = g_noff[n], i1 = g_noff[n + 1];
    uint2 su = hin[(size_t)n * 64 + q];
    float2 s01 = h2f2(su.x), s23 = h2f2(su.y);
    float ax = s01.x, ay = s01.y, az = s23.x, aw = s23.y;
    if (WITHVN) {
        int bg = __ldg(&batch[n]);
        float4 vv = vn[(size_t)bg * 64 + q];
        ax += vv.x; ay += vv.y; az += vv.z; aw += vv.w;
    }
    int i = i0;
    for (; i + 1 < i1; i += 2) {
        int ed0 = __ldg(&g_elist[i]);
        int ed1 = __ldg(&g_elist[i + 1]);
        int s0 = ed0 & 0x1FFFF, c0 = ed0 >> 17;
        int s1 = ed1 & 0x1FFFF, c1 = ed1 >> 17;
        uint2 u0 = hin[(size_t)s0 * 64 + q];
        uint2 u1 = hin[(size_t)s1 * 64 + q];
        float2 v0a = h2f2(u0.x), v0b = h2f2(u0.y);
        float2 v1a = h2f2(u1.x), v1b = h2f2(u1.y);
        float4 b0 = combo4[(size_t)c0 * 64 + q];
        float4 b1 = combo4[(size_t)c1 * 64 + q];
        if (WITHVN) {
            int bg0 = __ldg(&batch[s0]);
            int bg1 = __ldg(&batch[s1]);
            float4 w0 = vn[(size_t)bg0 * 64 + q];
            float4 w1 = vn[(size_t)bg1 * 64 + q];
            v0a.x += w0.x; v0a.y += w0.y; v0b.x += w0.z; v0b.y += w0.w;
            v1a.x += w1.x; v1a.y += w1.y; v1b.x += w1.z; v1b.y += w1.w;
        }
        ax += fmaxf(v0a.x + b0.x, 0.f) + MSG_EPS + fmaxf(v1a.x + b1.x, 0.f) + MSG_EPS;
        ay += fmaxf(v0a.y + b0.y, 0.f) + MSG_EPS + fmaxf(v1a.y + b1.y, 0.f) + MSG_EPS;
        az += fmaxf(v0b.x + b0.z, 0.f) + MSG_EPS + fmaxf(v1b.x + b1.z, 0.f) + MSG_EPS;
        aw += fmaxf(v0b.y + b0.w, 0.f) + MSG_EPS + fmaxf(v1b.y + b1.w, 0.f) + MSG_EPS;
    }
    if (i < i1) {
        int ed = __ldg(&g_elist[i]);
        int s0 = ed & 0x1FFFF, c0 = ed >> 17;
        uint2 u0 = hin[(size_t)s0 * 64 + q];
        float2 va = h2f2(u0.x), vb = h2f2(u0.y);
        float4 b = combo4[(size_t)c0 * 64 + q];
        if (WITHVN) {
            int bg0 = __ldg(&batch[s0]);
            float4 w = vn[(size_t)bg0 * 64 + q];
            va.x += w.x; va.y += w.y; vb.x += w.z; vb.y += w.w;
        }
        ax += fmaxf(va.x + b.x, 0.f) + MSG_EPS;
        ay += fmaxf(va.y + b.y, 0.f) + MSG_EPS;
        az += fmaxf(vb.x + b.z, 0.f) + MSG_EPS;
        aw += fmaxf(vb.y + b.w, 0.f) + MSG_EPS;
    }
    uint2 ou;
    ou.x = f22h2(ax, ay);
    ou.y = f22h2(az, aw);
    agg[(size_t)n * 64 + q] = ou;
}

// ---------------- tf32 helpers ----------------
__device__ __forceinline__ float tf32r(float x) {
    uint32_t u;
    asm("cvt.rna.tf32.f32 %0, %1;" : "=r"(u) : "f"(x));
    return __uint_as_float(u);
}
__device__ __forceinline__ uint32_t tf32u(float x) {
    uint32_t u;
    asm("cvt.rna.tf32.f32 %0, %1;" : "=r"(u) : "f"(x));
    return u;
}
__device__ __forceinline__ void mma_tf32(float* c, const uint32_t* a, const uint32_t* b) {
    asm volatile("mma.sync.aligned.m16n8k8.row.col.f32.tf32.tf32.f32 "
                 "{%0,%1,%2,%3}, {%4,%5,%6,%7}, {%8,%9}, {%0,%1,%2,%3};\n"
                 : "+f"(c[0]), "+f"(c[1]), "+f"(c[2]), "+f"(c[3])
                 : "r"(a[0]), "r"(a[1]), "r"(a[2]), "r"(a[3]),
                   "r"(b[0]), "r"(b[1]));
}

// ==================== fused GCN GEMM + residual + LN/ReLU [+ FFN] ====================
// A operand is fp16 (agg); fp16->fp32 is exact and fits tf32 (11-bit significand).
// BM=64, BN=256; 3-stage cp.async B pipeline; FFN phase only for layer 3.
#define HT_STRIDE 260
#define SM_AS   0
#define SM_BS   9216
#define SM_WF   66560
#define SM_SSA  80384
#define SM_SSB  81664
#define SM_MU   82944
#define SM_RS   83200
#define SM_TOTAL 83456

__global__ __launch_bounds__(256)
void gemm_fused(const __half* __restrict__ A16,
                const float* __restrict__ W, const float* __restrict__ bias,
                const float* __restrict__ res,
                const float* __restrict__ gam, const float* __restrict__ bet,
                const float* __restrict__ ffnW, const float* __restrict__ ffnB,
                float* __restrict__ outh, float* __restrict__ outh2,
                __half* __restrict__ outh2h,
                float* __restrict__ outf, int M)
{
    constexpr int BM = 64, BN = 256, BK = 16, K = D;
    constexpr int NITER = K / BK;
    constexpr int MT = 2, NT = 8;
    extern __shared__ char smraw[];
    float* As = reinterpret_cast<float*>(smraw + SM_AS);   // [buf*16+k][72]
    float* Bs = reinterpret_cast<float*>(smraw + SM_BS);   // [buf*16+k][264], 3 bufs
    float* HT = reinterpret_cast<float*>(smraw);           // [64][HT_STRIDE]
    float* Wf = reinterpret_cast<float*>(smraw + SM_WF);   // [buf*16+k][72], 3 bufs
    float* ssA = reinterpret_cast<float*>(smraw + SM_SSA);
    float* ssB = reinterpret_cast<float*>(smraw + SM_SSB);
    float* smu = reinterpret_cast<float*>(smraw + SM_MU);
    float* srs = reinterpret_cast<float*>(smraw + SM_RS);
    const uint32_t smbase = (uint32_t)__cvta_generic_to_shared(smraw);

    const int tid  = threadIdx.x;
    const int lane = tid & 31;
    const int wid  = tid >> 5;
    const int wr   = wid >> 2;
    const int wc   = wid & 3;
    const int gid  = lane >> 2;
    const int tig  = lane & 3;
    const int m0   = blockIdx.x * BM;

    const int arow = tid & 63;
    const int akc  = (tid >> 6) << 2;
    const bool avalid = (m0 + arow) < M;
    const uint2* aptr = reinterpret_cast<const uint2*>(A16 + (size_t)(m0 + arow) * K + akc);

    const int bk  = tid >> 4;
    const int bnc = (tid & 15) << 4;
    const float* bptr = W + (size_t)bk * BN + bnc;

    // ---- prologue: B stages 0 and 1 in flight ----
    {
        uint32_t dst0 = smbase + SM_BS + (uint32_t)((bk * 264 + bnc) * 4);
#pragma unroll
        for (int j = 0; j < 4; j++)
            cp_async16(dst0 + j * 16, bptr + j * 4);
        cp_commit();
        uint32_t dst1 = smbase + SM_BS + (uint32_t)(((16 + bk) * 264 + bnc) * 4);
        const float* bp1 = bptr + (size_t)BK * BN;
#pragma unroll
        for (int j = 0; j < 4; j++)
            cp_async16(dst1 + j * 16, bp1 + j * 4);
        cp_commit();
    }
    {
        uint2 au = make_uint2(0u, 0u);
        if (avalid) au = aptr[0];
        float2 a01 = h2f2(au.x), a23 = h2f2(au.y);
        As[(akc + 0) * 72 + arow] = a01.x;
        As[(akc + 1) * 72 + arow] = a01.y;
        As[(akc + 2) * 72 + arow] = a23.x;
        As[(akc + 3) * 72 + arow] = a23.y;
    }
    cp_wait1();
    __syncthreads();

    float acc[MT][NT][4];
#pragma unroll
    for (int i = 0; i < MT; i++)
#pragma unroll
        for (int j = 0; j < NT; j++)
#pragma unroll
            for (int q = 0; q < 4; q++) acc[i][j][q] = 0.f;

    for (int k0 = 0; k0 < NITER; k0++) {
        const int acur = k0 & 1;
        const int bcur = k0 % 3;
        uint2 au = make_uint2(0u, 0u);
        if (k0 + 2 < NITER) {
            const int bnx = (k0 + 2) % 3;
            uint32_t dst = smbase + SM_BS + (uint32_t)(((bnx * 16 + bk) * 264 + bnc) * 4);
            const float* bp = bptr + (size_t)(k0 + 2) * BK * BN;
#pragma unroll
            for (int j = 0; j < 4; j++)
                cp_async16(dst + j * 16, bp + j * 4);
            cp_commit();
        }
        if (k0 + 1 < NITER) {
            if (avalid) au = aptr[(k0 + 1) * (BK / 4)];
        }
#pragma unroll
        for (int ks = 0; ks < 2; ks++) {
            uint32_t af[MT][4];
            uint32_t bf[NT][2];
#pragma unroll
            for (int mt = 0; mt < MT; mt++) {
                int r = wr * 32 + mt * 16 + gid;
                af[mt][0] = __float_as_uint(As[(acur * 16 + ks * 8 + tig) * 72 + r]);
                af[mt][1] = __float_as_uint(As[(acur * 16 + ks * 8 + tig) * 72 + r + 8]);
                af[mt][2] = __float_as_uint(As[(acur * 16 + ks * 8 + tig + 4) * 72 + r]);
                af[mt][3] = __float_as_uint(As[(acur * 16 + ks * 8 + tig + 4) * 72 + r + 8]);
            }
#pragma unroll
            for (int nt = 0; nt < NT; nt++) {
                int c = wc * 64 + nt * 8 + gid;
                bf[nt][0] = tf32u(Bs[(bcur * 16 + ks * 8 + tig) * 264 + c]);
                bf[nt][1] = tf32u(Bs[(bcur * 16 + ks * 8 + tig + 4) * 264 + c]);
            }
#pragma unroll
            for (int mt = 0; mt < MT; mt++)
#pragma unroll
                for (int nt = 0; nt < NT; nt++)
                    mma_tf32(acc[mt][nt], af[mt], bf[nt]);
        }
        if (k0 + 1 < NITER) {
            const int anx = acur ^ 1;
            float2 a01 = h2f2(au.x), a23 = h2f2(au.y);
            As[(anx * 16 + akc + 0) * 72 + arow] = a01.x;
            As[(anx * 16 + akc + 1) * 72 + arow] = a01.y;
            As[(anx * 16 + akc + 2) * 72 + arow] = a23.x;
            As[(anx * 16 + akc + 3) * 72 + arow] = a23.y;
            if (k0 + 2 < NITER) cp_wait1(); else cp_wait0();
            __syncthreads();
        }
    }

    if (ffnW) {   // prefetch FFN W chunks 0 and 1
        int kr = tid >> 4;
        int wcol = (tid & 15) << 2;
        uint32_t dst0 = smbase + SM_WF + (uint32_t)((kr * 72 + wcol) * 4);
        cp_async16(dst0, ffnW + (size_t)kr * 64 + wcol);
        cp_commit();
        uint32_t dst1 = smbase + SM_WF + (uint32_t)(((16 + kr) * 72 + wcol) * 4);
        cp_async16(dst1, ffnW + (size_t)(16 + kr) * 64 + wcol);
        cp_commit();
    }

    // ---- epilogue: v = acc + bias (+res); write h ----
#pragma unroll
    for (int mt = 0; mt < MT; mt++) {
        int r  = m0 + wr * 32 + mt * 16 + gid;
        int r2 = r + 8;
#pragma unroll
        for (int nt = 0; nt < NT; nt++) {
            int c = wc * 64 + nt * 8 + 2 * tig;
            float2 bi = *reinterpret_cast<const float2*>(&bias[c]);
            float v0 = acc[mt][nt][0] + bi.x;
            float v1 = acc[mt][nt][1] + bi.y;
            float v2 = acc[mt][nt][2] + bi.x;
            float v3 = acc[mt][nt][3] + bi.y;
            if (res) {
                if (r < M) {
                    float2 rr = *reinterpret_cast<const float2*>(&res[(size_t)r * D + c]);
                    v0 += rr.x; v1 += rr.y;
                }
                if (r2 < M) {
                    float2 rr = *reinterpret_cast<const float2*>(&res[(size_t)r2 * D + c]);
                    v2 += rr.x; v3 += rr.y;
                }
            }
            acc[mt][nt][0] = v0; acc[mt][nt][1] = v1;
            acc[mt][nt][2] = v2; acc[mt][nt][3] = v3;
            if (r < M)
                *reinterpret_cast<float2*>(&outh[(size_t)r * D + c]) = make_float2(v0, v1);
            if (r2 < M)
                *reinterpret_cast<float2*>(&outh[(size_t)r2 * D + c]) = make_float2(v2, v3);
        }
    }

    if (ffnW) {   // mainloop smem reads done -> h_tile
        __syncthreads();
#pragma unroll
        for (int mt = 0; mt < MT; mt++) {
            int lr  = wr * 32 + mt * 16 + gid;
            int lr2 = lr + 8;
#pragma unroll
            for (int nt = 0; nt < NT; nt++) {
                int c = wc * 64 + nt * 8 + 2 * tig;
                HT[lr  * HT_STRIDE + c    ] = tf32r(acc[mt][nt][0]);
                HT[lr  * HT_STRIDE + c + 1] = tf32r(acc[mt][nt][1]);
                HT[lr2 * HT_STRIDE + c    ] = tf32r(acc[mt][nt][2]);
                HT[lr2 * HT_STRIDE + c + 1] = tf32r(acc[mt][nt][3]);
            }
        }
    }

    // ---- LayerNorm + ReLU -> outh2 (fp32) + outh2h (fp16) ----
    if (gam) {
#pragma unroll
        for (int mt = 0; mt < MT; mt++) {
#pragma unroll
            for (int hh = 0; hh < 2; hh++) {
                float s = 0.f, q = 0.f;
#pragma unroll
                for (int nt = 0; nt < NT; nt++) {
                    float u0 = acc[mt][nt][2 * hh];
                    float u1 = acc[mt][nt][2 * hh + 1];
                    s += u0 + u1;
                    q += u0 * u0 + u1 * u1;
                }
                s += __shfl_xor_sync(0xffffffffu, s, 1);
                q += __shfl_xor_sync(0xffffffffu, q, 1);
                s += __shfl_xor_sync(0xffffffffu, s, 2);
                q += __shfl_xor_sync(0xffffffffu, q, 2);
                if (tig == 0) {
                    int lr = wr * 32 + mt * 16 + hh * 8 + gid;
                    ssA[lr * 5 + wc] = s;
                    ssB[lr * 5 + wc] = q;
                }
            }
        }
        __syncthreads();
        if (tid < BM) {
            float s = ssA[tid * 5 + 0] + ssA[tid * 5 + 1] + ssA[tid * 5 + 2] + ssA[tid * 5 + 3];
            float q = ssB[tid * 5 + 0] + ssB[tid * 5 + 1] + ssB[tid * 5 + 2] + ssB[tid * 5 + 3];
            float mu  = s * (1.f / D);
            float var = q * (1.f / D) - mu * mu;
            smu[tid] = mu;
            srs[tid] = rsqrtf(var + LN_EPS);
        }
        __syncthreads();
#pragma unroll
        for (int mt = 0; mt < MT; mt++) {
            int lr  = wr * 32 + mt * 16 + gid;
            int lr2 = lr + 8;
            int r   = m0 + lr;
            int r2  = m0 + lr2;
            float mu0 = smu[lr],  rs0 = srs[lr];
            float mu1 = smu[lr2], rs1 = srs[lr2];
#pragma unroll
            for (int nt = 0; nt < NT; nt++) {
                int c = wc * 64 + nt * 8 + 2 * tig;
                float2 gg = *reinterpret_cast<const float2*>(&gam[c]);
                float2 bb = *reinterpret_cast<const float2*>(&bet[c]);
                if (r < M) {
                    float y0 = fmaxf((acc[mt][nt][0] - mu0) * rs0 * gg.x + bb.x, 0.f);
                    float y1 = fmaxf((acc[mt][nt][1] - mu0) * rs0 * gg.y + bb.y, 0.f);
                    *reinterpret_cast<float2*>(&outh2[(size_t)r * D + c]) = make_float2(y0, y1);
                    *reinterpret_cast<unsigned*>(&outh2h[(size_t)r * D + c]) = f22h2(y0, y1);
                }
                if (r2 < M) {
                    float y2 = fmaxf((acc[mt][nt][2] - mu1) * rs1 * gg.x + bb.x, 0.f);
                    float y3 = fmaxf((acc[mt][nt][3] - mu1) * rs1 * gg.y + bb.y, 0.f);
                    *reinterpret_cast<float2*>(&outh2[(size_t)r2 * D + c]) = make_float2(y2, y3);
                    *reinterpret_cast<unsigned*>(&outh2h[(size_t)r2 * D + c]) = f22h2(y2, y3);
                }
            }
        }
    }

    if (!ffnW) return;

    // ---- FFN phase: outf = h_tile @ ffnW + ffnB, 64x64x256, 3-stage Wf ----
    const int wrf = wid >> 1;
    const int wcf = wid & 1;
    const int fkr = tid >> 4;
    const int fwc = (tid & 15) << 2;
    cp_wait1();
    __syncthreads();

    float fac[4][4];
#pragma unroll
    for (int i = 0; i < 4; i++)
#pragma unroll
        for (int j = 0; j < 4; j++) fac[i][j] = 0.f;

    constexpr int FCH = 16;
    for (int ch = 0; ch < FCH; ch++) {
        const int cur = ch % 3;
        if (ch + 2 < FCH) {
            const int nx = (ch + 2) % 3;
            uint32_t dst = smbase + SM_WF + (uint32_t)(((nx * 16 + fkr) * 72 + fwc) * 4);
            cp_async16(dst, ffnW + (size_t)((ch + 2) * 16 + fkr) * 64 + fwc);
            cp_commit();
        }
#pragma unroll
        for (int ks = 0; ks < 2; ks++) {
            int kb = ch * 16 + ks * 8;
            uint32_t af[4];
            {
                int r = wrf * 16 + gid;
                af[0] = __float_as_uint(HT[r * HT_STRIDE + kb + tig]);
                af[1] = __float_as_uint(HT[(r + 8) * HT_STRIDE + kb + tig]);
                af[2] = __float_as_uint(HT[r * HT_STRIDE + kb + tig + 4]);
                af[3] = __float_as_uint(HT[(r + 8) * HT_STRIDE + kb + tig + 4]);
            }
#pragma unroll
            for (int nt = 0; nt < 4; nt++) {
                int c = wcf * 32 + nt * 8 + gid;
                uint32_t bf[2];
                bf[0] = tf32u(Wf[(cur * 16 + ks * 8 + tig) * 72 + c]);
                bf[1] = tf32u(Wf[(cur * 16 + ks * 8 + tig + 4) * 72 + c]);
                mma_tf32(fac[nt], af, bf);
            }
        }
        if (ch + 1 < FCH) {
            if (ch + 2 < FCH) cp_wait1(); else cp_wait0();
            __syncthreads();
        }
    }

    {
        int r  = m0 + wrf * 16 + gid;
        int r2 = r + 8;
#pragma unroll
        for (int nt = 0; nt < 4; nt++) {
            int c = wcf * 32 + nt * 8 + 2 * tig;
            float2 bi = *reinterpret_cast<const float2*>(&ffnB[c]);
            if (r < M)
                *reinterpret_cast<float2*>(&outf[(size_t)r * 256 + c]) =
                    make_float2(fac[nt][0] + bi.x, fac[nt][1] + bi.y);
            if (r2 < M)
                *reinterpret_cast<float2*>(&outf[(size_t)r2 * 256 + c]) =
                    make_float2(fac[nt][2] + bi.x, fac[nt][3] + bi.y);
        }
    }
}

// ---------------- standalone tf32 FFN GEMM (runs on side stream; fp32 A = h) ----------------
template<int BN, int WR, int WC>
__global__ __launch_bounds__(256)
void gemm_tf32(const float* __restrict__ A,
               const float* __restrict__ W, const float* __restrict__ bias,
               float* __restrict__ out,
               int M, int ldout, int ldw)
{
    constexpr int BM = 128, BK = 16, K = D;
    constexpr int NITER = K / BK;
    constexpr int TM = BM / WR;
    constexpr int TN = BN / WC;
    constexpr int MT = TM / 16;
    constexpr int NT = TN / 8;
    constexpr int PAD = 8;
    __shared__ float As[2][BK][BM + PAD];
    __shared__ float Bs[2][BK][BN + PAD];

    const int tid  = threadIdx.x;
    const int lane = tid & 31;
    const int wid  = tid >> 5;
    const int wr   = wid / WC;
    const int wc   = wid % WC;
    const int gid  = lane >> 2;
    const int tig  = lane & 3;
    const int m0   = blockIdx.x * BM;

    const int arow = tid & 127;
    const int akc  = (tid >> 7) << 3;
    const bool avalid = (m0 + arow) < M;
    const float* aptr = A + (size_t)(m0 + arow) * K + akc;

    constexpr int BVEC = (BN == 128) ? 2 : 1;
    const int bk  = tid >> 4;
    const int bnc = (tid & 15) * (BVEC * 4);
    const float* bptr = W + (size_t)bk * ldw + bnc;

    float4 a_st[2];
    float4 b_st[BVEC];

    a_st[0] = make_float4(0.f, 0.f, 0.f, 0.f);
    a_st[1] = a_st[0];
    if (avalid) {
        a_st[0] = *reinterpret_cast<const float4*>(aptr);
        a_st[1] = *reinterpret_cast<const float4*>(aptr + 4);
    }
#pragma unroll
    for (int i = 0; i < BVEC; i++)
        b_st[i] = *reinterpret_cast<const float4*>(bptr + i * 4);

    {
        const float* av = reinterpret_cast<const float*>(a_st);
#pragma unroll
        for (int j = 0; j < 8; j++) As[0][akc + j][arow] = tf32r(av[j]);
        const float* bv = reinterpret_cast<const float*>(b_st);
#pragma unroll
        for (int j = 0; j < BVEC * 4; j++) Bs[0][bk][bnc + j] = tf32r(bv[j]);
    }
    __syncthreads();

    float acc[MT][NT][4];
#pragma unroll
    for (int i = 0; i < MT; i++)
#pragma unroll
        for (int j = 0; j < NT; j++)
#pragma unroll
            for (int q = 0; q < 4; q++) acc[i][j][q] = 0.f;

    for (int k0 = 0; k0 < NITER; k0++) {
        const int cur = k0 & 1;
        if (k0 + 1 < NITER) {
            a_st[0] = make_float4(0.f, 0.f, 0.f, 0.f);
            a_st[1] = a_st[0];
            if (avalid) {
                a_st[0] = *reinterpret_cast<const float4*>(aptr + (k0 + 1) * BK);
                a_st[1] = *reinterpret_cast<const float4*>(aptr + (k0 + 1) * BK + 4);
            }
#pragma unroll
            for (int i = 0; i < BVEC; i++)
                b_st[i] = *reinterpret_cast<const float4*>(bptr + (size_t)(k0 + 1) * BK * ldw + i * 4);
        }
#pragma unroll
        for (int ks = 0; ks < 2; ks++) {
            uint32_t af[MT][4];
            uint32_t bf[NT][2];
#pragma unroll
            for (int mt = 0; mt < MT; mt++) {
                int r = wr * TM + mt * 16 + gid;
                af[mt][0] = __float_as_uint(As[cur][ks * 8 + tig    ][r]);
                af[mt][1] = __float_as_uint(As[cur][ks * 8 + tig    ][r + 8]);
                af[mt][2] = __float_as_uint(As[cur][ks * 8 + tig + 4][r]);
                af[mt][3] = __float_as_uint(As[cur][ks * 8 + tig + 4][r + 8]);
            }
#pragma unroll
            for (int nt = 0; nt < NT; nt++) {
                int c = wc * TN + nt * 8 + gid;
                bf[nt][0] = __float_as_uint(Bs[cur][ks * 8 + tig    ][c]);
                bf[nt][1] = __float_as_uint(Bs[cur][ks * 8 + tig + 4][c]);
            }
#pragma unroll
            for (int mt = 0; mt < MT; mt++)
#pragma unroll
                for (int nt = 0; nt < NT; nt++)
                    mma_tf32(acc[mt][nt], af[mt], bf[nt]);
        }
        if (k0 + 1 < NITER) {
            const int nxt = cur ^ 1;
            const float* av = reinterpret_cast<const float*>(a_st);
#pragma unroll
            for (int j = 0; j < 8; j++) As[nxt][akc + j][arow] = tf32r(av[j]);
            const float* bv = reinterpret_cast<const float*>(b_st);
#pragma unroll
            for (int j = 0; j < BVEC * 4; j++) Bs[nxt][bk][bnc + j] = tf32r(bv[j]);
            __syncthreads();
        }
    }

#pragma unroll
    for (int mt = 0; mt < MT; mt++) {
#pragma unroll
        for (int nt = 0; nt < NT; nt++) {
            int r = m0 + wr * TM + mt * 16 + gid;
            int c = wc * TN + nt * 8 + 2 * tig;
            float2 bi = *reinterpret_cast<const float2*>(&bias[c]);
            if (r < M)
                *reinterpret_cast<float2*>(&out[(size_t)r * ldout + c]) =
                    make_float2(acc[mt][nt][0] + bi.x, acc[mt][nt][1] + bi.y);
            int r2 = r + 8;
            if (r2 < M)
                *reinterpret_cast<float2*>(&out[(size_t)r2 * ldout + c]) =
                    make_float2(acc[mt][nt][2] + bi.x, acc[mt][nt][3] + bi.y);
        }
    }
}

// ---------------- virtual-node path (fp32 h2) ----------------
__device__ __forceinline__ void ln_rows8(float (*t)[D], float (*s)[D],
                                         const float* __restrict__ gam,
                                         const float* __restrict__ bet,
                                         float* smu, float* srs)
{
    int lane = threadIdx.x & 31, w = threadIdx.x >> 5;
    float a = 0.f, b = 0.f;
#pragma unroll
    for (int i = 0; i < 8; i++) {
        float v = t[w][lane + 32 * i];
        a += v; b += v * v;
    }
#pragma unroll
    for (int o = 16; o; o >>= 1) {
        a += __shfl_down_sync(0xffffffffu, a, o);
        b += __shfl_down_sync(0xffffffffu, b, o);
    }
    if (lane == 0) {
        float mu = a * (1.f / D);
        float var = b * (1.f / D) - mu * mu;
        smu[w] = mu;
        srs[w] = rsqrtf(var + LN_EPS);
    }
    __syncthreads();
    int d = threadIdx.x;
    float gd = gam[d], bd = bet[d];
#pragma unroll
    for (int gg = 0; gg < 8; gg++) {
        float v = (t[gg][d] - smu[gg]) * srs[gg] * gd + bd;
        s[gg][d] = fmaxf(v, 0.f);
    }
}

__global__ void vn_mlp_kernel(const float* __restrict__ h2, const int* __restrict__ off,
                              const float* __restrict__ W1, const float* __restrict__ b1,
                              const float* __restrict__ g1, const float* __restrict__ be1,
                              const float* __restrict__ W2, const float* __restrict__ b2,
                              const float* __restrict__ g2, const float* __restrict__ be2,
                              float* __restrict__ vn)
{
    __shared__ float s[8][D];
    __shared__ float t[8][D];
    __shared__ float smu[8], srs[8];
    int d = threadIdx.x;
    int g0 = blockIdx.x * 8;

#pragma unroll
    for (int gg = 0; gg < 8; gg++) {
        int g = g0 + gg;
        float acc = vn[(size_t)g * D + d];
        int n1 = off[g + 1];
        for (int n = off[g]; n < n1; n++)
            acc += h2[(size_t)n * D + d];
        s[gg][d] = acc;
    }
    __syncthreads();

    float y[8];
#pragma unroll
    for (int gg = 0; gg < 8; gg++) y[gg] = b1[d];
    for (int k = 0; k < D; k++) {
        float w = W1[(size_t)k * D + d];
#pragma unroll
        for (int gg = 0; gg < 8; gg++) y[gg] = fmaf(s[gg][k], w, y[gg]);
    }
    __syncthreads();
#pragma unroll
    for (int gg = 0; gg < 8; gg++) t[gg][d] = y[gg];
    __syncthreads();
    ln_rows8(t, s, g1, be1, smu, srs);
    __syncthreads();

#pragma unroll
    for (int gg = 0; gg < 8; gg++) y[gg] = b2[d];
    for (int k = 0; k < D; k++) {
        float w = W2[(size_t)k * D + d];
#pragma unroll
        for (int gg = 0; gg < 8; gg++) y[gg] = fmaf(s[gg][k], w, y[gg]);
    }
    __syncthreads();
#pragma unroll
    for (int gg = 0; gg < 8; gg++) t[gg][d] = y[gg];
    __syncthreads();
    ln_rows8(t, s, g2, be2, smu, srs);
    __syncthreads();
#pragma unroll
    for (int gg = 0; gg < 8; gg++)
        vn[(size_t)(g0 + gg) * D + d] = s[gg][d];
}

// ---------------- launcher ----------------
extern "C" void kernel_launch(void* const* d_in, const int* in_sizes, int n_in,
                              void* d_out, int out_size)
{
    const int*   x          = (const int*)  d_in[0];
    const int*   edge_attr  = (const int*)  d_in[1];
    const int*   edge_index = (const int*)  d_in[2];
    const int*   batch      = (const int*)  d_in[3];
    const float* atom_emb   = (const float*)d_in[4];
    const float* bond_emb   = (const float*)d_in[5];
    const float* vn_emb     = (const float*)d_in[6];
    const float* gcn_w      = (const float*)d_in[7];
    const float* gcn_b      = (const float*)d_in[8];
    const float* norm_g     = (const float*)d_in[9];
    const float* norm_b     = (const float*)d_in[10];
    const float* ffn_w      = (const float*)d_in[11];
    const float* ffn_b      = (const float*)d_in[12];
    const float* vn_w1      = (const float*)d_in[13];
    const float* vn_b1      = (const float*)d_in[14];
    const float* vn_g1      = (const float*)d_in[15];
    const float* vn_be1     = (const float*)d_in[16];
    const float* vn_w2      = (const float*)d_in[17];
    const float* vn_b2      = (const float*)d_in[18];
    const float* vn_g2      = (const float*)d_in[19];
    const float* vn_be2     = (const float*)d_in[20];

    float* out       = (float*)d_out;                       // h_graph [N,256]
    float* out_hinit = out + (size_t)N_NODES * D;           // h_init  [N,256]

    float *hb0, *hb1, *ph2, *pvn; int* poff;
    __half *phh, *ph2h, *paggh;
    cudaGetSymbolAddress((void**)&hb0,  g_h);
    cudaGetSymbolAddress((void**)&hb1,  g_hb);
    cudaGetSymbolAddress((void**)&ph2,  g_h2);
    cudaGetSymbolAddress((void**)&phh,  g_hh);
    cudaGetSymbolAddress((void**)&ph2h, g_h2h);
    cudaGetSymbolAddress((void**)&paggh, g_aggh);
    cudaGetSymbolAddress((void**)&pvn,  g_vn);
    cudaGetSymbolAddress((void**)&poff, g_off);

    static cudaStream_t s1 = nullptr;
    static cudaEvent_t evFork, evSide, evH[3], evF[3];
    if (!s1) {
        cudaStreamCreateWithFlags(&s1, cudaStreamNonBlocking);
        cudaEventCreateWithFlags(&evFork, cudaEventDisableTiming);
        cudaEventCreateWithFlags(&evSide, cudaEventDisableTiming);
        for (int i = 0; i < 3; i++) {
            cudaEventCreateWithFlags(&evH[i], cudaEventDisableTiming);
            cudaEventCreateWithFlags(&evF[i], cudaEventDisableTiming);
        }
        cudaFuncSetAttribute(gemm_fused, cudaFuncAttributeMaxDynamicSharedMemorySize, SM_TOTAL);
    }

    const int FUSED_GRID = (N_NODES + 63) / 64;    // 1563
    const int FFN_GRID   = (N_NODES + 127) / 128;  // 782
    const int AGG_GRID   = (N_NODES + 3) / 4;

    float* hwr[4]  = {hb0, hb1, hb0, hb1};
    float* hres[4] = {nullptr, hb0, hb1, hb0};

    // ---- fork: prologue on two streams ----
    cudaEventRecord(evFork, 0);
    cudaStreamWaitEvent(s1, evFork, 0);

    // stream 0: CSR build chain
    zero_deg_kernel<<<(N_NODES + 255) / 256, 256>>>();
    hist_kernel<<<(N_EDGES + 255) / 256, 256>>>(edge_index);
    scan_block_kernel<<<NBLK, SCAN_B>>>();
    scan_sums_kernel<<<1, 128>>>();
    add_off_kernel<<<(N_NODES + 255) / 256, 256>>>();
    fill_kernel<<<(N_EDGES + 255) / 256, 256>>>(edge_index, edge_attr);

    // stream 1: node init, combo table, graph offsets
    node_init_kernel<<<N_NODES / 4, 256, 0, s1>>>(x, (const float4*)atom_emb,
                                                  (const float4*)vn_emb,
                                                  (float4*)hb0, (uint2*)phh,
                                                  (float4*)pvn, (float4*)out_hinit);
    combo_kernel<<<512, 256, 0, s1>>>(bond_emb);
    offsets_kernel<<<(NGRAPHS + 1 + 255) / 256, 256, 0, s1>>>(batch, poff);
    cudaEventRecord(evSide, s1);
    cudaStreamWaitEvent(0, evSide, 0);

    // ----- layer 0 -----
    aggregate_kernel<false><<<AGG_GRID, 256>>>((const uint2*)phh, nullptr, nullptr, (uint2*)paggh);
    gemm_fused<<<FUSED_GRID, 256, SM_TOTAL>>>(paggh, gcn_w, gcn_b, nullptr,
                                              norm_g, norm_b, nullptr, nullptr,
                                              hwr[0], ph2, ph2h, nullptr, N_NODES);
    cudaEventRecord(evH[0], 0);
    cudaStreamWaitEvent(s1, evH[0], 0);
    gemm_tf32<64, 4, 2><<<FFN_GRID, 256, 0, s1>>>(hwr[0], ffn_w, ffn_b, out, N_NODES, D, 64);
    cudaEventRecord(evF[0], s1);

    // ----- layers 1..2 (FFN on side stream) -----
    for (int l = 1; l < 3; l++) {
        int j = l - 1;
        vn_mlp_kernel<<<NGRAPHS / 8, 256>>>(ph2, poff,
                                            vn_w1 + (size_t)j * D * D, vn_b1 + (size_t)j * D,
                                            vn_g1 + (size_t)j * D,     vn_be1 + (size_t)j * D,
                                            vn_w2 + (size_t)j * D * D, vn_b2 + (size_t)j * D,
                                            vn_g2 + (size_t)j * D,     vn_be2 + (size_t)j * D,
                                            pvn);
        aggregate_kernel<true><<<AGG_GRID, 256>>>((const uint2*)ph2h, (const float4*)pvn,
                                                  batch, (uint2*)paggh);
        if (l == 2) cudaStreamWaitEvent(0, evF[0], 0);    // about to rewrite hb0
        gemm_fused<<<FUSED_GRID, 256, SM_TOTAL>>>(paggh, gcn_w + (size_t)l * D * D,
                                                  gcn_b + (size_t)l * D, hres[l],
                                                  norm_g + (size_t)l * D, norm_b + (size_t)l * D,
                                                  nullptr, nullptr,
                                                  hwr[l], ph2, ph2h, nullptr, N_NODES);
        cudaEventRecord(evH[l], 0);
        cudaStreamWaitEvent(s1, evH[l], 0);
        gemm_tf32<64, 4, 2><<<FFN_GRID, 256, 0, s1>>>(hwr[l], ffn_w + (size_t)l * D * 64,
                                                      ffn_b + (size_t)l * 64,
                                                      out + (size_t)l * 64, N_NODES, D, 64);
        cudaEventRecord(evF[l], s1);
    }

    // ----- layer 3 (FFN fused; nothing left to overlap) -----
    {
        int l = 3, j = 2;
        vn_mlp_kernel<<<NGRAPHS / 8, 256>>>(ph2, poff,
                                            vn_w1 + (size_t)j * D * D, vn_b1 + (size_t)j * D,
                                            vn_g1 + (size_t)j * D,     vn_be1 + (size_t)j * D,
                                            vn_w2 + (size_t)j * D * D, vn_b2 + (size_t)j * D,
                                            vn_g2 + (size_t)j * D,     vn_be2 + (size_t)j * D,
                                            pvn);
        aggregate_kernel<true><<<AGG_GRID, 256>>>((const uint2*)ph2h, (const float4*)pvn,
                                                  batch, (uint2*)paggh);
        cudaStreamWaitEvent(0, evF[1], 0);                // about to rewrite hb1
        gemm_fused<<<FUSED_GRID, 256, SM_TOTAL>>>(paggh, gcn_w + (size_t)l * D * D,
                                                  gcn_b + (size_t)l * D, hres[l],
                                                  nullptr, nullptr,
                                                  ffn_w + (size_t)l * D * 64,
                                                  ffn_b + (size_t)l * 64,
                                                  hwr[l], ph2, nullptr,
                                                  out + (size_t)l * 64, N_NODES);
    }

    // ---- join side stream before returning ----
    cudaStreamWaitEvent(0, evF[2], 0);
}

// round 16
// speedup vs baseline: 1.2242x; 1.0149x over previous
#include <cuda_runtime.h>
#include <cuda_fp16.h>
#include <stddef.h>
#include <stdint.h>

#define N_NODES 100000
#define N_EDGES 300000
#define NGRAPHS 3000
#define D 256
#define MSG_EPS 1e-7f
#define LN_EPS  1e-5f
#define SCAN_B 1024
#define NBLK ((N_NODES + SCAN_B - 1) / SCAN_B)   // 98

// ---------------- scratch (static device allocations; no cudaMalloc) ----------------
__device__ __align__(16) float g_h  [(size_t)N_NODES * D];
__device__ __align__(16) float g_hb [(size_t)N_NODES * D];   // second h buffer (ping-pong)
__device__ __align__(16) float g_h2 [(size_t)N_NODES * D];
__device__ __align__(16) __half g_hh  [(size_t)N_NODES * D]; // fp16 copy of h (layer-0 gather src)
__device__ __align__(16) __half g_h2h [(size_t)N_NODES * D]; // fp16 copy of h2 (gather src)
__device__ __align__(16) __half g_aggh[(size_t)N_NODES * D]; // fp16 agg (GEMM A operand)
__device__ __align__(16) float g_vn [(size_t)NGRAPHS * D];   // fp32 master (vn_mlp recurrence)
__device__ __align__(16) __half g_vnh[(size_t)NGRAPHS * D];  // fp16 gather copy
__device__ __align__(16) __half g_combo[512 * D];            // fp16 bond combo table (256 KB, L1-resident)
__device__ int g_off[NGRAPHS + 1];
__device__ int g_deg[N_NODES];
__device__ int g_noff[N_NODES + 1];
__device__ int g_cursor[N_NODES];
__device__ int g_elist[N_EDGES];
__device__ int g_bsum[NBLK];

__device__ __forceinline__ void cp_async16(uint32_t smem_dst, const void* gsrc) {
    asm volatile("cp.async.cg.shared.global [%0], [%1], 16;\n"
                 :: "r"(smem_dst), "l"(gsrc));
}
__device__ __forceinline__ void cp_commit() {
    asm volatile("cp.async.commit_group;\n" ::);
}
__device__ __forceinline__ void cp_wait0() {
    asm volatile("cp.async.wait_group 0;\n" ::: "memory");
}
__device__ __forceinline__ void cp_wait1() {
    asm volatile("cp.async.wait_group 1;\n" ::: "memory");
}
__device__ __forceinline__ float2 h2f2(unsigned u) {
    __half2 h = *reinterpret_cast<__half2*>(&u);
    return __half22float2(h);
}
__device__ __forceinline__ unsigned f22h2(float a, float b) {
    __half2 h = __floats2half2_rn(a, b);
    return *reinterpret_cast<unsigned*>(&h);
}

// ================= CSR build =================
__global__ void zero_deg_kernel() {
    int i = blockIdx.x * blockDim.x + threadIdx.x;
    if (i < N_NODES) g_deg[i] = 0;
}
__global__ void hist_kernel(const int* __restrict__ ei) {
    int e = blockIdx.x * blockDim.x + threadIdx.x;
    if (e < N_EDGES) atomicAdd(&g_deg[ei[N_EDGES + e]], 1);
}
__global__ void scan_block_kernel() {
    __shared__ int s[SCAN_B];
    int tid = threadIdx.x;
    int i = blockIdx.x * SCAN_B + tid;
    int v = (i < N_NODES) ? g_deg[i] : 0;
    s[tid] = v;
    __syncthreads();
#pragma unroll
    for (int d = 1; d < SCAN_B; d <<= 1) {
        int t = (tid >= d) ? s[tid - d] : 0;
        __syncthreads();
        s[tid] += t;
        __syncthreads();
    }
    if (i < N_NODES) g_noff[i + 1] = s[tid];
    if (tid == SCAN_B - 1) g_bsum[blockIdx.x] = s[tid];
}
__global__ void scan_sums_kernel() {
    __shared__ int s[128];
    int tid = threadIdx.x;
    int v = (tid < NBLK) ? g_bsum[tid] : 0;
    s[tid] = v;
    __syncthreads();
#pragma unroll
    for (int d = 1; d < 128; d <<= 1) {
        int t = (tid >= d) ? s[tid - d] : 0;
        __syncthreads();
        s[tid] += t;
        __syncthreads();
    }
    if (tid < NBLK) g_bsum[tid] = s[tid] - v;
    if (tid == 0) g_noff[0] = 0;
}
__global__ void add_off_kernel() {       // also seeds cursor
    int i = blockIdx.x * blockDim.x + threadIdx.x;
    if (i < N_NODES) {
        int v = g_noff[i + 1] + g_bsum[i / SCAN_B];
        g_noff[i + 1] = v;
        if (i + 1 < N_NODES) g_cursor[i + 1] = v;
        if (i == 0) g_cursor[0] = 0;
    }
}
__global__ void fill_kernel(const int* __restrict__ ei, const int* __restrict__ ea) {
    int e = blockIdx.x * blockDim.x + threadIdx.x;
    if (e >= N_EDGES) return;
    int src = ei[e];
    int dst = ei[N_EDGES + e];
    int combo = ea[3 * e + 0] | (ea[3 * e + 1] << 3) | (ea[3 * e + 2] << 6);
    int pos = atomicAdd(&g_cursor[dst], 1);
    g_elist[pos] = src | (combo << 17);
}
__global__ void combo_kernel(const float* __restrict__ bond) {
    int c = blockIdx.x;
    int d = threadIdx.x;
    int a0 = c & 7, a1 = (c >> 3) & 7, a2 = (c >> 6) & 7;
    float v = bond[(size_t)(0 * 8 + a0) * D + d]
            + bond[(size_t)(1 * 8 + a1) * D + d]
            + bond[(size_t)(2 * 8 + a2) * D + d];
    g_combo[c * D + d] = __float2half_rn(v);
}

// ---------------- node init (4 nodes/block, float4) ----------------
__global__ void node_init_kernel(const int* __restrict__ x,
                                 const float4* __restrict__ atom_emb,
                                 const float4* __restrict__ vn_emb,
                                 float4* __restrict__ h,
                                 uint2* __restrict__ hh,
                                 float4* __restrict__ vn,
                                 float4* __restrict__ out_hinit)
{
    int n = blockIdx.x * 4 + (threadIdx.x >> 6);
    if (n >= N_NODES) return;
    int q = threadIdx.x & 63;
    float4 s = make_float4(0.f, 0.f, 0.f, 0.f);
#pragma unroll
    for (int f = 0; f < 9; f++) {
        int xi = __ldg(&x[n * 9 + f]);
        float4 v = atom_emb[((size_t)f * 64 + xi) * 64 + q];
        s.x += v.x; s.y += v.y; s.z += v.z; s.w += v.w;
    }
    size_t idx = (size_t)n * 64 + q;
    out_hinit[idx] = s;
    float4 vv = vn_emb[q];
    float4 hv = make_float4(s.x + vv.x, s.y + vv.y, s.z + vv.z, s.w + vv.w);
    h[idx] = hv;
    uint2 hu;
    hu.x = f22h2(hv.x, hv.y);
    hu.y = f22h2(hv.z, hv.w);
    hh[idx] = hu;
    if (n < NGRAPHS) vn[(size_t)n * 64 + q] = vv;
}

// ---------------- graph segment offsets ----------------
__global__ void offsets_kernel(const int* __restrict__ batch, int* __restrict__ off)
{
    int g = blockIdx.x * blockDim.x + threadIdx.x;
    if (g > NGRAPHS) return;
    int lo = 0, hi = N_NODES;
    while (lo < hi) {
        int mid = (lo + hi) >> 1;
        if (batch[mid] < g) lo = mid + 1; else hi = mid;
    }
    off[g] = lo;
}

// ---------------- CSR gather aggregation (all-fp16 gathers, fp32 math) ----------------
template<bool WITHVN>
__global__ void aggregate_kernel(const uint2* __restrict__ hin,    // fp16, 4 halves/uint2
                                 const uint2* __restrict__ vnh,    // fp16 vn gather copy
                                 const int* __restrict__ batch,
                                 uint2* __restrict__ agg)          // fp16 out
{
    int n = blockIdx.x * 4 + (threadIdx.x >> 6);
    if (n >= N_NODES) return;
    int q = threadIdx.x & 63;
    const uint2* combo2 = reinterpret_cast<const uint2*>(g_combo);
    int i0 = g_noff[n], i1 = g_noff[n + 1];
    uint2 su = hin[(size_t)n * 64 + q];
    float2 s01 = h2f2(su.x), s23 = h2f2(su.y);
    float ax = s01.x, ay = s01.y, az = s23.x, aw = s23.y;
    if (WITHVN) {
        int bg = __ldg(&batch[n]);
        uint2 vu = vnh[(size_t)bg * 64 + q];
        float2 va = h2f2(vu.x), vb = h2f2(vu.y);
        ax += va.x; ay += va.y; az += vb.x; aw += vb.y;
    }
    int i = i0;
    for (; i + 1 < i1; i += 2) {
        int ed0 = __ldg(&g_elist[i]);
        int ed1 = __ldg(&g_elist[i + 1]);
        int s0 = ed0 & 0x1FFFF, c0 = ed0 >> 17;
        int s1 = ed1 & 0x1FFFF, c1 = ed1 >> 17;
        uint2 u0 = hin[(size_t)s0 * 64 + q];
        uint2 u1 = hin[(size_t)s1 * 64 + q];
        float2 v0a = h2f2(u0.x), v0b = h2f2(u0.y);
        float2 v1a = h2f2(u1.x), v1b = h2f2(u1.y);
        uint2 cu0 = combo2[(size_t)c0 * 64 + q];
        uint2 cu1 = combo2[(size_t)c1 * 64 + q];
        float2 b0a = h2f2(cu0.x), b0b = h2f2(cu0.y);
        float2 b1a = h2f2(cu1.x), b1b = h2f2(cu1.y);
        if (WITHVN) {
            int bg0 = __ldg(&batch[s0]);
            int bg1 = __ldg(&batch[s1]);
            uint2 w0 = vnh[(size_t)bg0 * 64 + q];
            uint2 w1 = vnh[(size_t)bg1 * 64 + q];
            float2 w0a = h2f2(w0.x), w0b = h2f2(w0.y);
            float2 w1a = h2f2(w1.x), w1b = h2f2(w1.y);
            v0a.x += w0a.x; v0a.y += w0a.y; v0b.x += w0b.x; v0b.y += w0b.y;
            v1a.x += w1a.x; v1a.y += w1a.y; v1b.x += w1b.x; v1b.y += w1b.y;
        }
        ax += fmaxf(v0a.x + b0a.x, 0.f) + MSG_EPS + fmaxf(v1a.x + b1a.x, 0.f) + MSG_EPS;
        ay += fmaxf(v0a.y + b0a.y, 0.f) + MSG_EPS + fmaxf(v1a.y + b1a.y, 0.f) + MSG_EPS;
        az += fmaxf(v0b.x + b0b.x, 0.f) + MSG_EPS + fmaxf(v1b.x + b1b.x, 0.f) + MSG_EPS;
        aw += fmaxf(v0b.y + b0b.y, 0.f) + MSG_EPS + fmaxf(v1b.y + b1b.y, 0.f) + MSG_EPS;
    }
    if (i < i1) {
        int ed = __ldg(&g_elist[i]);
        int s0 = ed & 0x1FFFF, c0 = ed >> 17;
        uint2 u0 = hin[(size_t)s0 * 64 + q];
        float2 va = h2f2(u0.x), vb = h2f2(u0.y);
        uint2 cu = combo2[(size_t)c0 * 64 + q];
        float2 ba = h2f2(cu.x), bb = h2f2(cu.y);
        if (WITHVN) {
            int bg0 = __ldg(&batch[s0]);
            uint2 w = vnh[(size_t)bg0 * 64 + q];
            float2 wa = h2f2(w.x), wb = h2f2(w.y);
            va.x += wa.x; va.y += wa.y; vb.x += wb.x; vb.y += wb.y;
        }
        ax += fmaxf(va.x + ba.x, 0.f) + MSG_EPS;
        ay += fmaxf(va.y + ba.y, 0.f) + MSG_EPS;
        az += fmaxf(vb.x + bb.x, 0.f) + MSG_EPS;
        aw += fmaxf(vb.y + bb.y, 0.f) + MSG_EPS;
    }
    uint2 ou;
    ou.x = f22h2(ax, ay);
    ou.y = f22h2(az, aw);
    agg[(size_t)n * 64 + q] = ou;
}

// ---------------- tf32 helpers ----------------
__device__ __forceinline__ float tf32r(float x) {
    uint32_t u;
    asm("cvt.rna.tf32.f32 %0, %1;" : "=r"(u) : "f"(x));
    return __uint_as_float(u);
}
__device__ __forceinline__ uint32_t tf32u(float x) {
    uint32_t u;
    asm("cvt.rna.tf32.f32 %0, %1;" : "=r"(u) : "f"(x));
    return u;
}
__device__ __forceinline__ void mma_tf32(float* c, const uint32_t* a, const uint32_t* b) {
    asm volatile("mma.sync.aligned.m16n8k8.row.col.f32.tf32.tf32.f32 "
                 "{%0,%1,%2,%3}, {%4,%5,%6,%7}, {%8,%9}, {%0,%1,%2,%3};\n"
                 : "+f"(c[0]), "+f"(c[1]), "+f"(c[2]), "+f"(c[3])
                 : "r"(a[0]), "r"(a[1]), "r"(a[2]), "r"(a[3]),
                   "r"(b[0]), "r"(b[1]));
}

// ==================== fused GCN GEMM + residual + LN/ReLU [+ FFN] ====================
// A operand is fp16 (agg); fp16->fp32 is exact and fits tf32 (11-bit significand).
// BM=64, BN=256; 3-stage cp.async B pipeline; FFN phase only for layer 3.
#define HT_STRIDE 260
#define SM_AS   0
#define SM_BS   9216
#define SM_WF   66560
#define SM_SSA  80384
#define SM_SSB  81664
#define SM_MU   82944
#define SM_RS   83200
#define SM_TOTAL 83456

__global__ __launch_bounds__(256)
void gemm_fused(const __half* __restrict__ A16,
                const float* __restrict__ W, const float* __restrict__ bias,
                const float* __restrict__ res,
                const float* __restrict__ gam, const float* __restrict__ bet,
                const float* __restrict__ ffnW, const float* __restrict__ ffnB,
                float* __restrict__ outh, float* __restrict__ outh2,
                __half* __restrict__ outh2h,
                float* __restrict__ outf, int M)
{
    constexpr int BM = 64, BN = 256, BK = 16, K = D;
    constexpr int NITER = K / BK;
    constexpr int MT = 2, NT = 8;
    extern __shared__ char smraw[];
    float* As = reinterpret_cast<float*>(smraw + SM_AS);   // [buf*16+k][72]
    float* Bs = reinterpret_cast<float*>(smraw + SM_BS);   // [buf*16+k][264], 3 bufs
    float* HT = reinterpret_cast<float*>(smraw);           // [64][HT_STRIDE]
    float* Wf = reinterpret_cast<float*>(smraw + SM_WF);   // [buf*16+k][72], 3 bufs
    float* ssA = reinterpret_cast<float*>(smraw + SM_SSA);
    float* ssB = reinterpret_cast<float*>(smraw + SM_SSB);
    float* smu = reinterpret_cast<float*>(smraw + SM_MU);
    float* srs = reinterpret_cast<float*>(smraw + SM_RS);
    const uint32_t smbase = (uint32_t)__cvta_generic_to_shared(smraw);

    const int tid  = threadIdx.x;
    const int lane = tid & 31;
    const int wid  = tid >> 5;
    const int wr   = wid >> 2;
    const int wc   = wid & 3;
    const int gid  = lane >> 2;
    const int tig  = lane & 3;
    const int m0   = blockIdx.x * BM;

    const int arow = tid & 63;
    const int akc  = (tid >> 6) << 2;
    const bool avalid = (m0 + arow) < M;
    const uint2* aptr = reinterpret_cast<const uint2*>(A16 + (size_t)(m0 + arow) * K + akc);

    const int bk  = tid >> 4;
    const int bnc = (tid & 15) << 4;
    const float* bptr = W + (size_t)bk * BN + bnc;

    // ---- prologue: B stages 0 and 1 in flight ----
    {
        uint32_t dst0 = smbase + SM_BS + (uint32_t)((bk * 264 + bnc) * 4);
#pragma unroll
        for (int j = 0; j < 4; j++)
            cp_async16(dst0 + j * 16, bptr + j * 4);
        cp_commit();
        uint32_t dst1 = smbase + SM_BS + (uint32_t)(((16 + bk) * 264 + bnc) * 4);
        const float* bp1 = bptr + (size_t)BK * BN;
#pragma unroll
        for (int j = 0; j < 4; j++)
            cp_async16(dst1 + j * 16, bp1 + j * 4);
        cp_commit();
    }
    {
        uint2 au = make_uint2(0u, 0u);
        if (avalid) au = aptr[0];
        float2 a01 = h2f2(au.x), a23 = h2f2(au.y);
        As[(akc + 0) * 72 + arow] = a01.x;
        As[(akc + 1) * 72 + arow] = a01.y;
        As[(akc + 2) * 72 + arow] = a23.x;
        As[(akc + 3) * 72 + arow] = a23.y;
    }
    cp_wait1();
    __syncthreads();

    float acc[MT][NT][4];
#pragma unroll
    for (int i = 0; i < MT; i++)
#pragma unroll
        for (int j = 0; j < NT; j++)
#pragma unroll
            for (int q = 0; q < 4; q++) acc[i][j][q] = 0.f;

    for (int k0 = 0; k0 < NITER; k0++) {
        const int acur = k0 & 1;
        const int bcur = k0 % 3;
        uint2 au = make_uint2(0u, 0u);
        if (k0 + 2 < NITER) {
            const int bnx = (k0 + 2) % 3;
            uint32_t dst = smbase + SM_BS + (uint32_t)(((bnx * 16 + bk) * 264 + bnc) * 4);
            const float* bp = bptr + (size_t)(k0 + 2) * BK * BN;
#pragma unroll
            for (int j = 0; j < 4; j++)
                cp_async16(dst + j * 16, bp + j * 4);
            cp_commit();
        }
        if (k0 + 1 < NITER) {
            if (avalid) au = aptr[(k0 + 1) * (BK / 4)];
        }
#pragma unroll
        for (int ks = 0; ks < 2; ks++) {
            uint32_t af[MT][4];
            uint32_t bf[NT][2];
#pragma unroll
            for (int mt = 0; mt < MT; mt++) {
                int r = wr * 32 + mt * 16 + gid;
                af[mt][0] = __float_as_uint(As[(acur * 16 + ks * 8 + tig) * 72 + r]);
                af[mt][1] = __float_as_uint(As[(acur * 16 + ks * 8 + tig) * 72 + r + 8]);
                af[mt][2] = __float_as_uint(As[(acur * 16 + ks * 8 + tig + 4) * 72 + r]);
                af[mt][3] = __float_as_uint(As[(acur * 16 + ks * 8 + tig + 4) * 72 + r + 8]);
            }
#pragma unroll
            for (int nt = 0; nt < NT; nt++) {
                int c = wc * 64 + nt * 8 + gid;
                bf[nt][0] = tf32u(Bs[(bcur * 16 + ks * 8 + tig) * 264 + c]);
                bf[nt][1] = tf32u(Bs[(bcur * 16 + ks * 8 + tig + 4) * 264 + c]);
            }
#pragma unroll
            for (int mt = 0; mt < MT; mt++)
#pragma unroll
                for (int nt = 0; nt < NT; nt++)
                    mma_tf32(acc[mt][nt], af[mt], bf[nt]);
        }
        if (k0 + 1 < NITER) {
            const int anx = acur ^ 1;
            float2 a01 = h2f2(au.x), a23 = h2f2(au.y);
            As[(anx * 16 + akc + 0) * 72 + arow] = a01.x;
            As[(anx * 16 + akc + 1) * 72 + arow] = a01.y;
            As[(anx * 16 + akc + 2) * 72 + arow] = a23.x;
            As[(anx * 16 + akc + 3) * 72 + arow] = a23.y;
            if (k0 + 2 < NITER) cp_wait1(); else cp_wait0();
            __syncthreads();
        }
    }

    if (ffnW) {   // prefetch FFN W chunks 0 and 1
        int kr = tid >> 4;
        int wcol = (tid & 15) << 2;
        uint32_t dst0 = smbase + SM_WF + (uint32_t)((kr * 72 + wcol) * 4);
        cp_async16(dst0, ffnW + (size_t)kr * 64 + wcol);
        cp_commit();
        uint32_t dst1 = smbase + SM_WF + (uint32_t)(((16 + kr) * 72 + wcol) * 4);
        cp_async16(dst1, ffnW + (size_t)(16 + kr) * 64 + wcol);
        cp_commit();
    }

    // ---- epilogue: v = acc + bias (+res); write h ----
#pragma unroll
    for (int mt = 0; mt < MT; mt++) {
        int r  = m0 + wr * 32 + mt * 16 + gid;
        int r2 = r + 8;
#pragma unroll
        for (int nt = 0; nt < NT; nt++) {
            int c = wc * 64 + nt * 8 + 2 * tig;
            float2 bi = *reinterpret_cast<const float2*>(&bias[c]);
            float v0 = acc[mt][nt][0] + bi.x;
            float v1 = acc[mt][nt][1] + bi.y;
            float v2 = acc[mt][nt][2] + bi.x;
            float v3 = acc[mt][nt][3] + bi.y;
            if (res) {
                if (r < M) {
                    float2 rr = *reinterpret_cast<const float2*>(&res[(size_t)r * D + c]);
                    v0 += rr.x; v1 += rr.y;
                }
                if (r2 < M) {
                    float2 rr = *reinterpret_cast<const float2*>(&res[(size_t)r2 * D + c]);
                    v2 += rr.x; v3 += rr.y;
                }
            }
            acc[mt][nt][0] = v0; acc[mt][nt][1] = v1;
            acc[mt][nt][2] = v2; acc[mt][nt][3] = v3;
            if (r < M)
                *reinterpret_cast<float2*>(&outh[(size_t)r * D + c]) = make_float2(v0, v1);
            if (r2 < M)
                *reinterpret_cast<float2*>(&outh[(size_t)r2 * D + c]) = make_float2(v2, v3);
        }
    }

    if (ffnW) {   // mainloop smem reads done -> h_tile
        __syncthreads();
#pragma unroll
        for (int mt = 0; mt < MT; mt++) {
            int lr  = wr * 32 + mt * 16 + gid;
            int lr2 = lr + 8;
#pragma unroll
            for (int nt = 0; nt < NT; nt++) {
                int c = wc * 64 + nt * 8 + 2 * tig;
                HT[lr  * HT_STRIDE + c    ] = tf32r(acc[mt][nt][0]);
                HT[lr  * HT_STRIDE + c + 1] = tf32r(acc[mt][nt][1]);
                HT[lr2 * HT_STRIDE + c    ] = tf32r(acc[mt][nt][2]);
                HT[lr2 * HT_STRIDE + c + 1] = tf32r(acc[mt][nt][3]);
            }
        }
    }

    // ---- LayerNorm + ReLU -> outh2 (fp32) + outh2h (fp16) ----
    if (gam) {
#pragma unroll
        for (int mt = 0; mt < MT; mt++) {
#pragma unroll
            for (int hh = 0; hh < 2; hh++) {
                float s = 0.f, q = 0.f;
#pragma unroll
                for (int nt = 0; nt < NT; nt++) {
                    float u0 = acc[mt][nt][2 * hh];
                    float u1 = acc[mt][nt][2 * hh + 1];
                    s += u0 + u1;
                    q += u0 * u0 + u1 * u1;
                }
                s += __shfl_xor_sync(0xffffffffu, s, 1);
                q += __shfl_xor_sync(0xffffffffu, q, 1);
                s += __shfl_xor_sync(0xffffffffu, s, 2);
                q += __shfl_xor_sync(0xffffffffu, q, 2);
                if (tig == 0) {
                    int lr = wr * 32 + mt * 16 + hh * 8 + gid;
                    ssA[lr * 5 + wc] = s;
                    ssB[lr * 5 + wc] = q;
                }
            }
        }
        __syncthreads();
        if (tid < BM) {
            float s = ssA[tid * 5 + 0] + ssA[tid * 5 + 1] + ssA[tid * 5 + 2] + ssA[tid * 5 + 3];
            float q = ssB[tid * 5 + 0] + ssB[tid * 5 + 1] + ssB[tid * 5 + 2] + ssB[tid * 5 + 3];
            float mu  = s * (1.f / D);
            float var = q * (1.f / D) - mu * mu;
            smu[tid] = mu;
            srs[tid] = rsqrtf(var + LN_EPS);
        }
        __syncthreads();
#pragma unroll
        for (int mt = 0; mt < MT; mt++) {
            int lr  = wr * 32 + mt * 16 + gid;
            int lr2 = lr + 8;
            int r   = m0 + lr;
            int r2  = m0 + lr2;
            float mu0 = smu[lr],  rs0 = srs[lr];
            float mu1 = smu[lr2], rs1 = srs[lr2];
#pragma unroll
            for (int nt = 0; nt < NT; nt++) {
                int c = wc * 64 + nt * 8 + 2 * tig;
                float2 gg = *reinterpret_cast<const float2*>(&gam[c]);
                float2 bb = *reinterpret_cast<const float2*>(&bet[c]);
                if (r < M) {
                    float y0 = fmaxf((acc[mt][nt][0] - mu0) * rs0 * gg.x + bb.x, 0.f);
                    float y1 = fmaxf((acc[mt][nt][1] - mu0) * rs0 * gg.y + bb.y, 0.f);
                    *reinterpret_cast<float2*>(&outh2[(size_t)r * D + c]) = make_float2(y0, y1);
                    *reinterpret_cast<unsigned*>(&outh2h[(size_t)r * D + c]) = f22h2(y0, y1);
                }
                if (r2 < M) {
                    float y2 = fmaxf((acc[mt][nt][2] - mu1) * rs1 * gg.x + bb.x, 0.f);
                    float y3 = fmaxf((acc[mt][nt][3] - mu1) * rs1 * gg.y + bb.y, 0.f);
                    *reinterpret_cast<float2*>(&outh2[(size_t)r2 * D + c]) = make_float2(y2, y3);
                    *reinterpret_cast<unsigned*>(&outh2h[(size_t)r2 * D + c]) = f22h2(y2, y3);
                }
            }
        }
    }

    if (!ffnW) return;

    // ---- FFN phase: outf = h_tile @ ffnW + ffnB, 64x64x256, 3-stage Wf ----
    const int wrf = wid >> 1;
    const int wcf = wid & 1;
    const int fkr = tid >> 4;
    const int fwc = (tid & 15) << 2;
    cp_wait1();
    __syncthreads();

    float fac[4][4];
#pragma unroll
    for (int i = 0; i < 4; i++)
#pragma unroll
        for (int j = 0; j < 4; j++) fac[i][j] = 0.f;

    constexpr int FCH = 16;
    for (int ch = 0; ch < FCH; ch++) {
        const int cur = ch % 3;
        if (ch + 2 < FCH) {
            const int nx = (ch + 2) % 3;
            uint32_t dst = smbase + SM_WF + (uint32_t)(((nx * 16 + fkr) * 72 + fwc) * 4);
            cp_async16(dst, ffnW + (size_t)((ch + 2) * 16 + fkr) * 64 + fwc);
            cp_commit();
        }
#pragma unroll
        for (int ks = 0; ks < 2; ks++) {
            int kb = ch * 16 + ks * 8;
            uint32_t af[4];
            {
                int r = wrf * 16 + gid;
                af[0] = __float_as_uint(HT[r * HT_STRIDE + kb + tig]);
                af[1] = __float_as_uint(HT[(r + 8) * HT_STRIDE + kb + tig]);
                af[2] = __float_as_uint(HT[r * HT_STRIDE + kb + tig + 4]);
                af[3] = __float_as_uint(HT[(r + 8) * HT_STRIDE + kb + tig + 4]);
            }
#pragma unroll
            for (int nt = 0; nt < 4; nt++) {
                int c = wcf * 32 + nt * 8 + gid;
                uint32_t bf[2];
                bf[0] = tf32u(Wf[(cur * 16 + ks * 8 + tig) * 72 + c]);
                bf[1] = tf32u(Wf[(cur * 16 + ks * 8 + tig + 4) * 72 + c]);
                mma_tf32(fac[nt], af, bf);
            }
        }
        if (ch + 1 < FCH) {
            if (ch + 2 < FCH) cp_wait1(); else cp_wait0();
            __syncthreads();
        }
    }

    {
        int r  = m0 + wrf * 16 + gid;
        int r2 = r + 8;
#pragma unroll
        for (int nt = 0; nt < 4; nt++) {
            int c = wcf * 32 + nt * 8 + 2 * tig;
            float2 bi = *reinterpret_cast<const float2*>(&ffnB[c]);
            if (r < M)
                *reinterpret_cast<float2*>(&outf[(size_t)r * 256 + c]) =
                    make_float2(fac[nt][0] + bi.x, fac[nt][1] + bi.y);
            if (r2 < M)
                *reinterpret_cast<float2*>(&outf[(size_t)r2 * 256 + c]) =
                    make_float2(fac[nt][2] + bi.x, fac[nt][3] + bi.y);
        }
    }
}

// ---------------- standalone tf32 FFN GEMM (runs on side stream; fp32 A = h) ----------------
template<int BN, int WR, int WC>
__global__ __launch_bounds__(256)
void gemm_tf32(const float* __restrict__ A,
               const float* __restrict__ W, const float* __restrict__ bias,
               float* __restrict__ out,
               int M, int ldout, int ldw)
{
    constexpr int BM = 128, BK = 16, K = D;
    constexpr int NITER = K / BK;
    constexpr int TM = BM / WR;
    constexpr int TN = BN / WC;
    constexpr int MT = TM / 16;
    constexpr int NT = TN / 8;
    constexpr int PAD = 8;
    __shared__ float As[2][BK][BM + PAD];
    __shared__ float Bs[2][BK][BN + PAD];

    const int tid  = threadIdx.x;
    const int lane = tid & 31;
    const int wid  = tid >> 5;
    const int wr   = wid / WC;
    const int wc   = wid % WC;
    const int gid  = lane >> 2;
    const int tig  = lane & 3;
    const int m0   = blockIdx.x * BM;

    const int arow = tid & 127;
    const int akc  = (tid >> 7) << 3;
    const bool avalid = (m0 + arow) < M;
    const float* aptr = A + (size_t)(m0 + arow) * K + akc;

    constexpr int BVEC = (BN == 128) ? 2 : 1;
    const int bk  = tid >> 4;
    const int bnc = (tid & 15) * (BVEC * 4);
    const float* bptr = W + (size_t)bk * ldw + bnc;

    float4 a_st[2];
    float4 b_st[BVEC];

    a_st[0] = make_float4(0.f, 0.f, 0.f, 0.f);
    a_st[1] = a_st[0];
    if (avalid) {
        a_st[0] = *reinterpret_cast<const float4*>(aptr);
        a_st[1] = *reinterpret_cast<const float4*>(aptr + 4);
    }
#pragma unroll
    for (int i = 0; i < BVEC; i++)
        b_st[i] = *reinterpret_cast<const float4*>(bptr + i * 4);

    {
        const float* av = reinterpret_cast<const float*>(a_st);
#pragma unroll
        for (int j = 0; j < 8; j++) As[0][akc + j][arow] = tf32r(av[j]);
        const float* bv = reinterpret_cast<const float*>(b_st);
#pragma unroll
        for (int j = 0; j < BVEC * 4; j++) Bs[0][bk][bnc + j] = tf32r(bv[j]);
    }
    __syncthreads();

    float acc[MT][NT][4];
#pragma unroll
    for (int i = 0; i < MT; i++)
#pragma unroll
        for (int j = 0; j < NT; j++)
#pragma unroll
            for (int q = 0; q < 4; q++) acc[i][j][q] = 0.f;

    for (int k0 = 0; k0 < NITER; k0++) {
        const int cur = k0 & 1;
        if (k0 + 1 < NITER) {
            a_st[0] = make_float4(0.f, 0.f, 0.f, 0.f);
            a_st[1] = a_st[0];
            if (avalid) {
                a_st[0] = *reinterpret_cast<const float4*>(aptr + (k0 + 1) * BK);
                a_st[1] = *reinterpret_cast<const float4*>(aptr + (k0 + 1) * BK + 4);
            }
#pragma unroll
            for (int i = 0; i < BVEC; i++)
                b_st[i] = *reinterpret_cast<const float4*>(bptr + (size_t)(k0 + 1) * BK * ldw + i * 4);
        }
#pragma unroll
        for (int ks = 0; ks < 2; ks++) {
            uint32_t af[MT][4];
            uint32_t bf[NT][2];
#pragma unroll
            for (int mt = 0; mt < MT; mt++) {
                int r = wr * TM + mt * 16 + gid;
                af[mt][0] = __float_as_uint(As[cur][ks * 8 + tig    ][r]);
                af[mt][1] = __float_as_uint(As[cur][ks * 8 + tig    ][r + 8]);
                af[mt][2] = __float_as_uint(As[cur][ks * 8 + tig + 4][r]);
                af[mt][3] = __float_as_uint(As[cur][ks * 8 + tig + 4][r + 8]);
            }
#pragma unroll
            for (int nt = 0; nt < NT; nt++) {
                int c = wc * TN + nt * 8 + gid;
                bf[nt][0] = __float_as_uint(Bs[cur][ks * 8 + tig    ][c]);
                bf[nt][1] = __float_as_uint(Bs[cur][ks * 8 + tig + 4][c]);
            }
#pragma unroll
            for (int mt = 0; mt < MT; mt++)
#pragma unroll
                for (int nt = 0; nt < NT; nt++)
                    mma_tf32(acc[mt][nt], af[mt], bf[nt]);
        }
        if (k0 + 1 < NITER) {
            const int nxt = cur ^ 1;
            const float* av = reinterpret_cast<const float*>(a_st);
#pragma unroll
            for (int j = 0; j < 8; j++) As[nxt][akc + j][arow] = tf32r(av[j]);
            const float* bv = reinterpret_cast<const float*>(b_st);
#pragma unroll
            for (int j = 0; j < BVEC * 4; j++) Bs[nxt][bk][bnc + j] = tf32r(bv[j]);
            __syncthreads();
        }
    }

#pragma unroll
    for (int mt = 0; mt < MT; mt++) {
#pragma unroll
        for (int nt = 0; nt < NT; nt++) {
            int r = m0 + wr * TM + mt * 16 + gid;
            int c = wc * TN + nt * 8 + 2 * tig;
            float2 bi = *reinterpret_cast<const float2*>(&bias[c]);
            if (r < M)
                *reinterpret_cast<float2*>(&out[(size_t)r * ldout + c]) =
                    make_float2(acc[mt][nt][0] + bi.x, acc[mt][nt][1] + bi.y);
            int r2 = r + 8;
            if (r2 < M)
                *reinterpret_cast<float2*>(&out[(size_t)r2 * ldout + c]) =
                    make_float2(acc[mt][nt][2] + bi.x, acc[mt][nt][3] + bi.y);
        }
    }
}

// ---------------- virtual-node path (fp32 h2; writes fp32 vn + fp16 vnh) ----------------
__device__ __forceinline__ void ln_rows8(float (*t)[D], float (*s)[D],
                                         const float* __restrict__ gam,
                                         const float* __restrict__ bet,
                                         float* smu, float* srs)
{
    int lane = threadIdx.x & 31, w = threadIdx.x >> 5;
    float a = 0.f, b = 0.f;
#pragma unroll
    for (int i = 0; i < 8; i++) {
        float v = t[w][lane + 32 * i];
        a += v; b += v * v;
    }
#pragma unroll
    for (int o = 16; o; o >>= 1) {
        a += __shfl_down_sync(0xffffffffu, a, o);
        b += __shfl_down_sync(0xffffffffu, b, o);
    }
    if (lane == 0) {
        float mu = a * (1.f / D);
        float var = b * (1.f / D) - mu * mu;
        smu[w] = mu;
        srs[w] = rsqrtf(var + LN_EPS);
    }
    __syncthreads();
    int d = threadIdx.x;
    float gd = gam[d], bd = bet[d];
#pragma unroll
    for (int gg = 0; gg < 8; gg++) {
        float v = (t[gg][d] - smu[gg]) * srs[gg] * gd + bd;
        s[gg][d] = fmaxf(v, 0.f);
    }
}

__global__ void vn_mlp_kernel(const float* __restrict__ h2, const int* __restrict__ off,
                              const float* __restrict__ W1, const float* __restrict__ b1,
                              const float* __restrict__ g1, const float* __restrict__ be1,
                              const float* __restrict__ W2, const float* __restrict__ b2,
                              const float* __restrict__ g2, const float* __restrict__ be2,
                              float* __restrict__ vn, __half* __restrict__ vnh)
{
    __shared__ float s[8][D];
    __shared__ float t[8][D];
    __shared__ float smu[8], srs[8];
    int d = threadIdx.x;
    int g0 = blockIdx.x * 8;

#pragma unroll
    for (int gg = 0; gg < 8; gg++) {
        int g = g0 + gg;
        float acc = vn[(size_t)g * D + d];
        int n1 = off[g + 1];
        for (int n = off[g]; n < n1; n++)
            acc += h2[(size_t)n * D + d];
        s[gg][d] = acc;
    }
    __syncthreads();

    float y[8];
#pragma unroll
    for (int gg = 0; gg < 8; gg++) y[gg] = b1[d];
    for (int k = 0; k < D; k++) {
        float w = W1[(size_t)k * D + d];
#pragma unroll
        for (int gg = 0; gg < 8; gg++) y[gg] = fmaf(s[gg][k], w, y[gg]);
    }
    __syncthreads();
#pragma unroll
    for (int gg = 0; gg < 8; gg++) t[gg][d] = y[gg];
    __syncthreads();
    ln_rows8(t, s, g1, be1, smu, srs);
    __syncthreads();

#pragma unroll
    for (int gg = 0; gg < 8; gg++) y[gg] = b2[d];
    for (int k = 0; k < D; k++) {
        float w = W2[(size_t)k * D + d];
#pragma unroll
        for (int gg = 0; gg < 8; gg++) y[gg] = fmaf(s[gg][k], w, y[gg]);
    }
    __syncthreads();
#pragma unroll
    for (int gg = 0; gg < 8; gg++) t[gg][d] = y[gg];
    __syncthreads();
    ln_rows8(t, s, g2, be2, smu, srs);
    __syncthreads();
#pragma unroll
    for (int gg = 0; gg < 8; gg++) {
        int g = g0 + gg;
        float v = s[gg][d];
        vn[(size_t)g * D + d] = v;
        vnh[(size_t)g * D + d] = __float2half_rn(v);
    }
}

// ---------------- launcher ----------------
extern "C" void kernel_launch(void* const* d_in, const int* in_sizes, int n_in,
                              void* d_out, int out_size)
{
    const int*   x          = (const int*)  d_in[0];
    const int*   edge_attr  = (const int*)  d_in[1];
    const int*   edge_index = (const int*)  d_in[2];
    const int*   batch      = (const int*)  d_in[3];
    const float* atom_emb   = (const float*)d_in[4];
    const float* bond_emb   = (const float*)d_in[5];
    const float* vn_emb     = (const float*)d_in[6];
    const float* gcn_w      = (const float*)d_in[7];
    const float* gcn_b      = (const float*)d_in[8];
    const float* norm_g     = (const float*)d_in[9];
    const float* norm_b     = (const float*)d_in[10];
    const float* ffn_w      = (const float*)d_in[11];
    const float* ffn_b      = (const float*)d_in[12];
    const float* vn_w1      = (const float*)d_in[13];
    const float* vn_b1      = (const float*)d_in[14];
    const float* vn_g1      = (const float*)d_in[15];
    const float* vn_be1     = (const float*)d_in[16];
    const float* vn_w2      = (const float*)d_in[17];
    const float* vn_b2      = (const float*)d_in[18];
    const float* vn_g2      = (const float*)d_in[19];
    const float* vn_be2     = (const float*)d_in[20];

    float* out       = (float*)d_out;                       // h_graph [N,256]
    float* out_hinit = out + (size_t)N_NODES * D;           // h_init  [N,256]

    float *hb0, *hb1, *ph2, *pvn; int* poff;
    __half *phh, *ph2h, *paggh, *pvnh;
    cudaGetSymbolAddress((void**)&hb0,  g_h);
    cudaGetSymbolAddress((void**)&hb1,  g_hb);
    cudaGetSymbolAddress((void**)&ph2,  g_h2);
    cudaGetSymbolAddress((void**)&phh,  g_hh);
    cudaGetSymbolAddress((void**)&ph2h, g_h2h);
    cudaGetSymbolAddress((void**)&paggh, g_aggh);
    cudaGetSymbolAddress((void**)&pvn,  g_vn);
    cudaGetSymbolAddress((void**)&pvnh, g_vnh);
    cudaGetSymbolAddress((void**)&poff, g_off);

    static cudaStream_t s1 = nullptr;
    static cudaEvent_t evFork, evSide, evH[3], evF[3];
    if (!s1) {
        cudaStreamCreateWithFlags(&s1, cudaStreamNonBlocking);
        cudaEventCreateWithFlags(&evFork, cudaEventDisableTiming);
        cudaEventCreateWithFlags(&evSide, cudaEventDisableTiming);
        for (int i = 0; i < 3; i++) {
            cudaEventCreateWithFlags(&evH[i], cudaEventDisableTiming);
            cudaEventCreateWithFlags(&evF[i], cudaEventDisableTiming);
        }
        cudaFuncSetAttribute(gemm_fused, cudaFuncAttributeMaxDynamicSharedMemorySize, SM_TOTAL);
    }

    const int FUSED_GRID = (N_NODES + 63) / 64;    // 1563
    const int FFN_GRID   = (N_NODES + 127) / 128;  // 782
    const int AGG_GRID   = (N_NODES + 3) / 4;

    float* hwr[4]  = {hb0, hb1, hb0, hb1};
    float* hres[4] = {nullptr, hb0, hb1, hb0};

    // ---- fork: prologue on two streams ----
    cudaEventRecord(evFork, 0);
    cudaStreamWaitEvent(s1, evFork, 0);

    // stream 0: CSR build chain
    zero_deg_kernel<<<(N_NODES + 255) / 256, 256>>>();
    hist_kernel<<<(N_EDGES + 255) / 256, 256>>>(edge_index);
    scan_block_kernel<<<NBLK, SCAN_B>>>();
    scan_sums_kernel<<<1, 128>>>();
    add_off_kernel<<<(N_NODES + 255) / 256, 256>>>();
    fill_kernel<<<(N_EDGES + 255) / 256, 256>>>(edge_index, edge_attr);

    // stream 1: node init, combo table, graph offsets
    node_init_kernel<<<N_NODES / 4, 256, 0, s1>>>(x, (const float4*)atom_emb,
                                                  (const float4*)vn_emb,
                                                  (float4*)hb0, (uint2*)phh,
                                                  (float4*)pvn, (float4*)out_hinit);
    combo_kernel<<<512, 256, 0, s1>>>(bond_emb);
    offsets_kernel<<<(NGRAPHS + 1 + 255) / 256, 256, 0, s1>>>(batch, poff);
    cudaEventRecord(evSide, s1);
    cudaStreamWaitEvent(0, evSide, 0);

    // ----- layer 0 -----
    aggregate_kernel<false><<<AGG_GRID, 256>>>((const uint2*)phh, nullptr, nullptr, (uint2*)paggh);
    gemm_fused<<<FUSED_GRID, 256, SM_TOTAL>>>(paggh, gcn_w, gcn_b, nullptr,
                                              norm_g, norm_b, nullptr, nullptr,
                                              hwr[0], ph2, ph2h, nullptr, N_NODES);
    cudaEventRecord(evH[0], 0);
    cudaStreamWaitEvent(s1, evH[0], 0);
    gemm_tf32<64, 4, 2><<<FFN_GRID, 256, 0, s1>>>(hwr[0], ffn_w, ffn_b, out, N_NODES, D, 64);
    cudaEventRecord(evF[0], s1);

    // ----- layers 1..2 (FFN on side stream) -----
    for (int l = 1; l < 3; l++) {
        int j = l - 1;
        vn_mlp_kernel<<<NGRAPHS / 8, 256>>>(ph2, poff,
                                            vn_w1 + (size_t)j * D * D, vn_b1 + (size_t)j * D,
                                            vn_g1 + (size_t)j * D,     vn_be1 + (size_t)j * D,
                                            vn_w2 + (size_t)j * D * D, vn_b2 + (size_t)j * D,
                                            vn_g2 + (size_t)j * D,     vn_be2 + (size_t)j * D,
                                            pvn, pvnh);
        aggregate_kernel<true><<<AGG_GRID, 256>>>((const uint2*)ph2h, (const uint2*)pvnh,
                                                  batch, (uint2*)paggh);
        if (l == 2) cudaStreamWaitEvent(0, evF[0], 0);    // about to rewrite hb0
        gemm_fused<<<FUSED_GRID, 256, SM_TOTAL>>>(paggh, gcn_w + (size_t)l * D * D,
                                                  gcn_b + (size_t)l * D, hres[l],
                                                  norm_g + (size_t)l * D, norm_b + (size_t)l * D,
                                                  nullptr, nullptr,
                                                  hwr[l], ph2, ph2h, nullptr, N_NODES);
        cudaEventRecord(evH[l], 0);
        cudaStreamWaitEvent(s1, evH[l], 0);
        gemm_tf32<64, 4, 2><<<FFN_GRID, 256, 0, s1>>>(hwr[l], ffn_w + (size_t)l * D * 64,
                                                      ffn_b + (size_t)l * 64,
                                                      out + (size_t)l * 64, N_NODES, D, 64);
        cudaEventRecord(evF[l], s1);
    }

    // ----- layer 3 (FFN fused; nothing left to overlap) -----
    {
        int l = 3, j = 2;
        vn_mlp_kernel<<<NGRAPHS / 8, 256>>>(ph2, poff,
                                            vn_w1 + (size_t)j * D * D, vn_b1 + (size_t)j * D,
                                            vn_g1 + (size_t)j * D,     vn_be1 + (size_t)j * D,
                                            vn_w2 + (size_t)j * D * D, vn_b2 + (size_t)j * D,
                                            vn_g2 + (size_t)j * D,     vn_be2 + (size_t)j * D,
                                            pvn, pvnh);
        aggregate_kernel<true><<<AGG_GRID, 256>>>((const uint2*)ph2h, (const uint2*)pvnh,
                                                  batch, (uint2*)paggh);
        cudaStreamWaitEvent(0, evF[1], 0);                // about to rewrite hb1
        gemm_fused<<<FUSED_GRID, 256, SM_TOTAL>>>(paggh, gcn_w + (size_t)l * D * D,
                                                  gcn_b + (size_t)l * D, hres[l],
                                                  nullptr, nullptr,
                                                  ffn_w + (size_t)l * D * 64,
                                                  ffn_b + (size_t)l * 64,
                                                  hwr[l], ph2, nullptr,
                                                  out + (size_t)l * 64, N_NODES);
    }

    // ---- join side stream before returning ----
    cudaStreamWaitEvent(0, evF[2], 0);
}

// round 17
// speedup vs baseline: 1.2769x; 1.0430x over previous
#include <cuda_runtime.h>
#include <cuda_fp16.h>
#include <stddef.h>
#include <stdint.h>

#define N_NODES 100000
#define N_EDGES 300000
#define NGRAPHS 3000
#define D 256
#define MSG_EPS 1e-7f
#define LN_EPS  1e-5f
#define SCAN_B 1024
#define NBLK ((N_NODES + SCAN_B - 1) / SCAN_B)   // 98

// ---------------- scratch (static device allocations; no cudaMalloc) ----------------
__device__ __align__(16) float g_h  [(size_t)N_NODES * D];
__device__ __align__(16) float g_hb [(size_t)N_NODES * D];   // second h buffer (ping-pong)
__device__ __align__(16) __half g_hh  [(size_t)N_NODES * D]; // fp16 copy of h (layer-0 gather src)
__device__ __align__(16) __half g_h2h [(size_t)N_NODES * D]; // fp16 h2 (gather + vn_mlp src)
__device__ __align__(16) __half g_aggh[(size_t)N_NODES * D]; // fp16 agg (GEMM A operand)
__device__ __align__(16) float g_vn [(size_t)NGRAPHS * D];   // fp32 master (vn_mlp recurrence)
__device__ __align__(16) __half g_vnh[(size_t)NGRAPHS * D];  // fp16 gather copy
__device__ __align__(16) __half g_combo[512 * D];            // fp16 bond combo table (256 KB)
__device__ int g_off[NGRAPHS + 1];
__device__ int g_deg[N_NODES];
__device__ int g_noff[N_NODES + 1];
__device__ int g_cursor[N_NODES];
__device__ int g_elist[N_EDGES];
__device__ int g_bsum[NBLK];

__device__ __forceinline__ void cp_async16(uint32_t smem_dst, const void* gsrc) {
    asm volatile("cp.async.cg.shared.global [%0], [%1], 16;\n"
                 :: "r"(smem_dst), "l"(gsrc));
}
__device__ __forceinline__ void cp_commit() {
    asm volatile("cp.async.commit_group;\n" ::);
}
__device__ __forceinline__ void cp_wait0() {
    asm volatile("cp.async.wait_group 0;\n" ::: "memory");
}
__device__ __forceinline__ void cp_wait1() {
    asm volatile("cp.async.wait_group 1;\n" ::: "memory");
}
__device__ __forceinline__ float2 h2f2(unsigned u) {
    __half2 h = *reinterpret_cast<__half2*>(&u);
    return __half22float2(h);
}
__device__ __forceinline__ unsigned f22h2(float a, float b) {
    __half2 h = __floats2half2_rn(a, b);
    return *reinterpret_cast<unsigned*>(&h);
}

// ================= CSR build =================
__global__ void zero_deg_kernel() {
    int i = blockIdx.x * blockDim.x + threadIdx.x;
    if (i < N_NODES) g_deg[i] = 0;
}
__global__ void hist_kernel(const int* __restrict__ ei) {
    int e = blockIdx.x * blockDim.x + threadIdx.x;
    if (e < N_EDGES) atomicAdd(&g_deg[ei[N_EDGES + e]], 1);
}
__global__ void scan_block_kernel() {
    __shared__ int s[SCAN_B];
    int tid = threadIdx.x;
    int i = blockIdx.x * SCAN_B + tid;
    int v = (i < N_NODES) ? g_deg[i] : 0;
    s[tid] = v;
    __syncthreads();
#pragma unroll
    for (int d = 1; d < SCAN_B; d <<= 1) {
        int t = (tid >= d) ? s[tid - d] : 0;
        __syncthreads();
        s[tid] += t;
        __syncthreads();
    }
    if (i < N_NODES) g_noff[i + 1] = s[tid];
    if (tid == SCAN_B - 1) g_bsum[blockIdx.x] = s[tid];
}
__global__ void scan_sums_kernel() {
    __shared__ int s[128];
    int tid = threadIdx.x;
    int v = (tid < NBLK) ? g_bsum[tid] : 0;
    s[tid] = v;
    __syncthreads();
#pragma unroll
    for (int d = 1; d < 128; d <<= 1) {
        int t = (tid >= d) ? s[tid - d] : 0;
        __syncthreads();
        s[tid] += t;
        __syncthreads();
    }
    if (tid < NBLK) g_bsum[tid] = s[tid] - v;
    if (tid == 0) g_noff[0] = 0;
}
__global__ void add_off_kernel() {       // also seeds cursor
    int i = blockIdx.x * blockDim.x + threadIdx.x;
    if (i < N_NODES) {
        int v = g_noff[i + 1] + g_bsum[i / SCAN_B];
        g_noff[i + 1] = v;
        if (i + 1 < N_NODES) g_cursor[i + 1] = v;
        if (i == 0) g_cursor[0] = 0;
    }
}
__global__ void fill_kernel(const int* __restrict__ ei, const int* __restrict__ ea) {
    int e = blockIdx.x * blockDim.x + threadIdx.x;
    if (e >= N_EDGES) return;
    int src = ei[e];
    int dst = ei[N_EDGES + e];
    int combo = ea[3 * e + 0] | (ea[3 * e + 1] << 3) | (ea[3 * e + 2] << 6);
    int pos = atomicAdd(&g_cursor[dst], 1);
    g_elist[pos] = src | (combo << 17);
}
__global__ void combo_kernel(const float* __restrict__ bond) {
    int c = blockIdx.x;
    int d = threadIdx.x;
    int a0 = c & 7, a1 = (c >> 3) & 7, a2 = (c >> 6) & 7;
    float v = bond[(size_t)(0 * 8 + a0) * D + d]
            + bond[(size_t)(1 * 8 + a1) * D + d]
            + bond[(size_t)(2 * 8 + a2) * D + d];
    g_combo[c * D + d] = __float2half_rn(v);
}

// ---------------- node init (4 nodes/block, float4) ----------------
__global__ void node_init_kernel(const int* __restrict__ x,
                                 const float4* __restrict__ atom_emb,
                                 const float4* __restrict__ vn_emb,
                                 float4* __restrict__ h,
                                 uint2* __restrict__ hh,
                                 float4* __restrict__ vn,
                                 float4* __restrict__ out_hinit)
{
    int n = blockIdx.x * 4 + (threadIdx.x >> 6);
    if (n >= N_NODES) return;
    int q = threadIdx.x & 63;
    float4 s = make_float4(0.f, 0.f, 0.f, 0.f);
#pragma unroll
    for (int f = 0; f < 9; f++) {
        int xi = __ldg(&x[n * 9 + f]);
        float4 v = atom_emb[((size_t)f * 64 + xi) * 64 + q];
        s.x += v.x; s.y += v.y; s.z += v.z; s.w += v.w;
    }
    size_t idx = (size_t)n * 64 + q;
    out_hinit[idx] = s;
    float4 vv = vn_emb[q];
    float4 hv = make_float4(s.x + vv.x, s.y + vv.y, s.z + vv.z, s.w + vv.w);
    h[idx] = hv;
    uint2 hu;
    hu.x = f22h2(hv.x, hv.y);
    hu.y = f22h2(hv.z, hv.w);
    hh[idx] = hu;
    if (n < NGRAPHS) vn[(size_t)n * 64 + q] = vv;
}

// ---------------- graph segment offsets ----------------
__global__ void offsets_kernel(const int* __restrict__ batch, int* __restrict__ off)
{
    int g = blockIdx.x * blockDim.x + threadIdx.x;
    if (g > NGRAPHS) return;
    int lo = 0, hi = N_NODES;
    while (lo < hi) {
        int mid = (lo + hi) >> 1;
        if (batch[mid] < g) lo = mid + 1; else hi = mid;
    }
    off[g] = lo;
}

// ---------------- CSR gather aggregation (all-fp16 gathers, fp32 math) ----------------
template<bool WITHVN>
__global__ void aggregate_kernel(const uint2* __restrict__ hin,
                                 const uint2* __restrict__ vnh,
                                 const int* __restrict__ batch,
                                 uint2* __restrict__ agg)
{
    int n = blockIdx.x * 4 + (threadIdx.x >> 6);
    if (n >= N_NODES) return;
    int q = threadIdx.x & 63;
    const uint2* combo2 = reinterpret_cast<const uint2*>(g_combo);
    int i0 = g_noff[n], i1 = g_noff[n + 1];
    uint2 su = hin[(size_t)n * 64 + q];
    float2 s01 = h2f2(su.x), s23 = h2f2(su.y);
    float ax = s01.x, ay = s01.y, az = s23.x, aw = s23.y;
    if (WITHVN) {
        int bg = __ldg(&batch[n]);
        uint2 vu = vnh[(size_t)bg * 64 + q];
        float2 va = h2f2(vu.x), vb = h2f2(vu.y);
        ax += va.x; ay += va.y; az += vb.x; aw += vb.y;
    }
    int i = i0;
    for (; i + 1 < i1; i += 2) {
        int ed0 = __ldg(&g_elist[i]);
        int ed1 = __ldg(&g_elist[i + 1]);
        int s0 = ed0 & 0x1FFFF, c0 = ed0 >> 17;
        int s1 = ed1 & 0x1FFFF, c1 = ed1 >> 17;
        uint2 u0 = hin[(size_t)s0 * 64 + q];
        uint2 u1 = hin[(size_t)s1 * 64 + q];
        float2 v0a = h2f2(u0.x), v0b = h2f2(u0.y);
        float2 v1a = h2f2(u1.x), v1b = h2f2(u1.y);
        uint2 cu0 = combo2[(size_t)c0 * 64 + q];
        uint2 cu1 = combo2[(size_t)c1 * 64 + q];
        float2 b0a = h2f2(cu0.x), b0b = h2f2(cu0.y);
        float2 b1a = h2f2(cu1.x), b1b = h2f2(cu1.y);
        if (WITHVN) {
            int bg0 = __ldg(&batch[s0]);
            int bg1 = __ldg(&batch[s1]);
            uint2 w0 = vnh[(size_t)bg0 * 64 + q];
            uint2 w1 = vnh[(size_t)bg1 * 64 + q];
            float2 w0a = h2f2(w0.x), w0b = h2f2(w0.y);
            float2 w1a = h2f2(w1.x), w1b = h2f2(w1.y);
            v0a.x += w0a.x; v0a.y += w0a.y; v0b.x += w0b.x; v0b.y += w0b.y;
            v1a.x += w1a.x; v1a.y += w1a.y; v1b.x += w1b.x; v1b.y += w1b.y;
        }
        ax += fmaxf(v0a.x + b0a.x, 0.f) + MSG_EPS + fmaxf(v1a.x + b1a.x, 0.f) + MSG_EPS;
        ay += fmaxf(v0a.y + b0a.y, 0.f) + MSG_EPS + fmaxf(v1a.y + b1a.y, 0.f) + MSG_EPS;
        az += fmaxf(v0b.x + b0b.x, 0.f) + MSG_EPS + fmaxf(v1b.x + b1b.x, 0.f) + MSG_EPS;
        aw += fmaxf(v0b.y + b0b.y, 0.f) + MSG_EPS + fmaxf(v1b.y + b1b.y, 0.f) + MSG_EPS;
    }
    if (i < i1) {
        int ed = __ldg(&g_elist[i]);
        int s0 = ed & 0x1FFFF, c0 = ed >> 17;
        uint2 u0 = hin[(size_t)s0 * 64 + q];
        float2 va = h2f2(u0.x), vb = h2f2(u0.y);
        uint2 cu = combo2[(size_t)c0 * 64 + q];
        float2 ba = h2f2(cu.x), bb = h2f2(cu.y);
        if (WITHVN) {
            int bg0 = __ldg(&batch[s0]);
            uint2 w = vnh[(size_t)bg0 * 64 + q];
            float2 wa = h2f2(w.x), wb = h2f2(w.y);
            va.x += wa.x; va.y += wa.y; vb.x += wb.x; vb.y += wb.y;
        }
        ax += fmaxf(va.x + ba.x, 0.f) + MSG_EPS;
        ay += fmaxf(va.y + ba.y, 0.f) + MSG_EPS;
        az += fmaxf(vb.x + bb.x, 0.f) + MSG_EPS;
        aw += fmaxf(vb.y + bb.y, 0.f) + MSG_EPS;
    }
    uint2 ou;
    ou.x = f22h2(ax, ay);
    ou.y = f22h2(az, aw);
    agg[(size_t)n * 64 + q] = ou;
}

// ---------------- tf32 helpers ----------------
__device__ __forceinline__ float tf32r(float x) {
    uint32_t u;
    asm("cvt.rna.tf32.f32 %0, %1;" : "=r"(u) : "f"(x));
    return __uint_as_float(u);
}
__device__ __forceinline__ uint32_t tf32u(float x) {
    uint32_t u;
    asm("cvt.rna.tf32.f32 %0, %1;" : "=r"(u) : "f"(x));
    return u;
}
__device__ __forceinline__ void mma_tf32(float* c, const uint32_t* a, const uint32_t* b) {
    asm volatile("mma.sync.aligned.m16n8k8.row.col.f32.tf32.tf32.f32 "
                 "{%0,%1,%2,%3}, {%4,%5,%6,%7}, {%8,%9}, {%0,%1,%2,%3};\n"
                 : "+f"(c[0]), "+f"(c[1]), "+f"(c[2]), "+f"(c[3])
                 : "r"(a[0]), "r"(a[1]), "r"(a[2]), "r"(a[3]),
                   "r"(b[0]), "r"(b[1]));
}

// ==================== fused GCN GEMM + residual + LN/ReLU [+ FFN] ====================
// A operand fp16 (agg). h2 now written ONLY as fp16. outh nullable (layer 3: dead).
#define HT_STRIDE 260
#define SM_AS   0
#define SM_BS   9216
#define SM_WF   66560
#define SM_SSA  80384
#define SM_SSB  81664
#define SM_MU   82944
#define SM_RS   83200
#define SM_TOTAL 83456

__global__ __launch_bounds__(256)
void gemm_fused(const __half* __restrict__ A16,
                const float* __restrict__ W, const float* __restrict__ bias,
                const float* __restrict__ res,
                const float* __restrict__ gam, const float* __restrict__ bet,
                const float* __restrict__ ffnW, const float* __restrict__ ffnB,
                float* __restrict__ outh,
                __half* __restrict__ outh2h,
                float* __restrict__ outf, int M)
{
    constexpr int BM = 64, BN = 256, BK = 16, K = D;
    constexpr int NITER = K / BK;
    constexpr int MT = 2, NT = 8;
    extern __shared__ char smraw[];
    float* As = reinterpret_cast<float*>(smraw + SM_AS);
    float* Bs = reinterpret_cast<float*>(smraw + SM_BS);
    float* HT = reinterpret_cast<float*>(smraw);
    float* Wf = reinterpret_cast<float*>(smraw + SM_WF);
    float* ssA = reinterpret_cast<float*>(smraw + SM_SSA);
    float* ssB = reinterpret_cast<float*>(smraw + SM_SSB);
    float* smu = reinterpret_cast<float*>(smraw + SM_MU);
    float* srs = reinterpret_cast<float*>(smraw + SM_RS);
    const uint32_t smbase = (uint32_t)__cvta_generic_to_shared(smraw);

    const int tid  = threadIdx.x;
    const int lane = tid & 31;
    const int wid  = tid >> 5;
    const int wr   = wid >> 2;
    const int wc   = wid & 3;
    const int gid  = lane >> 2;
    const int tig  = lane & 3;
    const int m0   = blockIdx.x * BM;

    const int arow = tid & 63;
    const int akc  = (tid >> 6) << 2;
    const bool avalid = (m0 + arow) < M;
    const uint2* aptr = reinterpret_cast<const uint2*>(A16 + (size_t)(m0 + arow) * K + akc);

    const int bk  = tid >> 4;
    const int bnc = (tid & 15) << 4;
    const float* bptr = W + (size_t)bk * BN + bnc;

    // ---- prologue: B stages 0 and 1 in flight ----
    {
        uint32_t dst0 = smbase + SM_BS + (uint32_t)((bk * 264 + bnc) * 4);
#pragma unroll
        for (int j = 0; j < 4; j++)
            cp_async16(dst0 + j * 16, bptr + j * 4);
        cp_commit();
        uint32_t dst1 = smbase + SM_BS + (uint32_t)(((16 + bk) * 264 + bnc) * 4);
        const float* bp1 = bptr + (size_t)BK * BN;
#pragma unroll
        for (int j = 0; j < 4; j++)
            cp_async16(dst1 + j * 16, bp1 + j * 4);
        cp_commit();
    }
    {
        uint2 au = make_uint2(0u, 0u);
        if (avalid) au = aptr[0];
        float2 a01 = h2f2(au.x), a23 = h2f2(au.y);
        As[(akc + 0) * 72 + arow] = a01.x;
        As[(akc + 1) * 72 + arow] = a01.y;
        As[(akc + 2) * 72 + arow] = a23.x;
        As[(akc + 3) * 72 + arow] = a23.y;
    }
    cp_wait1();
    __syncthreads();

    float acc[MT][NT][4];
#pragma unroll
    for (int i = 0; i < MT; i++)
#pragma unroll
        for (int j = 0; j < NT; j++)
#pragma unroll
            for (int q = 0; q < 4; q++) acc[i][j][q] = 0.f;

    for (int k0 = 0; k0 < NITER; k0++) {
        const int acur = k0 & 1;
        const int bcur = k0 % 3;
        uint2 au = make_uint2(0u, 0u);
        if (k0 + 2 < NITER) {
            const int bnx = (k0 + 2) % 3;
            uint32_t dst = smbase + SM_BS + (uint32_t)(((bnx * 16 + bk) * 264 + bnc) * 4);
            const float* bp = bptr + (size_t)(k0 + 2) * BK * BN;
#pragma unroll
            for (int j = 0; j < 4; j++)
                cp_async16(dst + j * 16, bp + j * 4);
            cp_commit();
        }
        if (k0 + 1 < NITER) {
            if (avalid) au = aptr[(k0 + 1) * (BK / 4)];
        }
#pragma unroll
        for (int ks = 0; ks < 2; ks++) {
            uint32_t af[MT][4];
            uint32_t bf[NT][2];
#pragma unroll
            for (int mt = 0; mt < MT; mt++) {
                int r = wr * 32 + mt * 16 + gid;
                af[mt][0] = __float_as_uint(As[(acur * 16 + ks * 8 + tig) * 72 + r]);
                af[mt][1] = __float_as_uint(As[(acur * 16 + ks * 8 + tig) * 72 + r + 8]);
                af[mt][2] = __float_as_uint(As[(acur * 16 + ks * 8 + tig + 4) * 72 + r]);
                af[mt][3] = __float_as_uint(As[(acur * 16 + ks * 8 + tig + 4) * 72 + r + 8]);
            }
#pragma unroll
            for (int nt = 0; nt < NT; nt++) {
                int c = wc * 64 + nt * 8 + gid;
                bf[nt][0] = tf32u(Bs[(bcur * 16 + ks * 8 + tig) * 264 + c]);
                bf[nt][1] = tf32u(Bs[(bcur * 16 + ks * 8 + tig + 4) * 264 + c]);
            }
#pragma unroll
            for (int mt = 0; mt < MT; mt++)
#pragma unroll
                for (int nt = 0; nt < NT; nt++)
                    mma_tf32(acc[mt][nt], af[mt], bf[nt]);
        }
        if (k0 + 1 < NITER) {
            const int anx = acur ^ 1;
            float2 a01 = h2f2(au.x), a23 = h2f2(au.y);
            As[(anx * 16 + akc + 0) * 72 + arow] = a01.x;
            As[(anx * 16 + akc + 1) * 72 + arow] = a01.y;
            As[(anx * 16 + akc + 2) * 72 + arow] = a23.x;
            As[(anx * 16 + akc + 3) * 72 + arow] = a23.y;
            if (k0 + 2 < NITER) cp_wait1(); else cp_wait0();
            __syncthreads();
        }
    }

    if (ffnW) {   // prefetch FFN W chunks 0 and 1
        int kr = tid >> 4;
        int wcol = (tid & 15) << 2;
        uint32_t dst0 = smbase + SM_WF + (uint32_t)((kr * 72 + wcol) * 4);
        cp_async16(dst0, ffnW + (size_t)kr * 64 + wcol);
        cp_commit();
        uint32_t dst1 = smbase + SM_WF + (uint32_t)(((16 + kr) * 72 + wcol) * 4);
        cp_async16(dst1, ffnW + (size_t)(16 + kr) * 64 + wcol);
        cp_commit();
    }

    // ---- epilogue: v = acc + bias (+res); write h (if live) ----
#pragma unroll
    for (int mt = 0; mt < MT; mt++) {
        int r  = m0 + wr * 32 + mt * 16 + gid;
        int r2 = r + 8;
#pragma unroll
        for (int nt = 0; nt < NT; nt++) {
            int c = wc * 64 + nt * 8 + 2 * tig;
            float2 bi = *reinterpret_cast<const float2*>(&bias[c]);
            float v0 = acc[mt][nt][0] + bi.x;
            float v1 = acc[mt][nt][1] + bi.y;
            float v2 = acc[mt][nt][2] + bi.x;
            float v3 = acc[mt][nt][3] + bi.y;
            if (res) {
                if (r < M) {
                    float2 rr = *reinterpret_cast<const float2*>(&res[(size_t)r * D + c]);
                    v0 += rr.x; v1 += rr.y;
                }
                if (r2 < M) {
                    float2 rr = *reinterpret_cast<const float2*>(&res[(size_t)r2 * D + c]);
                    v2 += rr.x; v3 += rr.y;
                }
            }
            acc[mt][nt][0] = v0; acc[mt][nt][1] = v1;
            acc[mt][nt][2] = v2; acc[mt][nt][3] = v3;
            if (outh) {
                if (r < M)
                    *reinterpret_cast<float2*>(&outh[(size_t)r * D + c]) = make_float2(v0, v1);
                if (r2 < M)
                    *reinterpret_cast<float2*>(&outh[(size_t)r2 * D + c]) = make_float2(v2, v3);
            }
        }
    }

    if (ffnW) {   // mainloop smem reads done -> h_tile
        __syncthreads();
#pragma unroll
        for (int mt = 0; mt < MT; mt++) {
            int lr  = wr * 32 + mt * 16 + gid;
            int lr2 = lr + 8;
#pragma unroll
            for (int nt = 0; nt < NT; nt++) {
                int c = wc * 64 + nt * 8 + 2 * tig;
                HT[lr  * HT_STRIDE + c    ] = tf32r(acc[mt][nt][0]);
                HT[lr  * HT_STRIDE + c + 1] = tf32r(acc[mt][nt][1]);
                HT[lr2 * HT_STRIDE + c    ] = tf32r(acc[mt][nt][2]);
                HT[lr2 * HT_STRIDE + c + 1] = tf32r(acc[mt][nt][3]);
            }
        }
    }

    // ---- LayerNorm + ReLU -> outh2h (fp16 only) ----
    if (gam) {
#pragma unroll
        for (int mt = 0; mt < MT; mt++) {
#pragma unroll
            for (int hh = 0; hh < 2; hh++) {
                float s = 0.f, q = 0.f;
#pragma unroll
                for (int nt = 0; nt < NT; nt++) {
                    float u0 = acc[mt][nt][2 * hh];
                    float u1 = acc[mt][nt][2 * hh + 1];
                    s += u0 + u1;
                    q += u0 * u0 + u1 * u1;
                }
                s += __shfl_xor_sync(0xffffffffu, s, 1);
                q += __shfl_xor_sync(0xffffffffu, q, 1);
                s += __shfl_xor_sync(0xffffffffu, s, 2);
                q += __shfl_xor_sync(0xffffffffu, q, 2);
                if (tig == 0) {
                    int lr = wr * 32 + mt * 16 + hh * 8 + gid;
                    ssA[lr * 5 + wc] = s;
                    ssB[lr * 5 + wc] = q;
                }
            }
        }
        __syncthreads();
        if (tid < BM) {
            float s = ssA[tid * 5 + 0] + ssA[tid * 5 + 1] + ssA[tid * 5 + 2] + ssA[tid * 5 + 3];
            float q = ssB[tid * 5 + 0] + ssB[tid * 5 + 1] + ssB[tid * 5 + 2] + ssB[tid * 5 + 3];
            float mu  = s * (1.f / D);
            float var = q * (1.f / D) - mu * mu;
            smu[tid] = mu;
            srs[tid] = rsqrtf(var + LN_EPS);
        }
        __syncthreads();
#pragma unroll
        for (int mt = 0; mt < MT; mt++) {
            int lr  = wr * 32 + mt * 16 + gid;
            int lr2 = lr + 8;
            int r   = m0 + lr;
            int r2  = m0 + lr2;
            float mu0 = smu[lr],  rs0 = srs[lr];
            float mu1 = smu[lr2], rs1 = srs[lr2];
#pragma unroll
            for (int nt = 0; nt < NT; nt++) {
                int c = wc * 64 + nt * 8 + 2 * tig;
                float2 gg = *reinterpret_cast<const float2*>(&gam[c]);
                float2 bb = *reinterpret_cast<const float2*>(&bet[c]);
                if (r < M) {
                    float y0 = fmaxf((acc[mt][nt][0] - mu0) * rs0 * gg.x + bb.x, 0.f);
                    float y1 = fmaxf((acc[mt][nt][1] - mu0) * rs0 * gg.y + bb.y, 0.f);
                    *reinterpret_cast<unsigned*>(&outh2h[(size_t)r * D + c]) = f22h2(y0, y1);
                }
                if (r2 < M) {
                    float y2 = fmaxf((acc[mt][nt][2] - mu1) * rs1 * gg.x + bb.x, 0.f);
                    float y3 = fmaxf((acc[mt][nt][3] - mu1) * rs1 * gg.y + bb.y, 0.f);
                    *reinterpret_cast<unsigned*>(&outh2h[(size_t)r2 * D + c]) = f22h2(y2, y3);
                }
            }
        }
    }

    if (!ffnW) return;

    // ---- FFN phase: outf = h_tile @ ffnW + ffnB, 64x64x256, 3-stage Wf ----
    const int wrf = wid >> 1;
    const int wcf = wid & 1;
    const int fkr = tid >> 4;
    const int fwc = (tid & 15) << 2;
    cp_wait1();
    __syncthreads();

    float fac[4][4];
#pragma unroll
    for (int i = 0; i < 4; i++)
#pragma unroll
        for (int j = 0; j < 4; j++) fac[i][j] = 0.f;

    constexpr int FCH = 16;
    for (int ch = 0; ch < FCH; ch++) {
        const int cur = ch % 3;
        if (ch + 2 < FCH) {
            const int nx = (ch + 2) % 3;
            uint32_t dst = smbase + SM_WF + (uint32_t)(((nx * 16 + fkr) * 72 + fwc) * 4);
            cp_async16(dst, ffnW + (size_t)((ch + 2) * 16 + fkr) * 64 + fwc);
            cp_commit();
        }
#pragma unroll
        for (int ks = 0; ks < 2; ks++) {
            int kb = ch * 16 + ks * 8;
            uint32_t af[4];
            {
                int r = wrf * 16 + gid;
                af[0] = __float_as_uint(HT[r * HT_STRIDE + kb + tig]);
                af[1] = __float_as_uint(HT[(r + 8) * HT_STRIDE + kb + tig]);
                af[2] = __float_as_uint(HT[r * HT_STRIDE + kb + tig + 4]);
                af[3] = __float_as_uint(HT[(r + 8) * HT_STRIDE + kb + tig + 4]);
            }
#pragma unroll
            for (int nt = 0; nt < 4; nt++) {
                int c = wcf * 32 + nt * 8 + gid;
                uint32_t bf[2];
                bf[0] = tf32u(Wf[(cur * 16 + ks * 8 + tig) * 72 + c]);
                bf[1] = tf32u(Wf[(cur * 16 + ks * 8 + tig + 4) * 72 + c]);
                mma_tf32(fac[nt], af, bf);
            }
        }
        if (ch + 1 < FCH) {
            if (ch + 2 < FCH) cp_wait1(); else cp_wait0();
            __syncthreads();
        }
    }

    {
        int r  = m0 + wrf * 16 + gid;
        int r2 = r + 8;
#pragma unroll
        for (int nt = 0; nt < 4; nt++) {
            int c = wcf * 32 + nt * 8 + 2 * tig;
            float2 bi = *reinterpret_cast<const float2*>(&ffnB[c]);
            if (r < M)
                *reinterpret_cast<float2*>(&outf[(size_t)r * 256 + c]) =
                    make_float2(fac[nt][0] + bi.x, fac[nt][1] + bi.y);
            if (r2 < M)
                *reinterpret_cast<float2*>(&outf[(size_t)r2 * 256 + c]) =
                    make_float2(fac[nt][2] + bi.x, fac[nt][3] + bi.y);
        }
    }
}

// ---------------- standalone tf32 FFN GEMM (runs on side stream; fp32 A = h) ----------------
template<int BN, int WR, int WC>
__global__ __launch_bounds__(256)
void gemm_tf32(const float* __restrict__ A,
               const float* __restrict__ W, const float* __restrict__ bias,
               float* __restrict__ out,
               int M, int ldout, int ldw)
{
    constexpr int BM = 128, BK = 16, K = D;
    constexpr int NITER = K / BK;
    constexpr int TM = BM / WR;
    constexpr int TN = BN / WC;
    constexpr int MT = TM / 16;
    constexpr int NT = TN / 8;
    constexpr int PAD = 8;
    __shared__ float As[2][BK][BM + PAD];
    __shared__ float Bs[2][BK][BN + PAD];

    const int tid  = threadIdx.x;
    const int lane = tid & 31;
    const int wid  = tid >> 5;
    const int wr   = wid / WC;
    const int wc   = wid % WC;
    const int gid  = lane >> 2;
    const int tig  = lane & 3;
    const int m0   = blockIdx.x * BM;

    const int arow = tid & 127;
    const int akc  = (tid >> 7) << 3;
    const bool avalid = (m0 + arow) < M;
    const float* aptr = A + (size_t)(m0 + arow) * K + akc;

    constexpr int BVEC = (BN == 128) ? 2 : 1;
    const int bk  = tid >> 4;
    const int bnc = (tid & 15) * (BVEC * 4);
    const float* bptr = W + (size_t)bk * ldw + bnc;

    float4 a_st[2];
    float4 b_st[BVEC];

    a_st[0] = make_float4(0.f, 0.f, 0.f, 0.f);
    a_st[1] = a_st[0];
    if (avalid) {
        a_st[0] = *reinterpret_cast<const float4*>(aptr);
        a_st[1] = *reinterpret_cast<const float4*>(aptr + 4);
    }
#pragma unroll
    for (int i = 0; i < BVEC; i++)
        b_st[i] = *reinterpret_cast<const float4*>(bptr + i * 4);

    {
        const float* av = reinterpret_cast<const float*>(a_st);
#pragma unroll
        for (int j = 0; j < 8; j++) As[0][akc + j][arow] = tf32r(av[j]);
        const float* bv = reinterpret_cast<const float*>(b_st);
#pragma unroll
        for (int j = 0; j < BVEC * 4; j++) Bs[0][bk][bnc + j] = tf32r(bv[j]);
    }
    __syncthreads();

    float acc[MT][NT][4];
#pragma unroll
    for (int i = 0; i < MT; i++)
#pragma unroll
        for (int j = 0; j < NT; j++)
#pragma unroll
            for (int q = 0; q < 4; q++) acc[i][j][q] = 0.f;

    for (int k0 = 0; k0 < NITER; k0++) {
        const int cur = k0 & 1;
        if (k0 + 1 < NITER) {
            a_st[0] = make_float4(0.f, 0.f, 0.f, 0.f);
            a_st[1] = a_st[0];
            if (avalid) {
                a_st[0] = *reinterpret_cast<const float4*>(aptr + (k0 + 1) * BK);
                a_st[1] = *reinterpret_cast<const float4*>(aptr + (k0 + 1) * BK + 4);
            }
#pragma unroll
            for (int i = 0; i < BVEC; i++)
                b_st[i] = *reinterpret_cast<const float4*>(bptr + (size_t)(k0 + 1) * BK * ldw + i * 4);
        }
#pragma unroll
        for (int ks = 0; ks < 2; ks++) {
            uint32_t af[MT][4];
            uint32_t bf[NT][2];
#pragma unroll
            for (int mt = 0; mt < MT; mt++) {
                int r = wr * TM + mt * 16 + gid;
                af[mt][0] = __float_as_uint(As[cur][ks * 8 + tig    ][r]);
                af[mt][1] = __float_as_uint(As[cur][ks * 8 + tig    ][r + 8]);
                af[mt][2] = __float_as_uint(As[cur][ks * 8 + tig + 4][r]);
                af[mt][3] = __float_as_uint(As[cur][ks * 8 + tig + 4][r + 8]);
            }
#pragma unroll
            for (int nt = 0; nt < NT; nt++) {
                int c = wc * TN + nt * 8 + gid;
                bf[nt][0] = __float_as_uint(Bs[cur][ks * 8 + tig    ][c]);
                bf[nt][1] = __float_as_uint(Bs[cur][ks * 8 + tig + 4][c]);
            }
#pragma unroll
            for (int mt = 0; mt < MT; mt++)
#pragma unroll
                for (int nt = 0; nt < NT; nt++)
                    mma_tf32(acc[mt][nt], af[mt], bf[nt]);
        }
        if (k0 + 1 < NITER) {
            const int nxt = cur ^ 1;
            const float* av = reinterpret_cast<const float*>(a_st);
#pragma unroll
            for (int j = 0; j < 8; j++) As[nxt][akc + j][arow] = tf32r(av[j]);
            const float* bv = reinterpret_cast<const float*>(b_st);
#pragma unroll
            for (int j = 0; j < BVEC * 4; j++) Bs[nxt][bk][bnc + j] = tf32r(bv[j]);
            __syncthreads();
        }
    }

#pragma unroll
    for (int mt = 0; mt < MT; mt++) {
#pragma unroll
        for (int nt = 0; nt < NT; nt++) {
            int r = m0 + wr * TM + mt * 16 + gid;
            int c = wc * TN + nt * 8 + 2 * tig;
            float2 bi = *reinterpret_cast<const float2*>(&bias[c]);
            if (r < M)
                *reinterpret_cast<float2*>(&out[(size_t)r * ldout + c]) =
                    make_float2(acc[mt][nt][0] + bi.x, acc[mt][nt][1] + bi.y);
            int r2 = r + 8;
            if (r2 < M)
                *reinterpret_cast<float2*>(&out[(size_t)r2 * ldout + c]) =
                    make_float2(acc[mt][nt][2] + bi.x, acc[mt][nt][3] + bi.y);
        }
    }
}

// ---------------- virtual-node path (fp16 h2; fp32 vn master + fp16 vnh copy) ----------------
__device__ __forceinline__ void ln_rows8(float (*t)[D], float (*s)[D],
                                         const float* __restrict__ gam,
                                         const float* __restrict__ bet,
                                         float* smu, float* srs)
{
    int lane = threadIdx.x & 31, w = threadIdx.x >> 5;
    float a = 0.f, b = 0.f;
#pragma unroll
    for (int i = 0; i < 8; i++) {
        float v = t[w][lane + 32 * i];
        a += v; b += v * v;
    }
#pragma unroll
    for (int o = 16; o; o >>= 1) {
        a += __shfl_down_sync(0xffffffffu, a, o);
        b += __shfl_down_sync(0xffffffffu, b, o);
    }
    if (lane == 0) {
        float mu = a * (1.f / D);
        float var = b * (1.f / D) - mu * mu;
        smu[w] = mu;
        srs[w] = rsqrtf(var + LN_EPS);
    }
    __syncthreads();
    int d = threadIdx.x;
    float gd = gam[d], bd = bet[d];
#pragma unroll
    for (int gg = 0; gg < 8; gg++) {
        float v = (t[gg][d] - smu[gg]) * srs[gg] * gd + bd;
        s[gg][d] = fmaxf(v, 0.f);
    }
}

__global__ void vn_mlp_kernel(const __half* __restrict__ h2h, const int* __restrict__ off,
                              const float* __restrict__ W1, const float* __restrict__ b1,
                              const float* __restrict__ g1, const float* __restrict__ be1,
                              const float* __restrict__ W2, const float* __restrict__ b2,
                              const float* __restrict__ g2, const float* __restrict__ be2,
                              float* __restrict__ vn, __half* __restrict__ vnh)
{
    __shared__ float s[8][D];
    __shared__ float t[8][D];
    __shared__ float smu[8], srs[8];
    int d = threadIdx.x;
    int g0 = blockIdx.x * 8;

#pragma unroll
    for (int gg = 0; gg < 8; gg++) {
        int g = g0 + gg;
        float acc = vn[(size_t)g * D + d];
        int n1 = off[g + 1];
        for (int n = off[g]; n < n1; n++)
            acc += __half2float(h2h[(size_t)n * D + d]);
        s[gg][d] = acc;
    }
    __syncthreads();

    float y[8];
#pragma unroll
    for (int gg = 0; gg < 8; gg++) y[gg] = b1[d];
    for (int k = 0; k < D; k++) {
        float w = W1[(size_t)k * D + d];
#pragma unroll
        for (int gg = 0; gg < 8; gg++) y[gg] = fmaf(s[gg][k], w, y[gg]);
    }
    __syncthreads();
#pragma unroll
    for (int gg = 0; gg < 8; gg++) t[gg][d] = y[gg];
    __syncthreads();
    ln_rows8(t, s, g1, be1, smu, srs);
    __syncthreads();

#pragma unroll
    for (int gg = 0; gg < 8; gg++) y[gg] = b2[d];
    for (int k = 0; k < D; k++) {
        float w = W2[(size_t)k * D + d];
#pragma unroll
        for (int gg = 0; gg < 8; gg++) y[gg] = fmaf(s[gg][k], w, y[gg]);
    }
    __syncthreads();
#pragma unroll
    for (int gg = 0; gg < 8; gg++) t[gg][d] = y[gg];
    __syncthreads();
    ln_rows8(t, s, g2, be2, smu, srs);
    __syncthreads();
#pragma unroll
    for (int gg = 0; gg < 8; gg++) {
        int g = g0 + gg;
        float v = s[gg][d];
        vn[(size_t)g * D + d] = v;
        vnh[(size_t)g * D + d] = __float2half_rn(v);
    }
}

// ---------------- launcher ----------------
extern "C" void kernel_launch(void* const* d_in, const int* in_sizes, int n_in,
                              void* d_out, int out_size)
{
    const int*   x          = (const int*)  d_in[0];
    const int*   edge_attr  = (const int*)  d_in[1];
    const int*   edge_index = (const int*)  d_in[2];
    const int*   batch      = (const int*)  d_in[3];
    const float* atom_emb   = (const float*)d_in[4];
    const float* bond_emb   = (const float*)d_in[5];
    const float* vn_emb     = (const float*)d_in[6];
    const float* gcn_w      = (const float*)d_in[7];
    const float* gcn_b      = (const float*)d_in[8];
    const float* norm_g     = (const float*)d_in[9];
    const float* norm_b     = (const float*)d_in[10];
    const float* ffn_w      = (const float*)d_in[11];
    const float* ffn_b      = (const float*)d_in[12];
    const float* vn_w1      = (const float*)d_in[13];
    const float* vn_b1      = (const float*)d_in[14];
    const float* vn_g1      = (const float*)d_in[15];
    const float* vn_be1     = (const float*)d_in[16];
    const float* vn_w2      = (const float*)d_in[17];
    const float* vn_b2      = (const float*)d_in[18];
    const float* vn_g2      = (const float*)d_in[19];
    const float* vn_be2     = (const float*)d_in[20];

    float* out       = (float*)d_out;                       // h_graph [N,256]
    float* out_hinit = out + (size_t)N_NODES * D;           // h_init  [N,256]

    float *hb0, *hb1, *pvn; int* poff;
    __half *phh, *ph2h, *paggh, *pvnh;
    cudaGetSymbolAddress((void**)&hb0,  g_h);
    cudaGetSymbolAddress((void**)&hb1,  g_hb);
    cudaGetSymbolAddress((void**)&phh,  g_hh);
    cudaGetSymbolAddress((void**)&ph2h, g_h2h);
    cudaGetSymbolAddress((void**)&paggh, g_aggh);
    cudaGetSymbolAddress((void**)&pvn,  g_vn);
    cudaGetSymbolAddress((void**)&pvnh, g_vnh);
    cudaGetSymbolAddress((void**)&poff, g_off);

    static cudaStream_t s1 = nullptr;
    static cudaEvent_t evFork, evSide, evH[3], evF[3];
    if (!s1) {
        cudaStreamCreateWithFlags(&s1, cudaStreamNonBlocking);
        cudaEventCreateWithFlags(&evFork, cudaEventDisableTiming);
        cudaEventCreateWithFlags(&evSide, cudaEventDisableTiming);
        for (int i = 0; i < 3; i++) {
            cudaEventCreateWithFlags(&evH[i], cudaEventDisableTiming);
            cudaEventCreateWithFlags(&evF[i], cudaEventDisableTiming);
        }
        cudaFuncSetAttribute(gemm_fused, cudaFuncAttributeMaxDynamicSharedMemorySize, SM_TOTAL);
    }

    const int FUSED_GRID = (N_NODES + 63) / 64;    // 1563
    const int FFN_GRID   = (N_NODES + 127) / 128;  // 782
    const int AGG_GRID   = (N_NODES + 3) / 4;

    float* hwr[4]  = {hb0, hb1, hb0, nullptr};     // layer 3's h is dead
    float* hres[4] = {nullptr, hb0, hb1, hb0};

    // ---- fork: prologue on two streams ----
    cudaEventRecord(evFork, 0);
    cudaStreamWaitEvent(s1, evFork, 0);

    // stream 0: CSR build chain
    zero_deg_kernel<<<(N_NODES + 255) / 256, 256>>>();
    hist_kernel<<<(N_EDGES + 255) / 256, 256>>>(edge_index);
    scan_block_kernel<<<NBLK, SCAN_B>>>();
    scan_sums_kernel<<<1, 128>>>();
    add_off_kernel<<<(N_NODES + 255) / 256, 256>>>();
    fill_kernel<<<(N_EDGES + 255) / 256, 256>>>(edge_index, edge_attr);

    // stream 1: node init, combo table, graph offsets
    node_init_kernel<<<N_NODES / 4, 256, 0, s1>>>(x, (const float4*)atom_emb,
                                                  (const float4*)vn_emb,
                                                  (float4*)hb0, (uint2*)phh,
                                                  (float4*)pvn, (float4*)out_hinit);
    combo_kernel<<<512, 256, 0, s1>>>(bond_emb);
    offsets_kernel<<<(NGRAPHS + 1 + 255) / 256, 256, 0, s1>>>(batch, poff);
    cudaEventRecord(evSide, s1);
    cudaStreamWaitEvent(0, evSide, 0);

    // ----- layer 0 -----
    aggregate_kernel<false><<<AGG_GRID, 256>>>((const uint2*)phh, nullptr, nullptr, (uint2*)paggh);
    gemm_fused<<<FUSED_GRID, 256, SM_TOTAL>>>(paggh, gcn_w, gcn_b, nullptr,
                                              norm_g, norm_b, nullptr, nullptr,
                                              hwr[0], ph2h, nullptr, N_NODES);
    cudaEventRecord(evH[0], 0);
    cudaStreamWaitEvent(s1, evH[0], 0);
    gemm_tf32<64, 4, 2><<<FFN_GRID, 256, 0, s1>>>(hwr[0], ffn_w, ffn_b, out, N_NODES, D, 64);
    cudaEventRecord(evF[0], s1);

    // ----- layers 1..2 (FFN on side stream) -----
    for (int l = 1; l < 3; l++) {
        int j = l - 1;
        vn_mlp_kernel<<<NGRAPHS / 8, 256>>>(ph2h, poff,
                                            vn_w1 + (size_t)j * D * D, vn_b1 + (size_t)j * D,
                                            vn_g1 + (size_t)j * D,     vn_be1 + (size_t)j * D,
                                            vn_w2 + (size_t)j * D * D, vn_b2 + (size_t)j * D,
                                            vn_g2 + (size_t)j * D,     vn_be2 + (size_t)j * D,
                                            pvn, pvnh);
        aggregate_kernel<true><<<AGG_GRID, 256>>>((const uint2*)ph2h, (const uint2*)pvnh,
                                                  batch, (uint2*)paggh);
        if (l == 2) cudaStreamWaitEvent(0, evF[0], 0);    // about to rewrite hb0
        gemm_fused<<<FUSED_GRID, 256, SM_TOTAL>>>(paggh, gcn_w + (size_t)l * D * D,
                                                  gcn_b + (size_t)l * D, hres[l],
                                                  norm_g + (size_t)l * D, norm_b + (size_t)l * D,
                                                  nullptr, nullptr,
                                                  hwr[l], ph2h, nullptr, N_NODES);
        cudaEventRecord(evH[l], 0);
        cudaStreamWaitEvent(s1, evH[l], 0);
        gemm_tf32<64, 4, 2><<<FFN_GRID, 256, 0, s1>>>(hwr[l], ffn_w + (size_t)l * D * 64,
                                                      ffn_b + (size_t)l * 64,
                                                      out + (size_t)l * 64, N_NODES, D, 64);
        cudaEventRecord(evF[l], s1);
    }

    // ----- layer 3 (FFN fused; h write dead -> skipped) -----
    {
        int l = 3, j = 2;
        vn_mlp_kernel<<<NGRAPHS / 8, 256>>>(ph2h, poff,
                                            vn_w1 + (size_t)j * D * D, vn_b1 + (size_t)j * D,
                                            vn_g1 + (size_t)j * D,     vn_be1 + (size_t)j * D,
                                            vn_w2 + (size_t)j * D * D, vn_b2 + (size_t)j * D,
                                            vn_g2 + (size_t)j * D,     vn_be2 + (size_t)j * D,
                                            pvn, pvnh);
        aggregate_kernel<true><<<AGG_GRID, 256>>>((const uint2*)ph2h, (const uint2*)pvnh,
                                                  batch, (uint2*)paggh);
        cudaStreamWaitEvent(0, evF[1], 0);
        gemm_fused<<<FUSED_GRID, 256, SM_TOTAL>>>(paggh, gcn_w + (size_t)l * D * D,
                                                  gcn_b + (size_t)l * D, hres[l],
                                                  nullptr, nullptr,
                                                  ffn_w + (size_t)l * D * 64,
                                                  ffn_b + (size_t)l * 64,
                                                  hwr[l], ph2h,
                                                  out + (size_t)l * 64, N_NODES);
    }

    // ---- join side stream before returning ----
    cudaStreamWaitEvent(0, evF[2], 0);
}